// round 6
// baseline (speedup 1.0000x reference)
#include <cuda_runtime.h>
#include <cuda_bf16.h>
#include <math.h>
#include <stdint.h>

#define BATCH 256
#define DIM   512
#define LW    32
#define PIX   196
#define TT    8
#define MBIG  (BATCH*PIX)   // 50176

// ---------------- scratch (static __device__ — allocation-guard safe) ----------------
// hi/lo packed layout: [rows][2][512]  (hi at +0, lo at +512), row stride 1024
__device__ __nv_bfloat16 g_kT2[MBIG*1024];
__device__ __nv_bfloat16 g_I2 [MBIG*1024];
__device__ __nv_bfloat16 g_J2 [MBIG*1024];
__device__ float g_ra  [MBIG*DIM];
__device__ __nv_bfloat16 g_Wk2 [DIM*1024];   // [N][2][512]
__device__ __nv_bfloat16 g_WI2 [DIM*2048];   // [N][2][1024]
__device__ __nv_bfloat16 g_Wra2[DIM*1024];
__device__ float g_cq  [BATCH*DIM];
__device__ float g_mI  [BATCH*DIM];
__device__ float g_r   [BATCH*DIM];
__device__ float g_mprev[BATCH*DIM];
__device__ float g_mm  [BATCH*DIM];
__device__ float g_msa [BATCH*DIM];
__device__ float g_tmp [BATCH*DIM];
__device__ float g_gate[BATCH];

// ================= helpers =================
__device__ __forceinline__ uint32_t smem_u32(const void* p) {
    uint32_t a;
    asm("{ .reg .u64 t; cvta.to.shared.u64 t, %1; cvt.u32.u64 %0, t; }" : "=r"(a) : "l"(p));
    return a;
}
__device__ __forceinline__ void cpasync16(uint32_t dst, const void* src) {
    asm volatile("cp.async.cg.shared.global [%0], [%1], 16;" :: "r"(dst), "l"(src) : "memory");
}
__device__ __forceinline__ void cp_commit() { asm volatile("cp.async.commit_group;" ::: "memory"); }
__device__ __forceinline__ void cp_wait1() { asm volatile("cp.async.wait_group 1;" ::: "memory"); }
__device__ __forceinline__ void cp_wait0() { asm volatile("cp.async.wait_group 0;" ::: "memory"); }

__device__ __forceinline__ void ldm_x4(uint32_t& r0, uint32_t& r1, uint32_t& r2, uint32_t& r3, uint32_t a) {
    asm volatile("ldmatrix.sync.aligned.m8n8.x4.shared.b16 {%0,%1,%2,%3}, [%4];"
                 : "=r"(r0), "=r"(r1), "=r"(r2), "=r"(r3) : "r"(a));
}
__device__ __forceinline__ void mma16816(float* c, const uint32_t* a, const uint32_t* b) {
    asm volatile("mma.sync.aligned.m16n8k16.row.col.f32.bf16.bf16.f32 "
                 "{%0,%1,%2,%3}, {%4,%5,%6,%7}, {%8,%9}, {%0,%1,%2,%3};"
                 : "+f"(c[0]), "+f"(c[1]), "+f"(c[2]), "+f"(c[3])
                 : "r"(a[0]), "r"(a[1]), "r"(a[2]), "r"(a[3]), "r"(b[0]), "r"(b[1]));
}

// ================= HMMA bf16-split GEMM v3 =================
// 2-stage ring (32KB/stage), __launch_bounds__(256,2) => 2 CTAs/SM.
// Per kp: B hi/lo frags hoisted via ldm_x4 (pairs of n8), then per-mi A load + 12 MMAs.
#define MG_SMEM (2*32768)

template<int K, bool CONCAT, int EPI>
__global__ void __launch_bounds__(256, 2) mma_gemm(
    const __nv_bfloat16* __restrict__ A0, const __nv_bfloat16* __restrict__ A1,
    const __nv_bfloat16* __restrict__ W,
    const float* __restrict__ bias, const float* __restrict__ scale,
    __nv_bfloat16* __restrict__ O, float* __restrict__ Of)
{
    constexpr int KIT = K / 32;
    extern __shared__ __align__(128) char dsm[];
    const uint32_t smb = smem_u32(dsm);

    const int tid = threadIdx.x, lane = tid & 31, wid = tid >> 5;
    const int bm = blockIdx.y * 128, bn = blockIdx.x * 128;
    const int wm = (wid >> 2) * 64, wn = (wid & 3) * 32;

    float acc[4][4][4];
    #pragma unroll
    for (int i = 0; i < 4; i++)
        #pragma unroll
        for (int j = 0; j < 4; j++)
            #pragma unroll
            for (int v = 0; v < 4; v++) acc[i][j][v] = 0.f;

    auto load_stage = [&](int it, int stage) {
        uint32_t sb = smb + (uint32_t)stage * 32768u;
        int k0 = it * 32;
        const __nv_bfloat16* Asrc = A0;
        int ac = k0;
        if (CONCAT && k0 >= 512) { Asrc = A1; ac = k0 - 512; }
        const int cc = tid & 3;
        #pragma unroll
        for (int j = 0; j < 2; j++) {
            int row = (tid >> 2) + j * 64;
            uint32_t d = sb + row * 64 + ((cc * 16) ^ (((row >> 1) & 3) << 4));
            const __nv_bfloat16* ga = Asrc + (size_t)(bm + row) * 1024 + ac + cc * 8;
            cpasync16(d,          ga);          // A_hi
            cpasync16(d + 8192u,  ga + 512);    // A_lo
            const __nv_bfloat16* gw = W + (size_t)(bn + row) * (2 * K) + k0 + cc * 8;
            cpasync16(d + 16384u, gw);          // B_hi
            cpasync16(d + 24576u, gw + K);      // B_lo
        }
    };

    load_stage(0, 0); cp_commit();
    if (KIT > 1) { load_stage(1, 1); cp_commit(); }

    for (int it = 0; it < KIT; ++it) {
        if (it + 1 < KIT) cp_wait1(); else cp_wait0();
        __syncthreads();

        const uint32_t sb  = smb + (uint32_t)(it & 1) * 32768u;
        const uint32_t sAh = sb, sAl = sb + 8192u, sBh = sb + 16384u, sBl = sb + 24576u;
        #pragma unroll
        for (int kp = 0; kp < 2; kp++) {
            // B fragments: 2 pairs (n 0-15, n 16-31), hi+lo, each one ldm_x4
            uint32_t bh[2][4], bl[2][4];
            #pragma unroll
            for (int pr = 0; pr < 2; pr++) {
                int nrow = wn + pr * 16 + ((lane >> 4) << 3) + (lane & 7);
                int chunk = (kp * 2 + ((lane >> 3) & 1)) ^ ((nrow >> 1) & 3);
                uint32_t off = nrow * 64 + chunk * 16;
                ldm_x4(bh[pr][0], bh[pr][1], bh[pr][2], bh[pr][3], sBh + off);
                ldm_x4(bl[pr][0], bl[pr][1], bl[pr][2], bl[pr][3], sBl + off);
            }
            #pragma unroll
            for (int mi = 0; mi < 4; mi++) {
                uint32_t ah[4], al[4];
                int row = wm + mi * 16 + (lane & 15);
                int chunk = (kp * 2 + (lane >> 4)) ^ ((row >> 1) & 3);
                uint32_t off = row * 64 + chunk * 16;
                ldm_x4(ah[0], ah[1], ah[2], ah[3], sAh + off);
                ldm_x4(al[0], al[1], al[2], al[3], sAl + off);
                #pragma unroll
                for (int ni = 0; ni < 4; ni++)
                    mma16816(acc[mi][ni], ah, &bh[ni >> 1][(ni & 1) * 2]);
                #pragma unroll
                for (int ni = 0; ni < 4; ni++)
                    mma16816(acc[mi][ni], ah, &bl[ni >> 1][(ni & 1) * 2]);
                #pragma unroll
                for (int ni = 0; ni < 4; ni++)
                    mma16816(acc[mi][ni], al, &bh[ni >> 1][(ni & 1) * 2]);
            }
        }
        __syncthreads();
        if (it + 2 < KIT) { load_stage(it + 2, it & 1); cp_commit(); }
    }

    // ---------------- epilogue ----------------
    #pragma unroll
    for (int ni = 0; ni < 4; ni++) {
        const int n0 = bn + wn + ni * 8 + 2 * (lane & 3);
        const float b0 = bias[n0], b1 = bias[n0 + 1];
        #pragma unroll
        for (int mi = 0; mi < 4; mi++) {
            const int r0 = bm + wm + mi * 16 + (lane >> 2);
            const int r1 = r0 + 8;
            float* c = acc[mi][ni];
            if (EPI == 0) {
                const float* s0 = scale + (size_t)(r0 / PIX) * DIM;
                const float* s1 = scale + (size_t)(r1 / PIX) * DIM;
                float v00 = (c[0] + b0) * s0[n0], v01 = (c[1] + b1) * s0[n0 + 1];
                float v10 = (c[2] + b0) * s1[n0], v11 = (c[3] + b1) * s1[n0 + 1];
                __nv_bfloat16 h00 = __float2bfloat16(v00), h01 = __float2bfloat16(v01);
                __nv_bfloat16 h10 = __float2bfloat16(v10), h11 = __float2bfloat16(v11);
                uint32_t hi0 = (uint32_t)__bfloat16_as_ushort(h00) | ((uint32_t)__bfloat16_as_ushort(h01) << 16);
                uint32_t hi1 = (uint32_t)__bfloat16_as_ushort(h10) | ((uint32_t)__bfloat16_as_ushort(h11) << 16);
                __nv_bfloat16 l00 = __float2bfloat16(v00 - __bfloat162float(h00));
                __nv_bfloat16 l01 = __float2bfloat16(v01 - __bfloat162float(h01));
                __nv_bfloat16 l10 = __float2bfloat16(v10 - __bfloat162float(h10));
                __nv_bfloat16 l11 = __float2bfloat16(v11 - __bfloat162float(h11));
                uint32_t lo0 = (uint32_t)__bfloat16_as_ushort(l00) | ((uint32_t)__bfloat16_as_ushort(l01) << 16);
                uint32_t lo1 = (uint32_t)__bfloat16_as_ushort(l10) | ((uint32_t)__bfloat16_as_ushort(l11) << 16);
                *reinterpret_cast<uint32_t*>(O + (size_t)r0 * 1024 + n0)       = hi0;
                *reinterpret_cast<uint32_t*>(O + (size_t)r0 * 1024 + 512 + n0) = lo0;
                *reinterpret_cast<uint32_t*>(O + (size_t)r1 * 1024 + n0)       = hi1;
                *reinterpret_cast<uint32_t*>(O + (size_t)r1 * 1024 + 512 + n0) = lo1;
            } else {
                float2 v0 = make_float2(c[0] + b0, c[1] + b1);
                float2 v1 = make_float2(c[2] + b0, c[3] + b1);
                *reinterpret_cast<float2*>(Of + (size_t)r0 * DIM + n0) = v0;
                *reinterpret_cast<float2*>(Of + (size_t)r1 * DIM + n0) = v1;
            }
        }
    }
}

// ================= small fp32 GEMM: register-prefetch double-buffered =================
template<int K, bool CONCAT>
__global__ void __launch_bounds__(256) gemm_small(
    const float* __restrict__ A0, const float* __restrict__ A1,
    const float* __restrict__ W, const float* __restrict__ bias,
    float* __restrict__ C)
{
    constexpr int BM = 64, BN = 64, BK = 32;
    constexpr int NIT = K / BK;
    constexpr int halfK = K / 2;
    __shared__ __align__(16) float As[2][BK][BM];
    __shared__ __align__(16) float Bs[2][BK][BN];

    const int tid = threadIdx.x;
    const int bm = blockIdx.y * BM, bn = blockIdx.x * BN;
    const int tx = tid & 15, ty = tid >> 4;

    float4 pa[2], pb[2];
    auto gload = [&](int it) {
        int k0 = it * BK;
        #pragma unroll
        for (int j = 0; j < 2; j++) {
            int f = tid + j * 256;
            int r = f >> 3, c4 = (f & 7) * 4;
            int gk = k0 + c4;
            const float* srcA;
            if (CONCAT) {
                srcA = (gk < halfK) ? (A0 + (size_t)(bm + r) * halfK + gk)
                                    : (A1 + (size_t)(bm + r) * halfK + (gk - halfK));
            } else {
                srcA = A0 + (size_t)(bm + r) * K + gk;
            }
            pa[j] = *reinterpret_cast<const float4*>(srcA);
            pb[j] = *reinterpret_cast<const float4*>(W + (size_t)(bn + r) * K + gk);
        }
    };
    auto sstore = [&](int buf) {
        #pragma unroll
        for (int j = 0; j < 2; j++) {
            int f = tid + j * 256;
            int r = f >> 3, c4 = (f & 7) * 4;
            As[buf][c4 + 0][r] = pa[j].x; As[buf][c4 + 1][r] = pa[j].y;
            As[buf][c4 + 2][r] = pa[j].z; As[buf][c4 + 3][r] = pa[j].w;
            Bs[buf][c4 + 0][r] = pb[j].x; Bs[buf][c4 + 1][r] = pb[j].y;
            Bs[buf][c4 + 2][r] = pb[j].z; Bs[buf][c4 + 3][r] = pb[j].w;
        }
    };

    float acc[4][4];
    #pragma unroll
    for (int i = 0; i < 4; i++)
        #pragma unroll
        for (int j = 0; j < 4; j++) acc[i][j] = 0.f;

    gload(0); sstore(0); __syncthreads();
    for (int it = 0; it < NIT; ++it) {
        if (it + 1 < NIT) gload(it + 1);
        const int buf = it & 1;
        #pragma unroll
        for (int kk = 0; kk < BK; kk++) {
            float4 a = *reinterpret_cast<const float4*>(&As[buf][kk][ty * 4]);
            float4 b = *reinterpret_cast<const float4*>(&Bs[buf][kk][tx * 4]);
            acc[0][0] = fmaf(a.x, b.x, acc[0][0]); acc[0][1] = fmaf(a.x, b.y, acc[0][1]);
            acc[0][2] = fmaf(a.x, b.z, acc[0][2]); acc[0][3] = fmaf(a.x, b.w, acc[0][3]);
            acc[1][0] = fmaf(a.y, b.x, acc[1][0]); acc[1][1] = fmaf(a.y, b.y, acc[1][1]);
            acc[1][2] = fmaf(a.y, b.z, acc[1][2]); acc[1][3] = fmaf(a.y, b.w, acc[1][3]);
            acc[2][0] = fmaf(a.z, b.x, acc[2][0]); acc[2][1] = fmaf(a.z, b.y, acc[2][1]);
            acc[2][2] = fmaf(a.z, b.z, acc[2][2]); acc[2][3] = fmaf(a.z, b.w, acc[2][3]);
            acc[3][0] = fmaf(a.w, b.x, acc[3][0]); acc[3][1] = fmaf(a.w, b.y, acc[3][1]);
            acc[3][2] = fmaf(a.w, b.z, acc[3][2]); acc[3][3] = fmaf(a.w, b.w, acc[3][3]);
        }
        __syncthreads();
        if (it + 1 < NIT) { sstore((it + 1) & 1); __syncthreads(); }
    }

    float bb[4];
    #pragma unroll
    for (int j = 0; j < 4; j++) bb[j] = bias ? bias[bn + tx * 4 + j] : 0.f;
    #pragma unroll
    for (int i = 0; i < 4; i++) {
        int gm = bm + ty * 4 + i;
        float4 v = make_float4(acc[i][0] + bb[0], acc[i][1] + bb[1],
                               acc[i][2] + bb[2], acc[i][3] + bb[3]);
        *reinterpret_cast<float4*>(&C[(size_t)gm * DIM + bn + tx * 4]) = v;
    }
}

// ================= conversions =================
__global__ void split_w_kernel(const float* __restrict__ w, __nv_bfloat16* __restrict__ o, int N, int K)
{
    int i = blockIdx.x * 256 + threadIdx.x;
    if (i < N * K) {
        int n = i / K, k = i % K;
        float v = w[i];
        __nv_bfloat16 h = __float2bfloat16(v);
        o[(size_t)n * 2 * K + k]     = h;
        o[(size_t)n * 2 * K + K + k] = __float2bfloat16(v - __bfloat162float(h));
    }
}

// k [B,D,P] -> kT2 [B*P][2][512] hi/lo
__global__ void transpose_split_k(const float* __restrict__ k, __nv_bfloat16* __restrict__ kT2)
{
    __shared__ float tile[32][33];
    int b  = blockIdx.z;
    int p0 = blockIdx.x * 32;
    int c0 = blockIdx.y * 32;
    int tx = threadIdx.x, ty = threadIdx.y;
    #pragma unroll
    for (int j = 0; j < 32; j += 8) {
        int c = c0 + ty + j, p = p0 + tx;
        if (p < PIX) tile[ty + j][tx] = k[((size_t)b * DIM + c) * PIX + p];
    }
    __syncthreads();
    #pragma unroll
    for (int j = 0; j < 32; j += 8) {
        int p = p0 + ty + j, c = c0 + tx;
        if (p < PIX) {
            float v = tile[tx][ty + j];
            __nv_bfloat16 h = __float2bfloat16(v);
            size_t o = ((size_t)b * PIX + p) * 1024 + c;
            kT2[o]       = h;
            kT2[o + 512] = __float2bfloat16(v - __bfloat162float(h));
        }
    }
}

// ---------------- reduction helpers ----------------
template<int NW>
__device__ __forceinline__ float blkSum(float v, float* red) {
    #pragma unroll
    for (int o = 16; o > 0; o >>= 1) v += __shfl_xor_sync(0xffffffffu, v, o);
    __syncthreads();
    if ((threadIdx.x & 31) == 0) red[threadIdx.x >> 5] = v;
    __syncthreads();
    float s = 0.f;
    #pragma unroll
    for (int i = 0; i < NW; i++) s += red[i];
    return s;
}

// ---------------- ControlUnit tail ----------------
__global__ void control_kernel(const float* __restrict__ cq, const float* __restrict__ cw,
                               const int* __restrict__ mask, const float* __restrict__ Wca,
                               const float* __restrict__ bca,
                               float* __restrict__ cv_out, float* __restrict__ cnew)
{
    int b = blockIdx.x, tid = threadIdx.x;   // 256 threads
    __shared__ float u[DIM];
    __shared__ float s[LW];
    __shared__ float red[8];
    for (int d = tid; d < DIM; d += 256) u[d] = cq[(size_t)b * DIM + d] * Wca[d];
    __syncthreads();
    const float* cwb = cw + (size_t)b * LW * DIM;
    for (int l = 0; l < LW; l++) {
        float p = 0.f;
        for (int d = tid; d < DIM; d += 256) p += u[d] * cwb[(size_t)l * DIM + d];
        float tot = blkSum<8>(p, red);
        if (tid == 0) s[l] = (mask[b * LW + l] > 0) ? (tot + bca[0]) : -INFINITY;
    }
    __syncthreads();
    if (tid == 0) {
        float mx = -INFINITY;
        for (int l = 0; l < LW; l++) mx = fmaxf(mx, s[l]);
        float sm = 0.f;
        for (int l = 0; l < LW; l++) { float e = __expf(s[l] - mx); s[l] = e; sm += e; }
        float inv = 1.f / sm;
        for (int l = 0; l < LW; l++) { s[l] *= inv; cv_out[b * LW + l] = s[l]; }
    }
    __syncthreads();
    for (int d = tid; d < DIM; d += 256) {
        float a = 0.f;
        for (int l = 0; l < LW; l++) a = fmaf(s[l], cwb[(size_t)l * DIM + d], a);
        cnew[(size_t)b * DIM + d] = a;
    }
}

// ---------------- softmax over channels: warp-per-pixel, 28-pixel write staging ----------
#define SMRV_TILE_STRIDE 517
#define SMRV_SMEM (28*SMRV_TILE_STRIDE*4)

__global__ void __launch_bounds__(512) softmax_rv_kernel(
    const float* __restrict__ ra, const __nv_bfloat16* __restrict__ kT2,
    float* __restrict__ rv_out, float* __restrict__ r_out)
{
    extern __shared__ float tile[];          // [28][517]
    __shared__ float rsum[DIM];
    const int b = blockIdx.x, tid = threadIdx.x;
    const int w = tid >> 5, lane = tid & 31;
    const float* rab = ra + (size_t)b * PIX * DIM;
    const __nv_bfloat16* kb = kT2 + (size_t)b * PIX * 1024;
    float* rvb = rv_out + (size_t)b * DIM * PIX;

    if (tid < DIM) rsum[tid] = 0.f;
    float racc[16];
    #pragma unroll
    for (int j = 0; j < 16; j++) racc[j] = 0.f;
    __syncthreads();

    for (int pp = 0; pp < 7; pp++) {
        if (w < 14) {
            #pragma unroll
            for (int half = 0; half < 2; half++) {
                const int i = half * 14 + w;
                const int p = pp * 28 + i;
                float x[16];
                #pragma unroll
                for (int q = 0; q < 4; q++) {
                    float4 v = *reinterpret_cast<const float4*>(rab + (size_t)p * DIM + q * 128 + lane * 4);
                    x[q * 4 + 0] = v.x; x[q * 4 + 1] = v.y; x[q * 4 + 2] = v.z; x[q * 4 + 3] = v.w;
                }
                float mx = x[0];
                #pragma unroll
                for (int j = 1; j < 16; j++) mx = fmaxf(mx, x[j]);
                #pragma unroll
                for (int o = 16; o > 0; o >>= 1) mx = fmaxf(mx, __shfl_xor_sync(0xffffffffu, mx, o));
                float sm = 0.f;
                #pragma unroll
                for (int j = 0; j < 16; j++) { x[j] = __expf(x[j] - mx); sm += x[j]; }
                #pragma unroll
                for (int o = 16; o > 0; o >>= 1) sm += __shfl_xor_sync(0xffffffffu, sm, o);
                const float inv = 1.f / sm;
                #pragma unroll
                for (int q = 0; q < 4; q++) {
                    float rv0 = x[q * 4 + 0] * inv, rv1 = x[q * 4 + 1] * inv;
                    float rv2 = x[q * 4 + 2] * inv, rv3 = x[q * 4 + 3] * inv;
                    float* tr = &tile[i * SMRV_TILE_STRIDE + q * 128 + lane * 4];
                    tr[0] = rv0; tr[1] = rv1; tr[2] = rv2; tr[3] = rv3;
                    const size_t kidx = (size_t)p * 1024 + q * 128 + lane * 4;
                    __nv_bfloat162 kh0 = *reinterpret_cast<const __nv_bfloat162*>(kb + kidx);
                    __nv_bfloat162 kh1 = *reinterpret_cast<const __nv_bfloat162*>(kb + kidx + 2);
                    __nv_bfloat162 kl0 = *reinterpret_cast<const __nv_bfloat162*>(kb + kidx + 512);
                    __nv_bfloat162 kl1 = *reinterpret_cast<const __nv_bfloat162*>(kb + kidx + 514);
                    racc[q * 4 + 0] = fmaf(rv0, __bfloat162float(kh0.x) + __bfloat162float(kl0.x), racc[q * 4 + 0]);
                    racc[q * 4 + 1] = fmaf(rv1, __bfloat162float(kh0.y) + __bfloat162float(kl0.y), racc[q * 4 + 1]);
                    racc[q * 4 + 2] = fmaf(rv2, __bfloat162float(kh1.x) + __bfloat162float(kl1.x), racc[q * 4 + 2]);
                    racc[q * 4 + 3] = fmaf(rv3, __bfloat162float(kh1.y) + __bfloat162float(kl1.y), racc[q * 4 + 3]);
                }
            }
        }
        __syncthreads();
        #pragma unroll 1
        for (int cc = 0; cc < 32; cc++) {
            int c = w * 32 + cc;
            if (lane < 28) rvb[(size_t)c * PIX + pp * 28 + lane] = tile[lane * SMRV_TILE_STRIDE + c];
        }
        __syncthreads();
    }

    #pragma unroll
    for (int q = 0; q < 4; q++)
        #pragma unroll
        for (int j = 0; j < 4; j++)
            atomicAdd(&rsum[q * 128 + lane * 4 + j], racc[q * 4 + j]);
    __syncthreads();
    if (tid < DIM) r_out[(size_t)b * DIM + tid] = rsum[tid];
}

// ---------------- gate, sa softmax over T, m_sa ----------------
__global__ void gate_sa_kernel(const float* __restrict__ cnew, const float* __restrict__ Wc,
                               const float* __restrict__ bc,   const float* __restrict__ cs,
                               const float* __restrict__ Wsa,  const float* __restrict__ bsa,
                               const float* __restrict__ ms,
                               float* __restrict__ gate_out, float* __restrict__ msa_out)
{
    int b = blockIdx.x, tid = threadIdx.x;   // 256 threads
    __shared__ float red[8];
    __shared__ float sa[TT];
    __shared__ float gsh;
    float p = 0.f;
    for (int d = tid; d < DIM; d += 256) p += cnew[(size_t)b * DIM + d] * Wc[d];
    float tot = blkSum<8>(p, red);
    if (tid == 0) gsh = 1.f / (1.f + __expf(-(tot + bc[0])));
    __syncthreads();
    float gate = gsh;
    for (int t8 = 0; t8 < TT; t8++) {
        float qv = 0.f;
        const float* csrow = cs + ((size_t)t8 * BATCH + b) * DIM;
        for (int d = tid; d < DIM; d += 256) qv += csrow[d] * Wsa[d];
        float qt = blkSum<8>(qv, red);
        if (tid == 0) sa[t8] = gate * qt + bsa[0];
    }
    __syncthreads();
    if (tid == 0) {
        float mx = -INFINITY;
        for (int i = 0; i < TT; i++) mx = fmaxf(mx, sa[i]);
        float sm = 0.f;
        for (int i = 0; i < TT; i++) { float e = __expf(sa[i] - mx); sa[i] = e; sm += e; }
        float inv = 1.f / sm;
        for (int i = 0; i < TT; i++) sa[i] *= inv;
    }
    __syncthreads();
    for (int d = tid; d < DIM; d += 256) {
        float a = 0.f;
        #pragma unroll
        for (int i = 0; i < TT; i++)
            a = fmaf(sa[i], ms[((size_t)i * BATCH + b) * DIM + d], a);
        msa_out[(size_t)b * DIM + d] = a;
    }
    if (tid == 0) gate_out[b] = gate;
}

// ---------------- final ----------------
__global__ void final_kernel(const float* __restrict__ m, const float* __restrict__ mm,
                             const float* __restrict__ tmp, const float* __restrict__ gate,
                             float* __restrict__ mnew)
{
    int i = blockIdx.x * 256 + threadIdx.x;
    int b = i >> 9;
    float g = gate[b];
    mnew[i] = g * m[i] + (1.f - g) * (mm[i] + tmp[i]);
}

// ---------------- launch ----------------
extern "C" void kernel_launch(void* const* d_in, const int* in_sizes, int n_in,
                              void* d_out, int out_size)
{
    const float* c    = (const float*)d_in[0];
    const float* m    = (const float*)d_in[1];
    const float* k    = (const float*)d_in[2];
    const float* q    = (const float*)d_in[3];
    const float* cw   = (const float*)d_in[4];
    const int*   mask = (const int*)  d_in[5];
    const float* cs   = (const float*)d_in[6];
    const float* ms   = (const float*)d_in[7];
    const float* Wcq  = (const float*)d_in[8];
    const float* bcq  = (const float*)d_in[9];
    const float* Wca  = (const float*)d_in[10];
    const float* bca  = (const float*)d_in[11];
    const float* Wm_r = (const float*)d_in[12];
    const float* bm_r = (const float*)d_in[13];
    const float* Wk   = (const float*)d_in[14];
    const float* bk   = (const float*)d_in[15];
    const float* WI   = (const float*)d_in[16];
    const float* bI   = (const float*)d_in[17];
    const float* Wra  = (const float*)d_in[18];
    const float* bra  = (const float*)d_in[19];
    const float* Wm_w = (const float*)d_in[20];
    const float* bm_w = (const float*)d_in[21];
    const float* Wsa  = (const float*)d_in[22];
    const float* bsa  = (const float*)d_in[23];
    const float* Wm2  = (const float*)d_in[24];
    const float* bm2  = (const float*)d_in[25];
    const float* Wc   = (const float*)d_in[26];
    const float* bc   = (const float*)d_in[27];
    const float* Ws   = (const float*)d_in[28];

    float* out      = (float*)d_out;
    float* out_cnew = out;                       // [B,D]
    float* out_mnew = out + 131072;              // [B,D]
    float* out_cv   = out + 262144;              // [B,L]
    float* out_rv   = out + 270336;              // [B,D,H,W]

    __nv_bfloat16 *p_kT2, *p_I2, *p_J2, *p_Wk2, *p_WI2, *p_Wra2;
    float *p_ra, *p_cq, *p_mI, *p_r, *p_mprev, *p_mm, *p_msa, *p_tmp, *p_gate;
    cudaGetSymbolAddress((void**)&p_kT2,  g_kT2);
    cudaGetSymbolAddress((void**)&p_I2,   g_I2);
    cudaGetSymbolAddress((void**)&p_J2,   g_J2);
    cudaGetSymbolAddress((void**)&p_Wk2,  g_Wk2);
    cudaGetSymbolAddress((void**)&p_WI2,  g_WI2);
    cudaGetSymbolAddress((void**)&p_Wra2, g_Wra2);
    cudaGetSymbolAddress((void**)&p_ra,   g_ra);
    cudaGetSymbolAddress((void**)&p_cq,   g_cq);
    cudaGetSymbolAddress((void**)&p_mI,   g_mI);
    cudaGetSymbolAddress((void**)&p_r,    g_r);
    cudaGetSymbolAddress((void**)&p_mprev,g_mprev);
    cudaGetSymbolAddress((void**)&p_mm,   g_mm);
    cudaGetSymbolAddress((void**)&p_msa,  g_msa);
    cudaGetSymbolAddress((void**)&p_tmp,  g_tmp);
    cudaGetSymbolAddress((void**)&p_gate, g_gate);

    cudaFuncSetAttribute(mma_gemm<512,  false, 0>, cudaFuncAttributeMaxDynamicSharedMemorySize, MG_SMEM);
    cudaFuncSetAttribute(mma_gemm<1024, true,  0>, cudaFuncAttributeMaxDynamicSharedMemorySize, MG_SMEM);
    cudaFuncSetAttribute(mma_gemm<512,  false, 1>, cudaFuncAttributeMaxDynamicSharedMemorySize, MG_SMEM);
    cudaFuncSetAttribute(softmax_rv_kernel, cudaFuncAttributeMaxDynamicSharedMemorySize, SMRV_SMEM);

    // ---- ordered so my 4th launch = mma_gemm I (ncu -s 5 -c 1 visibility) ----
    // 1. Wk -> hi/lo
    split_w_kernel<<<(DIM*DIM + 255)/256, 256>>>(Wk, p_Wk2, DIM, DIM);
    // 2. k -> kT hi/lo
    transpose_split_k<<<dim3(7, 16, BATCH), dim3(32, 8)>>>(k, p_kT2);
    // 3. mI = m @ Wm_r^T + bm_r
    gemm_small<512, false><<<dim3(8, 4), 256>>>(m, nullptr, Wm_r, bm_r, p_mI);
    // 4. I = mI ⊙ (kT @ Wk^T + bk) -> hi/lo          [HMMA]  << profiled
    mma_gemm<512, false, 0><<<dim3(4, 392), 256, MG_SMEM>>>(
        p_kT2, nullptr, p_Wk2, bk, p_mI, p_I2, nullptr);
    // 5. WI -> hi/lo
    split_w_kernel<<<(DIM*2*DIM + 255)/256, 256>>>(WI, p_WI2, DIM, 2*DIM);
    // 6. cq = [c|q] @ Wcq^T + bcq
    gemm_small<1024, true><<<dim3(8, 4), 256>>>(c, q, Wcq, bcq, p_cq);
    // 7. ControlUnit tail -> cv, c_new
    control_kernel<<<BATCH, 256>>>(p_cq, cw, mask, Wca, bca, out_cv, out_cnew);
    // 8. J = c_new ⊙ ([I|kT] @ WI^T + bI) -> hi/lo   [HMMA]
    mma_gemm<1024, true, 0><<<dim3(4, 392), 256, MG_SMEM>>>(
        p_I2, p_kT2, p_WI2, bI, out_cnew, p_J2, nullptr);
    // 9. Wra -> hi/lo
    split_w_kernel<<<(DIM*DIM + 255)/256, 256>>>(Wra, p_Wra2, DIM, DIM);
    // 10. ra = J @ Wra^T + bra -> fp32               [HMMA]
    mma_gemm<512, false, 1><<<dim3(4, 392), 256, MG_SMEM>>>(
        p_J2, nullptr, p_Wra2, bra, nullptr, nullptr, p_ra);
    // 11. rv = softmax_c(ra) -> d_out (transposed), r = sum_p rv*k
    softmax_rv_kernel<<<BATCH, 512, SMRV_SMEM>>>(p_ra, p_kT2, out_rv, p_r);
    // 12. m_prev = [r|m] @ Wm_w^T + bm_w
    gemm_small<1024, true><<<dim3(8, 4), 256>>>(p_r, m, Wm_w, bm_w, p_mprev);
    // 13. m_ = m_prev @ Wm2^T + bm2
    gemm_small<512, false><<<dim3(8, 4), 256>>>(p_mprev, nullptr, Wm2, bm2, p_mm);
    // 14. gate, sa softmax, m_sa
    gate_sa_kernel<<<BATCH, 256>>>(out_cnew, Wc, bc, cs, Wsa, bsa, ms, p_gate, p_msa);
    // 15. tmp = m_sa @ Ws^T
    gemm_small<512, false><<<dim3(8, 4), 256>>>(p_msa, nullptr, Ws, nullptr, p_tmp);
    // 16. m_new = gate*m + (1-gate)*(m_ + tmp)
    final_kernel<<<(BATCH * DIM) / 256, 256>>>(m, p_mm, p_tmp, p_gate, out_mnew);
}

// round 7
// speedup vs baseline: 1.2516x; 1.2516x over previous
#include <cuda_runtime.h>
#include <cuda_bf16.h>
#include <cuda_fp16.h>
#include <math.h>
#include <stdint.h>

#define BATCH 256
#define DIM   512
#define LW    32
#define PIX   196
#define TT    8
#define MBIG  (BATCH*PIX)   // 50176

// ---------------- scratch (static __device__ — allocation-guard safe) ----------------
// A-side hi/lo packed layout: [rows][2][512] fp16 (hi at +0, lo at +512), row stride 1024
__device__ __half g_kT2[MBIG*1024];
__device__ __half g_I2 [MBIG*1024];
__device__ __half g_J2 [MBIG*1024];
__device__ float g_ra  [MBIG*DIM];
__device__ __half g_Wk2 [DIM*DIM];     // [N][512] fp16
__device__ __half g_WI2 [DIM*2*DIM];   // [N][1024] fp16
__device__ __half g_Wra2[DIM*DIM];
__device__ float g_cq  [BATCH*DIM];
__device__ float g_mI  [BATCH*DIM];
__device__ float g_r   [BATCH*DIM];
__device__ float g_mprev[BATCH*DIM];
__device__ float g_mm  [BATCH*DIM];
__device__ float g_msa [BATCH*DIM];
__device__ float g_tmp [BATCH*DIM];
__device__ float g_gate[BATCH];

// ================= helpers =================
__device__ __forceinline__ uint32_t smem_u32(const void* p) {
    uint32_t a;
    asm("{ .reg .u64 t; cvta.to.shared.u64 t, %1; cvt.u32.u64 %0, t; }" : "=r"(a) : "l"(p));
    return a;
}
__device__ __forceinline__ void cpasync16(uint32_t dst, const void* src) {
    asm volatile("cp.async.cg.shared.global [%0], [%1], 16;" :: "r"(dst), "l"(src) : "memory");
}
__device__ __forceinline__ void cp_commit() { asm volatile("cp.async.commit_group;" ::: "memory"); }
__device__ __forceinline__ void cp_wait2() { asm volatile("cp.async.wait_group 2;" ::: "memory"); }
__device__ __forceinline__ void cp_wait1() { asm volatile("cp.async.wait_group 1;" ::: "memory"); }
__device__ __forceinline__ void cp_wait0() { asm volatile("cp.async.wait_group 0;" ::: "memory"); }

__device__ __forceinline__ void ldm_x4(uint32_t& r0, uint32_t& r1, uint32_t& r2, uint32_t& r3, uint32_t a) {
    asm volatile("ldmatrix.sync.aligned.m8n8.x4.shared.b16 {%0,%1,%2,%3}, [%4];"
                 : "=r"(r0), "=r"(r1), "=r"(r2), "=r"(r3) : "r"(a));
}
__device__ __forceinline__ void mma16816h(float* c, const uint32_t* a, const uint32_t* b) {
    asm volatile("mma.sync.aligned.m16n8k16.row.col.f32.f16.f16.f32 "
                 "{%0,%1,%2,%3}, {%4,%5,%6,%7}, {%8,%9}, {%0,%1,%2,%3};"
                 : "+f"(c[0]), "+f"(c[1]), "+f"(c[2]), "+f"(c[3])
                 : "r"(a[0]), "r"(a[1]), "r"(a[2]), "r"(a[3]), "r"(b[0]), "r"(b[1]));
}

// ================= HMMA fp16 A-split GEMM (2 products: Ah*W + Al*W) =================
// A layout [row][2][512] fp16 hi/lo; W [N][K] fp16.
// 4-stage cp.async ring (24KB/stage), prefetch distance 3, 1 sync/it.
// EPI 0: v = (acc + bias[n]) * scale[m/PIX, n] -> fp16 hi/lo into O[row][2][512]
// EPI 1: v = acc + bias[n] -> fp32 Of[m][n]
#define MG_STAGE 24576
#define MG_SMEM  (4*MG_STAGE)

template<int K, bool CONCAT, int EPI>
__global__ void __launch_bounds__(256, 2) mma_gemm(
    const __half* __restrict__ A0, const __half* __restrict__ A1,
    const __half* __restrict__ W,
    const float* __restrict__ bias, const float* __restrict__ scale,
    __half* __restrict__ O, float* __restrict__ Of)
{
    constexpr int KIT = K / 32;
    extern __shared__ __align__(128) char dsm[];
    const uint32_t smb = smem_u32(dsm);

    const int tid = threadIdx.x, lane = tid & 31, wid = tid >> 5;
    const int bm = blockIdx.y * 128, bn = blockIdx.x * 128;
    const int wm = (wid >> 2) * 64, wn = (wid & 3) * 32;

    float acc[4][4][4];
    #pragma unroll
    for (int i = 0; i < 4; i++)
        #pragma unroll
        for (int j = 0; j < 4; j++)
            #pragma unroll
            for (int v = 0; v < 4; v++) acc[i][j][v] = 0.f;

    auto load_stage = [&](int it, int stage) {
        uint32_t sb = smb + (uint32_t)stage * MG_STAGE;
        int k0 = it * 32;
        const __half* Asrc = A0;
        int ac = k0;
        if (CONCAT && k0 >= 512) { Asrc = A1; ac = k0 - 512; }
        const int cc = tid & 3;
        #pragma unroll
        for (int j = 0; j < 2; j++) {
            int row = (tid >> 2) + j * 64;
            uint32_t d = sb + row * 64 + ((cc * 16) ^ (((row >> 1) & 3) << 4));
            const __half* ga = Asrc + (size_t)(bm + row) * 1024 + ac + cc * 8;
            cpasync16(d,          ga);          // A_hi
            cpasync16(d + 8192u,  ga + 512);    // A_lo
            const __half* gw = W + (size_t)(bn + row) * K + k0 + cc * 8;
            cpasync16(d + 16384u, gw);          // W (fp16, hi only)
        }
    };

    load_stage(0, 0); cp_commit();
    load_stage(1, 1); cp_commit();
    load_stage(2, 2); cp_commit();

    for (int it = 0; it < KIT; ++it) {
        if (it + 3 <= KIT) cp_wait2();
        else if (it + 2 == KIT) cp_wait1();
        else cp_wait0();
        __syncthreads();
        if (it + 3 < KIT) { load_stage(it + 3, (it + 3) & 3); cp_commit(); }

        const uint32_t sb  = smb + (uint32_t)(it & 3) * MG_STAGE;
        const uint32_t sAh = sb, sAl = sb + 8192u, sB = sb + 16384u;
        #pragma unroll
        for (int kp = 0; kp < 2; kp++) {
            // B fragments: 2 pairs (n 0-15, n 16-31), each one ldm_x4
            uint32_t bf[2][4];
            #pragma unroll
            for (int pr = 0; pr < 2; pr++) {
                int nrow = wn + pr * 16 + ((lane >> 4) << 3) + (lane & 7);
                int chunk = (kp * 2 + ((lane >> 3) & 1)) ^ ((nrow >> 1) & 3);
                ldm_x4(bf[pr][0], bf[pr][1], bf[pr][2], bf[pr][3], sB + nrow * 64 + chunk * 16);
            }
            #pragma unroll
            for (int mi = 0; mi < 4; mi++) {
                uint32_t ah[4], al[4];
                int row = wm + mi * 16 + (lane & 15);
                int chunk = (kp * 2 + (lane >> 4)) ^ ((row >> 1) & 3);
                uint32_t off = row * 64 + chunk * 16;
                ldm_x4(ah[0], ah[1], ah[2], ah[3], sAh + off);
                ldm_x4(al[0], al[1], al[2], al[3], sAl + off);
                #pragma unroll
                for (int ni = 0; ni < 4; ni++)
                    mma16816h(acc[mi][ni], ah, &bf[ni >> 1][(ni & 1) * 2]);
                #pragma unroll
                for (int ni = 0; ni < 4; ni++)
                    mma16816h(acc[mi][ni], al, &bf[ni >> 1][(ni & 1) * 2]);
            }
        }
    }

    // ---------------- epilogue ----------------
    #pragma unroll
    for (int ni = 0; ni < 4; ni++) {
        const int n0 = bn + wn + ni * 8 + 2 * (lane & 3);
        const float b0 = bias[n0], b1 = bias[n0 + 1];
        #pragma unroll
        for (int mi = 0; mi < 4; mi++) {
            const int r0 = bm + wm + mi * 16 + (lane >> 2);
            const int r1 = r0 + 8;
            float* c = acc[mi][ni];
            if (EPI == 0) {
                const float* s0 = scale + (size_t)(r0 / PIX) * DIM;
                const float* s1 = scale + (size_t)(r1 / PIX) * DIM;
                float v00 = (c[0] + b0) * s0[n0], v01 = (c[1] + b1) * s0[n0 + 1];
                float v10 = (c[2] + b0) * s1[n0], v11 = (c[3] + b1) * s1[n0 + 1];
                __half h00 = __float2half_rn(v00), h01 = __float2half_rn(v01);
                __half h10 = __float2half_rn(v10), h11 = __float2half_rn(v11);
                __half l00 = __float2half_rn(v00 - __half2float(h00));
                __half l01 = __float2half_rn(v01 - __half2float(h01));
                __half l10 = __float2half_rn(v10 - __half2float(h10));
                __half l11 = __float2half_rn(v11 - __half2float(h11));
                uint32_t hi0 = (uint32_t)__half_as_ushort(h00) | ((uint32_t)__half_as_ushort(h01) << 16);
                uint32_t hi1 = (uint32_t)__half_as_ushort(h10) | ((uint32_t)__half_as_ushort(h11) << 16);
                uint32_t lo0 = (uint32_t)__half_as_ushort(l00) | ((uint32_t)__half_as_ushort(l01) << 16);
                uint32_t lo1 = (uint32_t)__half_as_ushort(l10) | ((uint32_t)__half_as_ushort(l11) << 16);
                *reinterpret_cast<uint32_t*>(O + (size_t)r0 * 1024 + n0)       = hi0;
                *reinterpret_cast<uint32_t*>(O + (size_t)r0 * 1024 + 512 + n0) = lo0;
                *reinterpret_cast<uint32_t*>(O + (size_t)r1 * 1024 + n0)       = hi1;
                *reinterpret_cast<uint32_t*>(O + (size_t)r1 * 1024 + 512 + n0) = lo1;
            } else {
                float2 v0 = make_float2(c[0] + b0, c[1] + b1);
                float2 v1 = make_float2(c[2] + b0, c[3] + b1);
                *reinterpret_cast<float2*>(Of + (size_t)r0 * DIM + n0) = v0;
                *reinterpret_cast<float2*>(Of + (size_t)r1 * DIM + n0) = v1;
            }
        }
    }
}

// ================= small fp32 GEMM: register-prefetch double-buffered =================
template<int K, bool CONCAT>
__global__ void __launch_bounds__(256) gemm_small(
    const float* __restrict__ A0, const float* __restrict__ A1,
    const float* __restrict__ W, const float* __restrict__ bias,
    float* __restrict__ C)
{
    constexpr int BM = 64, BN = 64, BK = 32;
    constexpr int NIT = K / BK;
    constexpr int halfK = K / 2;
    __shared__ __align__(16) float As[2][BK][BM];
    __shared__ __align__(16) float Bs[2][BK][BN];

    const int tid = threadIdx.x;
    const int bm = blockIdx.y * BM, bn = blockIdx.x * BN;
    const int tx = tid & 15, ty = tid >> 4;

    float4 pa[2], pb[2];
    auto gload = [&](int it) {
        int k0 = it * BK;
        #pragma unroll
        for (int j = 0; j < 2; j++) {
            int f = tid + j * 256;
            int r = f >> 3, c4 = (f & 7) * 4;
            int gk = k0 + c4;
            const float* srcA;
            if (CONCAT) {
                srcA = (gk < halfK) ? (A0 + (size_t)(bm + r) * halfK + gk)
                                    : (A1 + (size_t)(bm + r) * halfK + (gk - halfK));
            } else {
                srcA = A0 + (size_t)(bm + r) * K + gk;
            }
            pa[j] = *reinterpret_cast<const float4*>(srcA);
            pb[j] = *reinterpret_cast<const float4*>(W + (size_t)(bn + r) * K + gk);
        }
    };
    auto sstore = [&](int buf) {
        #pragma unroll
        for (int j = 0; j < 2; j++) {
            int f = tid + j * 256;
            int r = f >> 3, c4 = (f & 7) * 4;
            As[buf][c4 + 0][r] = pa[j].x; As[buf][c4 + 1][r] = pa[j].y;
            As[buf][c4 + 2][r] = pa[j].z; As[buf][c4 + 3][r] = pa[j].w;
            Bs[buf][c4 + 0][r] = pb[j].x; Bs[buf][c4 + 1][r] = pb[j].y;
            Bs[buf][c4 + 2][r] = pb[j].z; Bs[buf][c4 + 3][r] = pb[j].w;
        }
    };

    float acc[4][4];
    #pragma unroll
    for (int i = 0; i < 4; i++)
        #pragma unroll
        for (int j = 0; j < 4; j++) acc[i][j] = 0.f;

    gload(0); sstore(0); __syncthreads();
    for (int it = 0; it < NIT; ++it) {
        if (it + 1 < NIT) gload(it + 1);
        const int buf = it & 1;
        #pragma unroll
        for (int kk = 0; kk < BK; kk++) {
            float4 a = *reinterpret_cast<const float4*>(&As[buf][kk][ty * 4]);
            float4 b = *reinterpret_cast<const float4*>(&Bs[buf][kk][tx * 4]);
            acc[0][0] = fmaf(a.x, b.x, acc[0][0]); acc[0][1] = fmaf(a.x, b.y, acc[0][1]);
            acc[0][2] = fmaf(a.x, b.z, acc[0][2]); acc[0][3] = fmaf(a.x, b.w, acc[0][3]);
            acc[1][0] = fmaf(a.y, b.x, acc[1][0]); acc[1][1] = fmaf(a.y, b.y, acc[1][1]);
            acc[1][2] = fmaf(a.y, b.z, acc[1][2]); acc[1][3] = fmaf(a.y, b.w, acc[1][3]);
            acc[2][0] = fmaf(a.z, b.x, acc[2][0]); acc[2][1] = fmaf(a.z, b.y, acc[2][1]);
            acc[2][2] = fmaf(a.z, b.z, acc[2][2]); acc[2][3] = fmaf(a.z, b.w, acc[2][3]);
            acc[3][0] = fmaf(a.w, b.x, acc[3][0]); acc[3][1] = fmaf(a.w, b.y, acc[3][1]);
            acc[3][2] = fmaf(a.w, b.z, acc[3][2]); acc[3][3] = fmaf(a.w, b.w, acc[3][3]);
        }
        __syncthreads();
        if (it + 1 < NIT) { sstore((it + 1) & 1); __syncthreads(); }
    }

    float bb[4];
    #pragma unroll
    for (int j = 0; j < 4; j++) bb[j] = bias ? bias[bn + tx * 4 + j] : 0.f;
    #pragma unroll
    for (int i = 0; i < 4; i++) {
        int gm = bm + ty * 4 + i;
        float4 v = make_float4(acc[i][0] + bb[0], acc[i][1] + bb[1],
                               acc[i][2] + bb[2], acc[i][3] + bb[3]);
        *reinterpret_cast<float4*>(&C[(size_t)gm * DIM + bn + tx * 4]) = v;
    }
}

// ================= conversions =================
// weights -> fp16 (hi only)
__global__ void halve_w_kernel(const float* __restrict__ w, __half* __restrict__ o, int n)
{
    int i = blockIdx.x * 256 + threadIdx.x;
    if (i < n) o[i] = __float2half_rn(w[i]);
}

// k [B,D,P] -> kT2 [B*P][2][512] fp16 hi/lo
__global__ void transpose_split_k(const float* __restrict__ k, __half* __restrict__ kT2)
{
    __shared__ float tile[32][33];
    int b  = blockIdx.z;
    int p0 = blockIdx.x * 32;
    int c0 = blockIdx.y * 32;
    int tx = threadIdx.x, ty = threadIdx.y;
    #pragma unroll
    for (int j = 0; j < 32; j += 8) {
        int c = c0 + ty + j, p = p0 + tx;
        if (p < PIX) tile[ty + j][tx] = k[((size_t)b * DIM + c) * PIX + p];
    }
    __syncthreads();
    #pragma unroll
    for (int j = 0; j < 32; j += 8) {
        int p = p0 + ty + j, c = c0 + tx;
        if (p < PIX) {
            float v = tile[tx][ty + j];
            __half h = __float2half_rn(v);
            size_t o = ((size_t)b * PIX + p) * 1024 + c;
            kT2[o]       = h;
            kT2[o + 512] = __float2half_rn(v - __half2float(h));
        }
    }
}

// ---------------- reduction helpers ----------------
template<int NW>
__device__ __forceinline__ float blkSum(float v, float* red) {
    #pragma unroll
    for (int o = 16; o > 0; o >>= 1) v += __shfl_xor_sync(0xffffffffu, v, o);
    __syncthreads();
    if ((threadIdx.x & 31) == 0) red[threadIdx.x >> 5] = v;
    __syncthreads();
    float s = 0.f;
    #pragma unroll
    for (int i = 0; i < NW; i++) s += red[i];
    return s;
}

// ---------------- ControlUnit tail ----------------
__global__ void control_kernel(const float* __restrict__ cq, const float* __restrict__ cw,
                               const int* __restrict__ mask, const float* __restrict__ Wca,
                               const float* __restrict__ bca,
                               float* __restrict__ cv_out, float* __restrict__ cnew)
{
    int b = blockIdx.x, tid = threadIdx.x;   // 256 threads
    __shared__ float u[DIM];
    __shared__ float s[LW];
    __shared__ float red[8];
    for (int d = tid; d < DIM; d += 256) u[d] = cq[(size_t)b * DIM + d] * Wca[d];
    __syncthreads();
    const float* cwb = cw + (size_t)b * LW * DIM;
    for (int l = 0; l < LW; l++) {
        float p = 0.f;
        for (int d = tid; d < DIM; d += 256) p += u[d] * cwb[(size_t)l * DIM + d];
        float tot = blkSum<8>(p, red);
        if (tid == 0) s[l] = (mask[b * LW + l] > 0) ? (tot + bca[0]) : -INFINITY;
    }
    __syncthreads();
    if (tid == 0) {
        float mx = -INFINITY;
        for (int l = 0; l < LW; l++) mx = fmaxf(mx, s[l]);
        float sm = 0.f;
        for (int l = 0; l < LW; l++) { float e = __expf(s[l] - mx); s[l] = e; sm += e; }
        float inv = 1.f / sm;
        for (int l = 0; l < LW; l++) { s[l] *= inv; cv_out[b * LW + l] = s[l]; }
    }
    __syncthreads();
    for (int d = tid; d < DIM; d += 256) {
        float a = 0.f;
        for (int l = 0; l < LW; l++) a = fmaf(s[l], cwb[(size_t)l * DIM + d], a);
        cnew[(size_t)b * DIM + d] = a;
    }
}

// ---------------- softmax over channels: warp-per-pixel, 28-pixel write staging ----------
#define SMRV_TILE_STRIDE 517
#define SMRV_SMEM (28*SMRV_TILE_STRIDE*4)

__global__ void __launch_bounds__(512) softmax_rv_kernel(
    const float* __restrict__ ra, const __half* __restrict__ kT2,
    float* __restrict__ rv_out, float* __restrict__ r_out)
{
    extern __shared__ float tile[];          // [28][517]
    __shared__ float rsum[DIM];
    const int b = blockIdx.x, tid = threadIdx.x;
    const int w = tid >> 5, lane = tid & 31;
    const float* rab = ra + (size_t)b * PIX * DIM;
    const __half* kb = kT2 + (size_t)b * PIX * 1024;
    float* rvb = rv_out + (size_t)b * DIM * PIX;

    if (tid < DIM) rsum[tid] = 0.f;
    float racc[16];
    #pragma unroll
    for (int j = 0; j < 16; j++) racc[j] = 0.f;
    __syncthreads();

    for (int pp = 0; pp < 7; pp++) {
        if (w < 14) {
            #pragma unroll
            for (int half = 0; half < 2; half++) {
                const int i = half * 14 + w;
                const int p = pp * 28 + i;
                float x[16];
                #pragma unroll
                for (int q = 0; q < 4; q++) {
                    float4 v = *reinterpret_cast<const float4*>(rab + (size_t)p * DIM + q * 128 + lane * 4);
                    x[q * 4 + 0] = v.x; x[q * 4 + 1] = v.y; x[q * 4 + 2] = v.z; x[q * 4 + 3] = v.w;
                }
                float mx = x[0];
                #pragma unroll
                for (int j = 1; j < 16; j++) mx = fmaxf(mx, x[j]);
                #pragma unroll
                for (int o = 16; o > 0; o >>= 1) mx = fmaxf(mx, __shfl_xor_sync(0xffffffffu, mx, o));
                float sm = 0.f;
                #pragma unroll
                for (int j = 0; j < 16; j++) { x[j] = __expf(x[j] - mx); sm += x[j]; }
                #pragma unroll
                for (int o = 16; o > 0; o >>= 1) sm += __shfl_xor_sync(0xffffffffu, sm, o);
                const float inv = 1.f / sm;
                #pragma unroll
                for (int q = 0; q < 4; q++) {
                    float rv0 = x[q * 4 + 0] * inv, rv1 = x[q * 4 + 1] * inv;
                    float rv2 = x[q * 4 + 2] * inv, rv3 = x[q * 4 + 3] * inv;
                    float* tr = &tile[i * SMRV_TILE_STRIDE + q * 128 + lane * 4];
                    tr[0] = rv0; tr[1] = rv1; tr[2] = rv2; tr[3] = rv3;
                    const size_t kidx = (size_t)p * 1024 + q * 128 + lane * 4;
                    __half2 kh0 = *reinterpret_cast<const __half2*>(kb + kidx);
                    __half2 kh1 = *reinterpret_cast<const __half2*>(kb + kidx + 2);
                    __half2 kl0 = *reinterpret_cast<const __half2*>(kb + kidx + 512);
                    __half2 kl1 = *reinterpret_cast<const __half2*>(kb + kidx + 514);
                    racc[q * 4 + 0] = fmaf(rv0, __half2float(kh0.x) + __half2float(kl0.x), racc[q * 4 + 0]);
                    racc[q * 4 + 1] = fmaf(rv1, __half2float(kh0.y) + __half2float(kl0.y), racc[q * 4 + 1]);
                    racc[q * 4 + 2] = fmaf(rv2, __half2float(kh1.x) + __half2float(kl1.x), racc[q * 4 + 2]);
                    racc[q * 4 + 3] = fmaf(rv3, __half2float(kh1.y) + __half2float(kl1.y), racc[q * 4 + 3]);
                }
            }
        }
        __syncthreads();
        #pragma unroll 1
        for (int cc = 0; cc < 32; cc++) {
            int c = w * 32 + cc;
            if (lane < 28) rvb[(size_t)c * PIX + pp * 28 + lane] = tile[lane * SMRV_TILE_STRIDE + c];
        }
        __syncthreads();
    }

    #pragma unroll
    for (int q = 0; q < 4; q++)
        #pragma unroll
        for (int j = 0; j < 4; j++)
            atomicAdd(&rsum[q * 128 + lane * 4 + j], racc[q * 4 + j]);
    __syncthreads();
    if (tid < DIM) r_out[(size_t)b * DIM + tid] = rsum[tid];
}

// ---------------- gate, sa softmax over T, m_sa ----------------
__global__ void gate_sa_kernel(const float* __restrict__ cnew, const float* __restrict__ Wc,
                               const float* __restrict__ bc,   const float* __restrict__ cs,
                               const float* __restrict__ Wsa,  const float* __restrict__ bsa,
                               const float* __restrict__ ms,
                               float* __restrict__ gate_out, float* __restrict__ msa_out)
{
    int b = blockIdx.x, tid = threadIdx.x;   // 256 threads
    __shared__ float red[8];
    __shared__ float sa[TT];
    __shared__ float gsh;
    float p = 0.f;
    for (int d = tid; d < DIM; d += 256) p += cnew[(size_t)b * DIM + d] * Wc[d];
    float tot = blkSum<8>(p, red);
    if (tid == 0) gsh = 1.f / (1.f + __expf(-(tot + bc[0])));
    __syncthreads();
    float gate = gsh;
    for (int t8 = 0; t8 < TT; t8++) {
        float qv = 0.f;
        const float* csrow = cs + ((size_t)t8 * BATCH + b) * DIM;
        for (int d = tid; d < DIM; d += 256) qv += csrow[d] * Wsa[d];
        float qt = blkSum<8>(qv, red);
        if (tid == 0) sa[t8] = gate * qt + bsa[0];
    }
    __syncthreads();
    if (tid == 0) {
        float mx = -INFINITY;
        for (int i = 0; i < TT; i++) mx = fmaxf(mx, sa[i]);
        float sm = 0.f;
        for (int i = 0; i < TT; i++) { float e = __expf(sa[i] - mx); sa[i] = e; sm += e; }
        float inv = 1.f / sm;
        for (int i = 0; i < TT; i++) sa[i] *= inv;
    }
    __syncthreads();
    for (int d = tid; d < DIM; d += 256) {
        float a = 0.f;
        #pragma unroll
        for (int i = 0; i < TT; i++)
            a = fmaf(sa[i], ms[((size_t)i * BATCH + b) * DIM + d], a);
        msa_out[(size_t)b * DIM + d] = a;
    }
    if (tid == 0) gate_out[b] = gate;
}

// ---------------- final ----------------
__global__ void final_kernel(const float* __restrict__ m, const float* __restrict__ mm,
                             const float* __restrict__ tmp, const float* __restrict__ gate,
                             float* __restrict__ mnew)
{
    int i = blockIdx.x * 256 + threadIdx.x;
    int b = i >> 9;
    float g = gate[b];
    mnew[i] = g * m[i] + (1.f - g) * (mm[i] + tmp[i]);
}

// ---------------- launch ----------------
extern "C" void kernel_launch(void* const* d_in, const int* in_sizes, int n_in,
                              void* d_out, int out_size)
{
    const float* c    = (const float*)d_in[0];
    const float* m    = (const float*)d_in[1];
    const float* k    = (const float*)d_in[2];
    const float* q    = (const float*)d_in[3];
    const float* cw   = (const float*)d_in[4];
    const int*   mask = (const int*)  d_in[5];
    const float* cs   = (const float*)d_in[6];
    const float* ms   = (const float*)d_in[7];
    const float* Wcq  = (const float*)d_in[8];
    const float* bcq  = (const float*)d_in[9];
    const float* Wca  = (const float*)d_in[10];
    const float* bca  = (const float*)d_in[11];
    const float* Wm_r = (const float*)d_in[12];
    const float* bm_r = (const float*)d_in[13];
    const float* Wk   = (const float*)d_in[14];
    const float* bk   = (const float*)d_in[15];
    const float* WI   = (const float*)d_in[16];
    const float* bI   = (const float*)d_in[17];
    const float* Wra  = (const float*)d_in[18];
    const float* bra  = (const float*)d_in[19];
    const float* Wm_w = (const float*)d_in[20];
    const float* bm_w = (const float*)d_in[21];
    const float* Wsa  = (const float*)d_in[22];
    const float* bsa  = (const float*)d_in[23];
    const float* Wm2  = (const float*)d_in[24];
    const float* bm2  = (const float*)d_in[25];
    const float* Wc   = (const float*)d_in[26];
    const float* bc   = (const float*)d_in[27];
    const float* Ws   = (const float*)d_in[28];

    float* out      = (float*)d_out;
    float* out_cnew = out;                       // [B,D]
    float* out_mnew = out + 131072;              // [B,D]
    float* out_cv   = out + 262144;              // [B,L]
    float* out_rv   = out + 270336;              // [B,D,H,W]

    __half *p_kT2, *p_I2, *p_J2, *p_Wk2, *p_WI2, *p_Wra2;
    float *p_ra, *p_cq, *p_mI, *p_r, *p_mprev, *p_mm, *p_msa, *p_tmp, *p_gate;
    cudaGetSymbolAddress((void**)&p_kT2,  g_kT2);
    cudaGetSymbolAddress((void**)&p_I2,   g_I2);
    cudaGetSymbolAddress((void**)&p_J2,   g_J2);
    cudaGetSymbolAddress((void**)&p_Wk2,  g_Wk2);
    cudaGetSymbolAddress((void**)&p_WI2,  g_WI2);
    cudaGetSymbolAddress((void**)&p_Wra2, g_Wra2);
    cudaGetSymbolAddress((void**)&p_ra,   g_ra);
    cudaGetSymbolAddress((void**)&p_cq,   g_cq);
    cudaGetSymbolAddress((void**)&p_mI,   g_mI);
    cudaGetSymbolAddress((void**)&p_r,    g_r);
    cudaGetSymbolAddress((void**)&p_mprev,g_mprev);
    cudaGetSymbolAddress((void**)&p_mm,   g_mm);
    cudaGetSymbolAddress((void**)&p_msa,  g_msa);
    cudaGetSymbolAddress((void**)&p_tmp,  g_tmp);
    cudaGetSymbolAddress((void**)&p_gate, g_gate);

    cudaFuncSetAttribute(mma_gemm<512,  false, 0>, cudaFuncAttributeMaxDynamicSharedMemorySize, MG_SMEM);
    cudaFuncSetAttribute(mma_gemm<1024, true,  0>, cudaFuncAttributeMaxDynamicSharedMemorySize, MG_SMEM);
    cudaFuncSetAttribute(mma_gemm<512,  false, 1>, cudaFuncAttributeMaxDynamicSharedMemorySize, MG_SMEM);
    cudaFuncSetAttribute(softmax_rv_kernel, cudaFuncAttributeMaxDynamicSharedMemorySize, SMRV_SMEM);

    // ---- ordered so my 4th launch = mma_gemm I (ncu -s 5 -c 1 visibility) ----
    // 1. Wk -> fp16
    halve_w_kernel<<<(DIM*DIM + 255)/256, 256>>>(Wk, p_Wk2, DIM*DIM);
    // 2. k -> kT fp16 hi/lo
    transpose_split_k<<<dim3(7, 16, BATCH), dim3(32, 8)>>>(k, p_kT2);
    // 3. mI = m @ Wm_r^T + bm_r
    gemm_small<512, false><<<dim3(8, 4), 256>>>(m, nullptr, Wm_r, bm_r, p_mI);
    // 4. I = mI ⊙ (kT @ Wk^T + bk) -> fp16 hi/lo     [HMMA]  << profiled
    mma_gemm<512, false, 0><<<dim3(4, 392), 256, MG_SMEM>>>(
        p_kT2, nullptr, p_Wk2, bk, p_mI, p_I2, nullptr);
    // 5. WI -> fp16
    halve_w_kernel<<<(DIM*2*DIM + 255)/256, 256>>>(WI, p_WI2, DIM*2*DIM);
    // 6. cq = [c|q] @ Wcq^T + bcq
    gemm_small<1024, true><<<dim3(8, 4), 256>>>(c, q, Wcq, bcq, p_cq);
    // 7. ControlUnit tail -> cv, c_new
    control_kernel<<<BATCH, 256>>>(p_cq, cw, mask, Wca, bca, out_cv, out_cnew);
    // 8. J = c_new ⊙ ([I|kT] @ WI^T + bI) -> fp16 hi/lo  [HMMA]
    mma_gemm<1024, true, 0><<<dim3(4, 392), 256, MG_SMEM>>>(
        p_I2, p_kT2, p_WI2, bI, out_cnew, p_J2, nullptr);
    // 9. Wra -> fp16
    halve_w_kernel<<<(DIM*DIM + 255)/256, 256>>>(Wra, p_Wra2, DIM*DIM);
    // 10. ra = J @ Wra^T + bra -> fp32                [HMMA]
    mma_gemm<512, false, 1><<<dim3(4, 392), 256, MG_SMEM>>>(
        p_J2, nullptr, p_Wra2, bra, nullptr, nullptr, p_ra);
    // 11. rv = softmax_c(ra) -> d_out (transposed), r = sum_p rv*k
    softmax_rv_kernel<<<BATCH, 512, SMRV_SMEM>>>(p_ra, p_kT2, out_rv, p_r);
    // 12. m_prev = [r|m] @ Wm_w^T + bm_w
    gemm_small<1024, true><<<dim3(8, 4), 256>>>(p_r, m, Wm_w, bm_w, p_mprev);
    // 13. m_ = m_prev @ Wm2^T + bm2
    gemm_small<512, false><<<dim3(8, 4), 256>>>(p_mprev, nullptr, Wm2, bm2, p_mm);
    // 14. gate, sa softmax, m_sa
    gate_sa_kernel<<<BATCH, 256>>>(out_cnew, Wc, bc, cs, Wsa, bsa, ms, p_gate, p_msa);
    // 15. tmp = m_sa @ Ws^T
    gemm_small<512, false><<<dim3(8, 4), 256>>>(p_msa, nullptr, Ws, nullptr, p_tmp);
    // 16. m_new = gate*m + (1-gate)*(m_ + tmp)
    final_kernel<<<(BATCH * DIM) / 256, 256>>>(m, p_mm, p_tmp, p_gate, out_mnew);
}

// round 8
// speedup vs baseline: 1.6905x; 1.3507x over previous
#include <cuda_runtime.h>
#include <cuda_bf16.h>
#include <cuda_fp16.h>
#include <math.h>
#include <stdint.h>

#define BATCH 256
#define DIM   512
#define LW    32
#define PIX   196
#define TT    8
#define MBIG  (BATCH*PIX)   // 50176

// ---------------- scratch (static __device__ — allocation-guard safe) ----------------
// kT: [B*P][2][512] fp16 hi/lo (GEMMs read hi at stride 1024; softmax reads both)
__device__ __half g_kT2[MBIG*1024];
__device__ __half g_I2 [MBIG*512];     // plain fp16, stride 512
__device__ __half g_J2 [MBIG*512];
__device__ float g_ra  [MBIG*DIM];
__device__ __half g_Wk2 [DIM*DIM];
__device__ __half g_WI2 [DIM*2*DIM];
__device__ __half g_Wra2[DIM*DIM];
__device__ float g_cq  [BATCH*DIM];
__device__ float g_mI  [BATCH*DIM];
__device__ float g_r   [BATCH*DIM];
__device__ float g_mprev[BATCH*DIM];
__device__ float g_mm  [BATCH*DIM];
__device__ float g_msa [BATCH*DIM];
__device__ float g_tmp [BATCH*DIM];
__device__ float g_gate[BATCH];

// ================= helpers =================
__device__ __forceinline__ uint32_t smem_u32(const void* p) {
    uint32_t a;
    asm("{ .reg .u64 t; cvta.to.shared.u64 t, %1; cvt.u32.u64 %0, t; }" : "=r"(a) : "l"(p));
    return a;
}
__device__ __forceinline__ void cpasync16(uint32_t dst, const void* src) {
    asm volatile("cp.async.cg.shared.global [%0], [%1], 16;" :: "r"(dst), "l"(src) : "memory");
}
__device__ __forceinline__ void cp_commit() { asm volatile("cp.async.commit_group;" ::: "memory"); }
__device__ __forceinline__ void cp_wait2() { asm volatile("cp.async.wait_group 2;" ::: "memory"); }
__device__ __forceinline__ void cp_wait1() { asm volatile("cp.async.wait_group 1;" ::: "memory"); }
__device__ __forceinline__ void cp_wait0() { asm volatile("cp.async.wait_group 0;" ::: "memory"); }

__device__ __forceinline__ void ldm_x4(uint32_t& r0, uint32_t& r1, uint32_t& r2, uint32_t& r3, uint32_t a) {
    asm volatile("ldmatrix.sync.aligned.m8n8.x4.shared.b16 {%0,%1,%2,%3}, [%4];"
                 : "=r"(r0), "=r"(r1), "=r"(r2), "=r"(r3) : "r"(a));
}
__device__ __forceinline__ void mma16816h(float* c, const uint32_t* a, const uint32_t* b) {
    asm volatile("mma.sync.aligned.m16n8k16.row.col.f32.f16.f16.f32 "
                 "{%0,%1,%2,%3}, {%4,%5,%6,%7}, {%8,%9}, {%0,%1,%2,%3};"
                 : "+f"(c[0]), "+f"(c[1]), "+f"(c[2]), "+f"(c[3])
                 : "r"(a[0]), "r"(a[1]), "r"(a[2]), "r"(a[3]), "r"(b[0]), "r"(b[1]));
}

// ================= HMMA pure-fp16 GEMM =================
// A fp16 [row][AS] (AS=512 plain or 1024 = hi part of hi/lo); W [N][K] fp16.
// 4-stage cp.async ring (16KB/stage), prefetch distance 3.
// EPI 0: v = (acc + bias[n]) * scale[m/PIX, n] -> fp16 into O[row][512]
// EPI 1: v = acc + bias[n] -> fp32 Of[m][n]
#define MG_STAGE 16384
#define MG_SMEM  (4*MG_STAGE)

template<int K, bool CONCAT, int EPI, int AS0, int AS1>
__global__ void __launch_bounds__(256, 2) mma_gemm(
    const __half* __restrict__ A0, const __half* __restrict__ A1,
    const __half* __restrict__ W,
    const float* __restrict__ bias, const float* __restrict__ scale,
    __half* __restrict__ O, float* __restrict__ Of)
{
    constexpr int KIT = K / 32;
    extern __shared__ __align__(128) char dsm[];
    const uint32_t smb = smem_u32(dsm);

    const int tid = threadIdx.x, lane = tid & 31, wid = tid >> 5;
    const int bm = blockIdx.y * 128, bn = blockIdx.x * 128;
    const int wm = (wid >> 2) * 64, wn = (wid & 3) * 32;

    float acc[4][4][4];
    #pragma unroll
    for (int i = 0; i < 4; i++)
        #pragma unroll
        for (int j = 0; j < 4; j++)
            #pragma unroll
            for (int v = 0; v < 4; v++) acc[i][j][v] = 0.f;

    auto load_stage = [&](int it, int stage) {
        uint32_t sb = smb + (uint32_t)stage * MG_STAGE;
        int k0 = it * 32;
        const __half* Asrc;
        int ac;
        int as;
        if (CONCAT && k0 >= 512) { Asrc = A1; ac = k0 - 512; as = AS1; }
        else                     { Asrc = A0; ac = k0;       as = AS0; }
        const int cc = tid & 3;
        #pragma unroll
        for (int j = 0; j < 2; j++) {
            int row = (tid >> 2) + j * 64;
            uint32_t d = sb + row * 64 + ((cc * 16) ^ (((row >> 1) & 3) << 4));
            cpasync16(d, Asrc + (size_t)(bm + row) * as + ac + cc * 8);       // A
            cpasync16(d + 8192u, W + (size_t)(bn + row) * K + k0 + cc * 8);   // W
        }
    };

    load_stage(0, 0); cp_commit();
    load_stage(1, 1); cp_commit();
    load_stage(2, 2); cp_commit();

    for (int it = 0; it < KIT; ++it) {
        if (it + 3 <= KIT) cp_wait2();
        else if (it + 2 == KIT) cp_wait1();
        else cp_wait0();
        __syncthreads();
        if (it + 3 < KIT) { load_stage(it + 3, (it + 3) & 3); cp_commit(); }

        const uint32_t sb = smb + (uint32_t)(it & 3) * MG_STAGE;
        const uint32_t sA = sb, sB = sb + 8192u;
        #pragma unroll
        for (int kp = 0; kp < 2; kp++) {
            uint32_t bf[2][4];
            #pragma unroll
            for (int pr = 0; pr < 2; pr++) {
                int nrow = wn + pr * 16 + ((lane >> 4) << 3) + (lane & 7);
                int chunk = (kp * 2 + ((lane >> 3) & 1)) ^ ((nrow >> 1) & 3);
                ldm_x4(bf[pr][0], bf[pr][1], bf[pr][2], bf[pr][3], sB + nrow * 64 + chunk * 16);
            }
            #pragma unroll
            for (int mi = 0; mi < 4; mi++) {
                uint32_t ah[4];
                int row = wm + mi * 16 + (lane & 15);
                int chunk = (kp * 2 + (lane >> 4)) ^ ((row >> 1) & 3);
                ldm_x4(ah[0], ah[1], ah[2], ah[3], sA + row * 64 + chunk * 16);
                #pragma unroll
                for (int ni = 0; ni < 4; ni++)
                    mma16816h(acc[mi][ni], ah, &bf[ni >> 1][(ni & 1) * 2]);
            }
        }
    }

    // ---------------- epilogue ----------------
    #pragma unroll
    for (int ni = 0; ni < 4; ni++) {
        const int n0 = bn + wn + ni * 8 + 2 * (lane & 3);
        const float b0 = bias[n0], b1 = bias[n0 + 1];
        #pragma unroll
        for (int mi = 0; mi < 4; mi++) {
            const int r0 = bm + wm + mi * 16 + (lane >> 2);
            const int r1 = r0 + 8;
            float* c = acc[mi][ni];
            if (EPI == 0) {
                const float* s0 = scale + (size_t)(r0 / PIX) * DIM;
                const float* s1 = scale + (size_t)(r1 / PIX) * DIM;
                float v00 = (c[0] + b0) * s0[n0], v01 = (c[1] + b1) * s0[n0 + 1];
                float v10 = (c[2] + b0) * s1[n0], v11 = (c[3] + b1) * s1[n0 + 1];
                __half2 h0 = __floats2half2_rn(v00, v01);
                __half2 h1 = __floats2half2_rn(v10, v11);
                *reinterpret_cast<__half2*>(O + (size_t)r0 * 512 + n0) = h0;
                *reinterpret_cast<__half2*>(O + (size_t)r1 * 512 + n0) = h1;
            } else {
                float2 v0 = make_float2(c[0] + b0, c[1] + b1);
                float2 v1 = make_float2(c[2] + b0, c[3] + b1);
                *reinterpret_cast<float2*>(Of + (size_t)r0 * DIM + n0) = v0;
                *reinterpret_cast<float2*>(Of + (size_t)r1 * DIM + n0) = v1;
            }
        }
    }
}

// ================= small fp32 GEMM: register-prefetch double-buffered =================
template<int K, bool CONCAT>
__global__ void __launch_bounds__(256) gemm_small(
    const float* __restrict__ A0, const float* __restrict__ A1,
    const float* __restrict__ W, const float* __restrict__ bias,
    float* __restrict__ C)
{
    constexpr int BM = 64, BN = 64, BK = 32;
    constexpr int NIT = K / BK;
    constexpr int halfK = K / 2;
    __shared__ __align__(16) float As[2][BK][BM];
    __shared__ __align__(16) float Bs[2][BK][BN];

    const int tid = threadIdx.x;
    const int bm = blockIdx.y * BM, bn = blockIdx.x * BN;
    const int tx = tid & 15, ty = tid >> 4;

    float4 pa[2], pb[2];
    auto gload = [&](int it) {
        int k0 = it * BK;
        #pragma unroll
        for (int j = 0; j < 2; j++) {
            int f = tid + j * 256;
            int r = f >> 3, c4 = (f & 7) * 4;
            int gk = k0 + c4;
            const float* srcA;
            if (CONCAT) {
                srcA = (gk < halfK) ? (A0 + (size_t)(bm + r) * halfK + gk)
                                    : (A1 + (size_t)(bm + r) * halfK + (gk - halfK));
            } else {
                srcA = A0 + (size_t)(bm + r) * K + gk;
            }
            pa[j] = *reinterpret_cast<const float4*>(srcA);
            pb[j] = *reinterpret_cast<const float4*>(W + (size_t)(bn + r) * K + gk);
        }
    };
    auto sstore = [&](int buf) {
        #pragma unroll
        for (int j = 0; j < 2; j++) {
            int f = tid + j * 256;
            int r = f >> 3, c4 = (f & 7) * 4;
            As[buf][c4 + 0][r] = pa[j].x; As[buf][c4 + 1][r] = pa[j].y;
            As[buf][c4 + 2][r] = pa[j].z; As[buf][c4 + 3][r] = pa[j].w;
            Bs[buf][c4 + 0][r] = pb[j].x; Bs[buf][c4 + 1][r] = pb[j].y;
            Bs[buf][c4 + 2][r] = pb[j].z; Bs[buf][c4 + 3][r] = pb[j].w;
        }
    };

    float acc[4][4];
    #pragma unroll
    for (int i = 0; i < 4; i++)
        #pragma unroll
        for (int j = 0; j < 4; j++) acc[i][j] = 0.f;

    gload(0); sstore(0); __syncthreads();
    for (int it = 0; it < NIT; ++it) {
        if (it + 1 < NIT) gload(it + 1);
        const int buf = it & 1;
        #pragma unroll
        for (int kk = 0; kk < BK; kk++) {
            float4 a = *reinterpret_cast<const float4*>(&As[buf][kk][ty * 4]);
            float4 b = *reinterpret_cast<const float4*>(&Bs[buf][kk][tx * 4]);
            acc[0][0] = fmaf(a.x, b.x, acc[0][0]); acc[0][1] = fmaf(a.x, b.y, acc[0][1]);
            acc[0][2] = fmaf(a.x, b.z, acc[0][2]); acc[0][3] = fmaf(a.x, b.w, acc[0][3]);
            acc[1][0] = fmaf(a.y, b.x, acc[1][0]); acc[1][1] = fmaf(a.y, b.y, acc[1][1]);
            acc[1][2] = fmaf(a.y, b.z, acc[1][2]); acc[1][3] = fmaf(a.y, b.w, acc[1][3]);
            acc[2][0] = fmaf(a.z, b.x, acc[2][0]); acc[2][1] = fmaf(a.z, b.y, acc[2][1]);
            acc[2][2] = fmaf(a.z, b.z, acc[2][2]); acc[2][3] = fmaf(a.z, b.w, acc[2][3]);
            acc[3][0] = fmaf(a.w, b.x, acc[3][0]); acc[3][1] = fmaf(a.w, b.y, acc[3][1]);
            acc[3][2] = fmaf(a.w, b.z, acc[3][2]); acc[3][3] = fmaf(a.w, b.w, acc[3][3]);
        }
        __syncthreads();
        if (it + 1 < NIT) { sstore((it + 1) & 1); __syncthreads(); }
    }

    float bb[4];
    #pragma unroll
    for (int j = 0; j < 4; j++) bb[j] = bias ? bias[bn + tx * 4 + j] : 0.f;
    #pragma unroll
    for (int i = 0; i < 4; i++) {
        int gm = bm + ty * 4 + i;
        float4 v = make_float4(acc[i][0] + bb[0], acc[i][1] + bb[1],
                               acc[i][2] + bb[2], acc[i][3] + bb[3]);
        *reinterpret_cast<float4*>(&C[(size_t)gm * DIM + bn + tx * 4]) = v;
    }
}

// ================= conversions =================
__global__ void halve_w_kernel(const float* __restrict__ w, __half* __restrict__ o, int n)
{
    int i = blockIdx.x * 256 + threadIdx.x;
    if (i < n) o[i] = __float2half_rn(w[i]);
}

// k [B,D,P] -> kT2 [B*P][2][512] fp16 hi/lo
__global__ void transpose_split_k(const float* __restrict__ k, __half* __restrict__ kT2)
{
    __shared__ float tile[32][33];
    int b  = blockIdx.z;
    int p0 = blockIdx.x * 32;
    int c0 = blockIdx.y * 32;
    int tx = threadIdx.x, ty = threadIdx.y;
    #pragma unroll
    for (int j = 0; j < 32; j += 8) {
        int c = c0 + ty + j, p = p0 + tx;
        if (p < PIX) tile[ty + j][tx] = k[((size_t)b * DIM + c) * PIX + p];
    }
    __syncthreads();
    #pragma unroll
    for (int j = 0; j < 32; j += 8) {
        int p = p0 + ty + j, c = c0 + tx;
        if (p < PIX) {
            float v = tile[tx][ty + j];
            __half h = __float2half_rn(v);
            size_t o = ((size_t)b * PIX + p) * 1024 + c;
            kT2[o]       = h;
            kT2[o + 512] = __float2half_rn(v - __half2float(h));
        }
    }
}

// ---------------- reduction helpers ----------------
template<int NW>
__device__ __forceinline__ float blkSum(float v, float* red) {
    #pragma unroll
    for (int o = 16; o > 0; o >>= 1) v += __shfl_xor_sync(0xffffffffu, v, o);
    __syncthreads();
    if ((threadIdx.x & 31) == 0) red[threadIdx.x >> 5] = v;
    __syncthreads();
    float s = 0.f;
    #pragma unroll
    for (int i = 0; i < NW; i++) s += red[i];
    return s;
}

// ---------------- ControlUnit tail ----------------
__global__ void control_kernel(const float* __restrict__ cq, const float* __restrict__ cw,
                               const int* __restrict__ mask, const float* __restrict__ Wca,
                               const float* __restrict__ bca,
                               float* __restrict__ cv_out, float* __restrict__ cnew)
{
    int b = blockIdx.x, tid = threadIdx.x;   // 256 threads
    __shared__ float u[DIM];
    __shared__ float s[LW];
    __shared__ float red[8];
    for (int d = tid; d < DIM; d += 256) u[d] = cq[(size_t)b * DIM + d] * Wca[d];
    __syncthreads();
    const float* cwb = cw + (size_t)b * LW * DIM;
    for (int l = 0; l < LW; l++) {
        float p = 0.f;
        for (int d = tid; d < DIM; d += 256) p += u[d] * cwb[(size_t)l * DIM + d];
        float tot = blkSum<8>(p, red);
        if (tid == 0) s[l] = (mask[b * LW + l] > 0) ? (tot + bca[0]) : -INFINITY;
    }
    __syncthreads();
    if (tid == 0) {
        float mx = -INFINITY;
        for (int l = 0; l < LW; l++) mx = fmaxf(mx, s[l]);
        float sm = 0.f;
        for (int l = 0; l < LW; l++) { float e = __expf(s[l] - mx); s[l] = e; sm += e; }
        float inv = 1.f / sm;
        for (int l = 0; l < LW; l++) { s[l] *= inv; cv_out[b * LW + l] = s[l]; }
    }
    __syncthreads();
    for (int d = tid; d < DIM; d += 256) {
        float a = 0.f;
        for (int l = 0; l < LW; l++) a = fmaf(s[l], cwb[(size_t)l * DIM + d], a);
        cnew[(size_t)b * DIM + d] = a;
    }
}

// ---------------- softmax over channels: warp-per-pixel, 28-pixel write staging ----------
#define SMRV_TILE_STRIDE 517
#define SMRV_SMEM (28*SMRV_TILE_STRIDE*4)

__global__ void __launch_bounds__(512) softmax_rv_kernel(
    const float* __restrict__ ra, const __half* __restrict__ kT2,
    float* __restrict__ rv_out, float* __restrict__ r_out)
{
    extern __shared__ float tile[];          // [28][517]
    __shared__ float rsum[DIM];
    const int b = blockIdx.x, tid = threadIdx.x;
    const int w = tid >> 5, lane = tid & 31;
    const float* rab = ra + (size_t)b * PIX * DIM;
    const __half* kb = kT2 + (size_t)b * PIX * 1024;
    float* rvb = rv_out + (size_t)b * DIM * PIX;

    if (tid < DIM) rsum[tid] = 0.f;
    float racc[16];
    #pragma unroll
    for (int j = 0; j < 16; j++) racc[j] = 0.f;
    __syncthreads();

    for (int pp = 0; pp < 7; pp++) {
        if (w < 14) {
            #pragma unroll
            for (int half = 0; half < 2; half++) {
                const int i = half * 14 + w;
                const int p = pp * 28 + i;
                float x[16];
                #pragma unroll
                for (int q = 0; q < 4; q++) {
                    float4 v = *reinterpret_cast<const float4*>(rab + (size_t)p * DIM + q * 128 + lane * 4);
                    x[q * 4 + 0] = v.x; x[q * 4 + 1] = v.y; x[q * 4 + 2] = v.z; x[q * 4 + 3] = v.w;
                }
                float mx = x[0];
                #pragma unroll
                for (int j = 1; j < 16; j++) mx = fmaxf(mx, x[j]);
                #pragma unroll
                for (int o = 16; o > 0; o >>= 1) mx = fmaxf(mx, __shfl_xor_sync(0xffffffffu, mx, o));
                float sm = 0.f;
                #pragma unroll
                for (int j = 0; j < 16; j++) { x[j] = __expf(x[j] - mx); sm += x[j]; }
                #pragma unroll
                for (int o = 16; o > 0; o >>= 1) sm += __shfl_xor_sync(0xffffffffu, sm, o);
                const float inv = 1.f / sm;
                #pragma unroll
                for (int q = 0; q < 4; q++) {
                    float rv0 = x[q * 4 + 0] * inv, rv1 = x[q * 4 + 1] * inv;
                    float rv2 = x[q * 4 + 2] * inv, rv3 = x[q * 4 + 3] * inv;
                    float* tr = &tile[i * SMRV_TILE_STRIDE + q * 128 + lane * 4];
                    tr[0] = rv0; tr[1] = rv1; tr[2] = rv2; tr[3] = rv3;
                    const size_t kidx = (size_t)p * 1024 + q * 128 + lane * 4;
                    __half2 kh0 = *reinterpret_cast<const __half2*>(kb + kidx);
                    __half2 kh1 = *reinterpret_cast<const __half2*>(kb + kidx + 2);
                    __half2 kl0 = *reinterpret_cast<const __half2*>(kb + kidx + 512);
                    __half2 kl1 = *reinterpret_cast<const __half2*>(kb + kidx + 514);
                    racc[q * 4 + 0] = fmaf(rv0, __half2float(kh0.x) + __half2float(kl0.x), racc[q * 4 + 0]);
                    racc[q * 4 + 1] = fmaf(rv1, __half2float(kh0.y) + __half2float(kl0.y), racc[q * 4 + 1]);
                    racc[q * 4 + 2] = fmaf(rv2, __half2float(kh1.x) + __half2float(kl1.x), racc[q * 4 + 2]);
                    racc[q * 4 + 3] = fmaf(rv3, __half2float(kh1.y) + __half2float(kl1.y), racc[q * 4 + 3]);
                }
            }
        }
        __syncthreads();
        #pragma unroll 1
        for (int cc = 0; cc < 32; cc++) {
            int c = w * 32 + cc;
            if (lane < 28) rvb[(size_t)c * PIX + pp * 28 + lane] = tile[lane * SMRV_TILE_STRIDE + c];
        }
        __syncthreads();
    }

    #pragma unroll
    for (int q = 0; q < 4; q++)
        #pragma unroll
        for (int j = 0; j < 4; j++)
            atomicAdd(&rsum[q * 128 + lane * 4 + j], racc[q * 4 + j]);
    __syncthreads();
    if (tid < DIM) r_out[(size_t)b * DIM + tid] = rsum[tid];
}

// ---------------- gate, sa softmax over T, m_sa ----------------
__global__ void gate_sa_kernel(const float* __restrict__ cnew, const float* __restrict__ Wc,
                               const float* __restrict__ bc,   const float* __restrict__ cs,
                               const float* __restrict__ Wsa,  const float* __restrict__ bsa,
                               const float* __restrict__ ms,
                               float* __restrict__ gate_out, float* __restrict__ msa_out)
{
    int b = blockIdx.x, tid = threadIdx.x;   // 256 threads
    __shared__ float red[8];
    __shared__ float sa[TT];
    __shared__ float gsh;
    float p = 0.f;
    for (int d = tid; d < DIM; d += 256) p += cnew[(size_t)b * DIM + d] * Wc[d];
    float tot = blkSum<8>(p, red);
    if (tid == 0) gsh = 1.f / (1.f + __expf(-(tot + bc[0])));
    __syncthreads();
    float gate = gsh;
    for (int t8 = 0; t8 < TT; t8++) {
        float qv = 0.f;
        const float* csrow = cs + ((size_t)t8 * BATCH + b) * DIM;
        for (int d = tid; d < DIM; d += 256) qv += csrow[d] * Wsa[d];
        float qt = blkSum<8>(qv, red);
        if (tid == 0) sa[t8] = gate * qt + bsa[0];
    }
    __syncthreads();
    if (tid == 0) {
        float mx = -INFINITY;
        for (int i = 0; i < TT; i++) mx = fmaxf(mx, sa[i]);
        float sm = 0.f;
        for (int i = 0; i < TT; i++) { float e = __expf(sa[i] - mx); sa[i] = e; sm += e; }
        float inv = 1.f / sm;
        for (int i = 0; i < TT; i++) sa[i] *= inv;
    }
    __syncthreads();
    for (int d = tid; d < DIM; d += 256) {
        float a = 0.f;
        #pragma unroll
        for (int i = 0; i < TT; i++)
            a = fmaf(sa[i], ms[((size_t)i * BATCH + b) * DIM + d], a);
        msa_out[(size_t)b * DIM + d] = a;
    }
    if (tid == 0) gate_out[b] = gate;
}

// ---------------- final ----------------
__global__ void final_kernel(const float* __restrict__ m, const float* __restrict__ mm,
                             const float* __restrict__ tmp, const float* __restrict__ gate,
                             float* __restrict__ mnew)
{
    int i = blockIdx.x * 256 + threadIdx.x;
    int b = i >> 9;
    float g = gate[b];
    mnew[i] = g * m[i] + (1.f - g) * (mm[i] + tmp[i]);
}

// ---------------- launch ----------------
extern "C" void kernel_launch(void* const* d_in, const int* in_sizes, int n_in,
                              void* d_out, int out_size)
{
    const float* c    = (const float*)d_in[0];
    const float* m    = (const float*)d_in[1];
    const float* k    = (const float*)d_in[2];
    const float* q    = (const float*)d_in[3];
    const float* cw   = (const float*)d_in[4];
    const int*   mask = (const int*)  d_in[5];
    const float* cs   = (const float*)d_in[6];
    const float* ms   = (const float*)d_in[7];
    const float* Wcq  = (const float*)d_in[8];
    const float* bcq  = (const float*)d_in[9];
    const float* Wca  = (const float*)d_in[10];
    const float* bca  = (const float*)d_in[11];
    const float* Wm_r = (const float*)d_in[12];
    const float* bm_r = (const float*)d_in[13];
    const float* Wk   = (const float*)d_in[14];
    const float* bk   = (const float*)d_in[15];
    const float* WI   = (const float*)d_in[16];
    const float* bI   = (const float*)d_in[17];
    const float* Wra  = (const float*)d_in[18];
    const float* bra  = (const float*)d_in[19];
    const float* Wm_w = (const float*)d_in[20];
    const float* bm_w = (const float*)d_in[21];
    const float* Wsa  = (const float*)d_in[22];
    const float* bsa  = (const float*)d_in[23];
    const float* Wm2  = (const float*)d_in[24];
    const float* bm2  = (const float*)d_in[25];
    const float* Wc   = (const float*)d_in[26];
    const float* bc   = (const float*)d_in[27];
    const float* Ws   = (const float*)d_in[28];

    float* out      = (float*)d_out;
    float* out_cnew = out;                       // [B,D]
    float* out_mnew = out + 131072;              // [B,D]
    float* out_cv   = out + 262144;              // [B,L]
    float* out_rv   = out + 270336;              // [B,D,H,W]

    __half *p_kT2, *p_I2, *p_J2, *p_Wk2, *p_WI2, *p_Wra2;
    float *p_ra, *p_cq, *p_mI, *p_r, *p_mprev, *p_mm, *p_msa, *p_tmp, *p_gate;
    cudaGetSymbolAddress((void**)&p_kT2,  g_kT2);
    cudaGetSymbolAddress((void**)&p_I2,   g_I2);
    cudaGetSymbolAddress((void**)&p_J2,   g_J2);
    cudaGetSymbolAddress((void**)&p_Wk2,  g_Wk2);
    cudaGetSymbolAddress((void**)&p_WI2,  g_WI2);
    cudaGetSymbolAddress((void**)&p_Wra2, g_Wra2);
    cudaGetSymbolAddress((void**)&p_ra,   g_ra);
    cudaGetSymbolAddress((void**)&p_cq,   g_cq);
    cudaGetSymbolAddress((void**)&p_mI,   g_mI);
    cudaGetSymbolAddress((void**)&p_r,    g_r);
    cudaGetSymbolAddress((void**)&p_mprev,g_mprev);
    cudaGetSymbolAddress((void**)&p_mm,   g_mm);
    cudaGetSymbolAddress((void**)&p_msa,  g_msa);
    cudaGetSymbolAddress((void**)&p_tmp,  g_tmp);
    cudaGetSymbolAddress((void**)&p_gate, g_gate);

    cudaFuncSetAttribute((const void*)mma_gemm<512,  false, 0, 1024, 1024>, cudaFuncAttributeMaxDynamicSharedMemorySize, MG_SMEM);
    cudaFuncSetAttribute((const void*)mma_gemm<1024, true,  0, 512, 1024>,  cudaFuncAttributeMaxDynamicSharedMemorySize, MG_SMEM);
    cudaFuncSetAttribute((const void*)mma_gemm<512,  false, 1, 512, 512>,   cudaFuncAttributeMaxDynamicSharedMemorySize, MG_SMEM);
    cudaFuncSetAttribute(softmax_rv_kernel, cudaFuncAttributeMaxDynamicSharedMemorySize, SMRV_SMEM);

    // ---- ordered so my 4th launch = mma_gemm I (ncu -s 5 -c 1 visibility) ----
    // 1. Wk -> fp16
    halve_w_kernel<<<(DIM*DIM + 255)/256, 256>>>(Wk, p_Wk2, DIM*DIM);
    // 2. k -> kT fp16 hi/lo
    transpose_split_k<<<dim3(7, 16, BATCH), dim3(32, 8)>>>(k, p_kT2);
    // 3. mI = m @ Wm_r^T + bm_r
    gemm_small<512, false><<<dim3(8, 4), 256>>>(m, nullptr, Wm_r, bm_r, p_mI);
    // 4. I = mI ⊙ (kT_hi @ Wk^T + bk) -> fp16        [HMMA]  << profiled
    mma_gemm<512, false, 0, 1024, 1024><<<dim3(4, 392), 256, MG_SMEM>>>(
        p_kT2, nullptr, p_Wk2, bk, p_mI, p_I2, nullptr);
    // 5. WI -> fp16
    halve_w_kernel<<<(DIM*2*DIM + 255)/256, 256>>>(WI, p_WI2, DIM*2*DIM);
    // 6. cq = [c|q] @ Wcq^T + bcq
    gemm_small<1024, true><<<dim3(8, 4), 256>>>(c, q, Wcq, bcq, p_cq);
    // 7. ControlUnit tail -> cv, c_new
    control_kernel<<<BATCH, 256>>>(p_cq, cw, mask, Wca, bca, out_cv, out_cnew);
    // 8. J = c_new ⊙ ([I|kT_hi] @ WI^T + bI) -> fp16 [HMMA]
    mma_gemm<1024, true, 0, 512, 1024><<<dim3(4, 392), 256, MG_SMEM>>>(
        p_I2, p_kT2, p_WI2, bI, out_cnew, p_J2, nullptr);
    // 9. Wra -> fp16
    halve_w_kernel<<<(DIM*DIM + 255)/256, 256>>>(Wra, p_Wra2, DIM*DIM);
    // 10. ra = J @ Wra^T + bra -> fp32               [HMMA]
    mma_gemm<512, false, 1, 512, 512><<<dim3(4, 392), 256, MG_SMEM>>>(
        p_J2, nullptr, p_Wra2, bra, nullptr, nullptr, p_ra);
    // 11. rv = softmax_c(ra) -> d_out (transposed), r = sum_p rv*k (exact hi+lo k)
    softmax_rv_kernel<<<BATCH, 512, SMRV_SMEM>>>(p_ra, p_kT2, out_rv, p_r);
    // 12. m_prev = [r|m] @ Wm_w^T + bm_w
    gemm_small<1024, true><<<dim3(8, 4), 256>>>(p_r, m, Wm_w, bm_w, p_mprev);
    // 13. m_ = m_prev @ Wm2^T + bm2
    gemm_small<512, false><<<dim3(8, 4), 256>>>(p_mprev, nullptr, Wm2, bm2, p_mm);
    // 14. gate, sa softmax, m_sa
    gate_sa_kernel<<<BATCH, 256>>>(out_cnew, Wc, bc, cs, Wsa, bsa, ms, p_gate, p_msa);
    // 15. tmp = m_sa @ Ws^T
    gemm_small<512, false><<<dim3(8, 4), 256>>>(p_msa, nullptr, Ws, nullptr, p_tmp);
    // 16. m_new = gate*m + (1-gate)*(m_ + tmp)
    final_kernel<<<(BATCH * DIM) / 256, 256>>>(m, p_mm, p_tmp, p_gate, out_mnew);
}

// round 9
// speedup vs baseline: 1.8621x; 1.1015x over previous
#include <cuda_runtime.h>
#include <cuda_bf16.h>
#include <cuda_fp16.h>
#include <math.h>
#include <stdint.h>

#define BATCH 256
#define DIM   512
#define LW    32
#define PIX   196
#define TT    8
#define MBIG  (BATCH*PIX)   // 50176

// ---------------- scratch (static __device__ — allocation-guard safe) ----------------
__device__ __half g_kT [MBIG*512];     // plain fp16, stride 512
__device__ __half g_I2 [MBIG*512];
__device__ __half g_J2 [MBIG*512];
__device__ float g_ra  [MBIG*DIM];
__device__ __half g_Wk2 [DIM*DIM];
__device__ __half g_WI2 [DIM*2*DIM];
__device__ __half g_Wra2[DIM*DIM];
__device__ float g_cq  [BATCH*DIM];
__device__ float g_mI  [BATCH*DIM];
__device__ float g_r   [BATCH*DIM];
__device__ float g_mprev[BATCH*DIM];
__device__ float g_mm  [BATCH*DIM];
__device__ float g_msa [BATCH*DIM];
__device__ float g_tmp [BATCH*DIM];
__device__ float g_gate[BATCH];

// ================= helpers =================
__device__ __forceinline__ uint32_t smem_u32(const void* p) {
    uint32_t a;
    asm("{ .reg .u64 t; cvta.to.shared.u64 t, %1; cvt.u32.u64 %0, t; }" : "=r"(a) : "l"(p));
    return a;
}
__device__ __forceinline__ void cpasync16(uint32_t dst, const void* src) {
    asm volatile("cp.async.cg.shared.global [%0], [%1], 16;" :: "r"(dst), "l"(src) : "memory");
}
__device__ __forceinline__ void cp_commit() { asm volatile("cp.async.commit_group;" ::: "memory"); }
__device__ __forceinline__ void cp_wait1() { asm volatile("cp.async.wait_group 1;" ::: "memory"); }
__device__ __forceinline__ void cp_wait0() { asm volatile("cp.async.wait_group 0;" ::: "memory"); }

__device__ __forceinline__ void ldm_x4(uint32_t& r0, uint32_t& r1, uint32_t& r2, uint32_t& r3, uint32_t a) {
    asm volatile("ldmatrix.sync.aligned.m8n8.x4.shared.b16 {%0,%1,%2,%3}, [%4];"
                 : "=r"(r0), "=r"(r1), "=r"(r2), "=r"(r3) : "r"(a));
}
__device__ __forceinline__ void mma16816h(float* c, const uint32_t* a, const uint32_t* b) {
    asm volatile("mma.sync.aligned.m16n8k16.row.col.f32.f16.f16.f32 "
                 "{%0,%1,%2,%3}, {%4,%5,%6,%7}, {%8,%9}, {%0,%1,%2,%3};"
                 : "+f"(c[0]), "+f"(c[1]), "+f"(c[2]), "+f"(c[3])
                 : "r"(a[0]), "r"(a[1]), "r"(a[2]), "r"(a[3]), "r"(b[0]), "r"(b[1]));
}

// ================= HMMA pure-fp16 GEMM v4 =================
// 64-K stages: A 128x128B + B 128x128B = 32KB/stage, 3-stage ring (96KB), 2 CTAs/SM.
// 8-way chunk swizzle (chunk ^ (row & 7)) on 128B rows — ldmatrix conflict-free.
// EPI 0: v = (acc + bias[n]) * scale[m/PIX, n] -> fp16 into O[row][512]
// EPI 1: v = acc + bias[n] -> fp32 Of[m][n]
#define MG_STAGE 32768
#define MG_SMEM  (3*MG_STAGE)

template<int K, bool CONCAT, int EPI>
__global__ void __launch_bounds__(256, 2) mma_gemm(
    const __half* __restrict__ A0, const __half* __restrict__ A1,
    const __half* __restrict__ W,
    const float* __restrict__ bias, const float* __restrict__ scale,
    __half* __restrict__ O, float* __restrict__ Of)
{
    constexpr int KIT = K / 64;
    extern __shared__ __align__(128) char dsm[];
    const uint32_t smb = smem_u32(dsm);

    const int tid = threadIdx.x, lane = tid & 31, wid = tid >> 5;
    const int bm = blockIdx.y * 128, bn = blockIdx.x * 128;
    const int wm = (wid >> 2) * 64, wn = (wid & 3) * 32;

    float acc[4][4][4];
    #pragma unroll
    for (int i = 0; i < 4; i++)
        #pragma unroll
        for (int j = 0; j < 4; j++)
            #pragma unroll
            for (int v = 0; v < 4; v++) acc[i][j][v] = 0.f;

    auto load_stage = [&](int it, int stage) {
        uint32_t sb = smb + (uint32_t)stage * MG_STAGE;
        int k0 = it * 64;
        const __half* Asrc = A0;
        int ac = k0;
        if (CONCAT && k0 >= 512) { Asrc = A1; ac = k0 - 512; }
        #pragma unroll
        for (int j = 0; j < 4; j++) {
            int f = tid + j * 256;                 // 0..1023
            int row = f >> 3, cc = f & 7;
            uint32_t d = sb + row * 128 + (uint32_t)((cc ^ (row & 7)) * 16);
            cpasync16(d, Asrc + (size_t)(bm + row) * 512 + ac + cc * 8);          // A
            cpasync16(d + 16384u, W + (size_t)(bn + row) * K + k0 + cc * 8);      // W
        }
    };

    load_stage(0, 0); cp_commit();
    if (KIT > 1) { load_stage(1, 1); cp_commit(); }

    for (int it = 0; it < KIT; ++it) {
        if (it + 1 < KIT) cp_wait1(); else cp_wait0();
        __syncthreads();
        if (it + 2 < KIT) { load_stage(it + 2, (it + 2) % 3); cp_commit(); }

        const uint32_t sb = smb + (uint32_t)(it % 3) * MG_STAGE;
        const uint32_t sA = sb, sB = sb + 16384u;
        #pragma unroll
        for (int kp = 0; kp < 4; kp++) {
            uint32_t bf[2][4];
            #pragma unroll
            for (int pr = 0; pr < 2; pr++) {
                int nrow = wn + pr * 16 + ((lane >> 4) << 3) + (lane & 7);
                int chunk = (kp * 2 + ((lane >> 3) & 1)) ^ (nrow & 7);
                ldm_x4(bf[pr][0], bf[pr][1], bf[pr][2], bf[pr][3], sB + nrow * 128 + chunk * 16);
            }
            #pragma unroll
            for (int mi = 0; mi < 4; mi++) {
                uint32_t ah[4];
                int row = wm + mi * 16 + (lane & 15);
                int chunk = (kp * 2 + (lane >> 4)) ^ (row & 7);
                ldm_x4(ah[0], ah[1], ah[2], ah[3], sA + row * 128 + chunk * 16);
                #pragma unroll
                for (int ni = 0; ni < 4; ni++)
                    mma16816h(acc[mi][ni], ah, &bf[ni >> 1][(ni & 1) * 2]);
            }
        }
    }

    // ---------------- epilogue ----------------
    #pragma unroll
    for (int ni = 0; ni < 4; ni++) {
        const int n0 = bn + wn + ni * 8 + 2 * (lane & 3);
        const float b0 = bias[n0], b1 = bias[n0 + 1];
        #pragma unroll
        for (int mi = 0; mi < 4; mi++) {
            const int r0 = bm + wm + mi * 16 + (lane >> 2);
            const int r1 = r0 + 8;
            float* c = acc[mi][ni];
            if (EPI == 0) {
                const float* s0 = scale + (size_t)(r0 / PIX) * DIM;
                const float* s1 = scale + (size_t)(r1 / PIX) * DIM;
                float v00 = (c[0] + b0) * s0[n0], v01 = (c[1] + b1) * s0[n0 + 1];
                float v10 = (c[2] + b0) * s1[n0], v11 = (c[3] + b1) * s1[n0 + 1];
                __half2 h0 = __floats2half2_rn(v00, v01);
                __half2 h1 = __floats2half2_rn(v10, v11);
                *reinterpret_cast<__half2*>(O + (size_t)r0 * 512 + n0) = h0;
                *reinterpret_cast<__half2*>(O + (size_t)r1 * 512 + n0) = h1;
            } else {
                float2 v0 = make_float2(c[0] + b0, c[1] + b1);
                float2 v1 = make_float2(c[2] + b0, c[3] + b1);
                *reinterpret_cast<float2*>(Of + (size_t)r0 * DIM + n0) = v0;
                *reinterpret_cast<float2*>(Of + (size_t)r1 * DIM + n0) = v1;
            }
        }
    }
}

// ================= small fp32 GEMM: register-prefetch double-buffered =================
template<int K, bool CONCAT>
__global__ void __launch_bounds__(256) gemm_small(
    const float* __restrict__ A0, const float* __restrict__ A1,
    const float* __restrict__ W, const float* __restrict__ bias,
    float* __restrict__ C)
{
    constexpr int BM = 64, BN = 64, BK = 32;
    constexpr int NIT = K / BK;
    constexpr int halfK = K / 2;
    __shared__ __align__(16) float As[2][BK][BM];
    __shared__ __align__(16) float Bs[2][BK][BN];

    const int tid = threadIdx.x;
    const int bm = blockIdx.y * BM, bn = blockIdx.x * BN;
    const int tx = tid & 15, ty = tid >> 4;

    float4 pa[2], pb[2];
    auto gload = [&](int it) {
        int k0 = it * BK;
        #pragma unroll
        for (int j = 0; j < 2; j++) {
            int f = tid + j * 256;
            int r = f >> 3, c4 = (f & 7) * 4;
            int gk = k0 + c4;
            const float* srcA;
            if (CONCAT) {
                srcA = (gk < halfK) ? (A0 + (size_t)(bm + r) * halfK + gk)
                                    : (A1 + (size_t)(bm + r) * halfK + (gk - halfK));
            } else {
                srcA = A0 + (size_t)(bm + r) * K + gk;
            }
            pa[j] = *reinterpret_cast<const float4*>(srcA);
            pb[j] = *reinterpret_cast<const float4*>(W + (size_t)(bn + r) * K + gk);
        }
    };
    auto sstore = [&](int buf) {
        #pragma unroll
        for (int j = 0; j < 2; j++) {
            int f = tid + j * 256;
            int r = f >> 3, c4 = (f & 7) * 4;
            As[buf][c4 + 0][r] = pa[j].x; As[buf][c4 + 1][r] = pa[j].y;
            As[buf][c4 + 2][r] = pa[j].z; As[buf][c4 + 3][r] = pa[j].w;
            Bs[buf][c4 + 0][r] = pb[j].x; Bs[buf][c4 + 1][r] = pb[j].y;
            Bs[buf][c4 + 2][r] = pb[j].z; Bs[buf][c4 + 3][r] = pb[j].w;
        }
    };

    float acc[4][4];
    #pragma unroll
    for (int i = 0; i < 4; i++)
        #pragma unroll
        for (int j = 0; j < 4; j++) acc[i][j] = 0.f;

    gload(0); sstore(0); __syncthreads();
    for (int it = 0; it < NIT; ++it) {
        if (it + 1 < NIT) gload(it + 1);
        const int buf = it & 1;
        #pragma unroll
        for (int kk = 0; kk < BK; kk++) {
            float4 a = *reinterpret_cast<const float4*>(&As[buf][kk][ty * 4]);
            float4 b = *reinterpret_cast<const float4*>(&Bs[buf][kk][tx * 4]);
            acc[0][0] = fmaf(a.x, b.x, acc[0][0]); acc[0][1] = fmaf(a.x, b.y, acc[0][1]);
            acc[0][2] = fmaf(a.x, b.z, acc[0][2]); acc[0][3] = fmaf(a.x, b.w, acc[0][3]);
            acc[1][0] = fmaf(a.y, b.x, acc[1][0]); acc[1][1] = fmaf(a.y, b.y, acc[1][1]);
            acc[1][2] = fmaf(a.y, b.z, acc[1][2]); acc[1][3] = fmaf(a.y, b.w, acc[1][3]);
            acc[2][0] = fmaf(a.z, b.x, acc[2][0]); acc[2][1] = fmaf(a.z, b.y, acc[2][1]);
            acc[2][2] = fmaf(a.z, b.z, acc[2][2]); acc[2][3] = fmaf(a.z, b.w, acc[2][3]);
            acc[3][0] = fmaf(a.w, b.x, acc[3][0]); acc[3][1] = fmaf(a.w, b.y, acc[3][1]);
            acc[3][2] = fmaf(a.w, b.z, acc[3][2]); acc[3][3] = fmaf(a.w, b.w, acc[3][3]);
        }
        __syncthreads();
        if (it + 1 < NIT) { sstore((it + 1) & 1); __syncthreads(); }
    }

    float bb[4];
    #pragma unroll
    for (int j = 0; j < 4; j++) bb[j] = bias ? bias[bn + tx * 4 + j] : 0.f;
    #pragma unroll
    for (int i = 0; i < 4; i++) {
        int gm = bm + ty * 4 + i;
        float4 v = make_float4(acc[i][0] + bb[0], acc[i][1] + bb[1],
                               acc[i][2] + bb[2], acc[i][3] + bb[3]);
        *reinterpret_cast<float4*>(&C[(size_t)gm * DIM + bn + tx * 4]) = v;
    }
}

// ================= conversions =================
__global__ void halve_w_kernel(const float* __restrict__ w, __half* __restrict__ o, int n)
{
    int i = blockIdx.x * 256 + threadIdx.x;
    if (i < n) o[i] = __float2half_rn(w[i]);
}

// k [B,D,P] -> kT [B*P][512] fp16
__global__ void transpose_half_k(const float* __restrict__ k, __half* __restrict__ kT)
{
    __shared__ float tile[32][33];
    int b  = blockIdx.z;
    int p0 = blockIdx.x * 32;
    int c0 = blockIdx.y * 32;
    int tx = threadIdx.x, ty = threadIdx.y;
    #pragma unroll
    for (int j = 0; j < 32; j += 8) {
        int c = c0 + ty + j, p = p0 + tx;
        if (p < PIX) tile[ty + j][tx] = k[((size_t)b * DIM + c) * PIX + p];
    }
    __syncthreads();
    #pragma unroll
    for (int j = 0; j < 32; j += 8) {
        int p = p0 + ty + j, c = c0 + tx;
        if (p < PIX)
            kT[((size_t)b * PIX + p) * 512 + c] = __float2half_rn(tile[tx][ty + j]);
    }
}

// ---------------- reduction helpers ----------------
template<int NW>
__device__ __forceinline__ float blkSum(float v, float* red) {
    #pragma unroll
    for (int o = 16; o > 0; o >>= 1) v += __shfl_xor_sync(0xffffffffu, v, o);
    __syncthreads();
    if ((threadIdx.x & 31) == 0) red[threadIdx.x >> 5] = v;
    __syncthreads();
    float s = 0.f;
    #pragma unroll
    for (int i = 0; i < NW; i++) s += red[i];
    return s;
}

// ---------------- ControlUnit tail v2: warp-per-l ----------------
__global__ void __launch_bounds__(512) control_kernel(
    const float* __restrict__ cq, const float* __restrict__ cw,
    const int* __restrict__ mask, const float* __restrict__ Wca,
    const float* __restrict__ bca,
    float* __restrict__ cv_out, float* __restrict__ cnew)
{
    int b = blockIdx.x, tid = threadIdx.x;   // 512 threads
    int w = tid >> 5, lane = tid & 31;
    __shared__ float u[DIM];
    __shared__ float s[LW];
    const float* cwb = cw + (size_t)b * LW * DIM;
    u[tid] = cq[(size_t)b * DIM + tid] * Wca[tid];
    __syncthreads();
    #pragma unroll
    for (int li = 0; li < 2; li++) {
        int l = w * 2 + li;
        const float* row = cwb + (size_t)l * DIM;
        float p = 0.f;
        #pragma unroll
        for (int j = 0; j < 16; j++) p = fmaf(u[lane + j * 32], row[lane + j * 32], p);
        #pragma unroll
        for (int o = 16; o > 0; o >>= 1) p += __shfl_xor_sync(0xffffffffu, p, o);
        if (lane == 0) s[l] = (mask[b * LW + l] > 0) ? (p + bca[0]) : -INFINITY;
    }
    __syncthreads();
    if (tid == 0) {
        float mx = -INFINITY;
        for (int l = 0; l < LW; l++) mx = fmaxf(mx, s[l]);
        float sm = 0.f;
        for (int l = 0; l < LW; l++) { float e = __expf(s[l] - mx); s[l] = e; sm += e; }
        float inv = 1.f / sm;
        for (int l = 0; l < LW; l++) { s[l] *= inv; cv_out[b * LW + l] = s[l]; }
    }
    __syncthreads();
    float a = 0.f;
    #pragma unroll
    for (int l = 0; l < LW; l++) a = fmaf(s[l], cwb[(size_t)l * DIM + tid], a);
    cnew[(size_t)b * DIM + tid] = a;
}

// ---------------- softmax over channels: warp-per-pixel, 28-pixel write staging ----------
#define SMRV_TILE_STRIDE 517
#define SMRV_SMEM (28*SMRV_TILE_STRIDE*4)

__global__ void __launch_bounds__(512) softmax_rv_kernel(
    const float* __restrict__ ra, const __half* __restrict__ kT,
    float* __restrict__ rv_out, float* __restrict__ r_out)
{
    extern __shared__ float tile[];          // [28][517]
    __shared__ float rsum[DIM];
    const int b = blockIdx.x, tid = threadIdx.x;
    const int w = tid >> 5, lane = tid & 31;
    const float* rab = ra + (size_t)b * PIX * DIM;
    const __half* kb = kT + (size_t)b * PIX * 512;
    float* rvb = rv_out + (size_t)b * DIM * PIX;

    if (tid < DIM) rsum[tid] = 0.f;
    float racc[16];
    #pragma unroll
    for (int j = 0; j < 16; j++) racc[j] = 0.f;
    __syncthreads();

    for (int pp = 0; pp < 7; pp++) {
        if (w < 14) {
            #pragma unroll
            for (int half = 0; half < 2; half++) {
                const int i = half * 14 + w;
                const int p = pp * 28 + i;
                float x[16];
                #pragma unroll
                for (int q = 0; q < 4; q++) {
                    float4 v = *reinterpret_cast<const float4*>(rab + (size_t)p * DIM + q * 128 + lane * 4);
                    x[q * 4 + 0] = v.x; x[q * 4 + 1] = v.y; x[q * 4 + 2] = v.z; x[q * 4 + 3] = v.w;
                }
                float mx = x[0];
                #pragma unroll
                for (int j = 1; j < 16; j++) mx = fmaxf(mx, x[j]);
                #pragma unroll
                for (int o = 16; o > 0; o >>= 1) mx = fmaxf(mx, __shfl_xor_sync(0xffffffffu, mx, o));
                float sm = 0.f;
                #pragma unroll
                for (int j = 0; j < 16; j++) { x[j] = __expf(x[j] - mx); sm += x[j]; }
                #pragma unroll
                for (int o = 16; o > 0; o >>= 1) sm += __shfl_xor_sync(0xffffffffu, sm, o);
                const float inv = 1.f / sm;
                #pragma unroll
                for (int q = 0; q < 4; q++) {
                    float rv0 = x[q * 4 + 0] * inv, rv1 = x[q * 4 + 1] * inv;
                    float rv2 = x[q * 4 + 2] * inv, rv3 = x[q * 4 + 3] * inv;
                    float* tr = &tile[i * SMRV_TILE_STRIDE + q * 128 + lane * 4];
                    tr[0] = rv0; tr[1] = rv1; tr[2] = rv2; tr[3] = rv3;
                    const size_t kidx = (size_t)p * 512 + q * 128 + lane * 4;
                    __half2 kh0 = *reinterpret_cast<const __half2*>(kb + kidx);
                    __half2 kh1 = *reinterpret_cast<const __half2*>(kb + kidx + 2);
                    racc[q * 4 + 0] = fmaf(rv0, __half2float(kh0.x), racc[q * 4 + 0]);
                    racc[q * 4 + 1] = fmaf(rv1, __half2float(kh0.y), racc[q * 4 + 1]);
                    racc[q * 4 + 2] = fmaf(rv2, __half2float(kh1.x), racc[q * 4 + 2]);
                    racc[q * 4 + 3] = fmaf(rv3, __half2float(kh1.y), racc[q * 4 + 3]);
                }
            }
        }
        __syncthreads();
        #pragma unroll 1
        for (int cc = 0; cc < 32; cc++) {
            int c = w * 32 + cc;
            if (lane < 28) rvb[(size_t)c * PIX + pp * 28 + lane] = tile[lane * SMRV_TILE_STRIDE + c];
        }
        __syncthreads();
    }

    #pragma unroll
    for (int q = 0; q < 4; q++)
        #pragma unroll
        for (int j = 0; j < 4; j++)
            atomicAdd(&rsum[q * 128 + lane * 4 + j], racc[q * 4 + j]);
    __syncthreads();
    if (tid < DIM) r_out[(size_t)b * DIM + tid] = rsum[tid];
}

// ---------------- gate, sa softmax over T, m_sa ----------------
__global__ void gate_sa_kernel(const float* __restrict__ cnew, const float* __restrict__ Wc,
                               const float* __restrict__ bc,   const float* __restrict__ cs,
                               const float* __restrict__ Wsa,  const float* __restrict__ bsa,
                               const float* __restrict__ ms,
                               float* __restrict__ gate_out, float* __restrict__ msa_out)
{
    int b = blockIdx.x, tid = threadIdx.x;   // 256 threads
    __shared__ float red[8];
    __shared__ float sa[TT];
    __shared__ float gsh;
    float p = 0.f;
    for (int d = tid; d < DIM; d += 256) p += cnew[(size_t)b * DIM + d] * Wc[d];
    float tot = blkSum<8>(p, red);
    if (tid == 0) gsh = 1.f / (1.f + __expf(-(tot + bc[0])));
    __syncthreads();
    float gate = gsh;
    for (int t8 = 0; t8 < TT; t8++) {
        float qv = 0.f;
        const float* csrow = cs + ((size_t)t8 * BATCH + b) * DIM;
        for (int d = tid; d < DIM; d += 256) qv += csrow[d] * Wsa[d];
        float qt = blkSum<8>(qv, red);
        if (tid == 0) sa[t8] = gate * qt + bsa[0];
    }
    __syncthreads();
    if (tid == 0) {
        float mx = -INFINITY;
        for (int i = 0; i < TT; i++) mx = fmaxf(mx, sa[i]);
        float sm = 0.f;
        for (int i = 0; i < TT; i++) { float e = __expf(sa[i] - mx); sa[i] = e; sm += e; }
        float inv = 1.f / sm;
        for (int i = 0; i < TT; i++) sa[i] *= inv;
    }
    __syncthreads();
    for (int d = tid; d < DIM; d += 256) {
        float a = 0.f;
        #pragma unroll
        for (int i = 0; i < TT; i++)
            a = fmaf(sa[i], ms[((size_t)i * BATCH + b) * DIM + d], a);
        msa_out[(size_t)b * DIM + d] = a;
    }
    if (tid == 0) gate_out[b] = gate;
}

// ---------------- final ----------------
__global__ void final_kernel(const float* __restrict__ m, const float* __restrict__ mm,
                             const float* __restrict__ tmp, const float* __restrict__ gate,
                             float* __restrict__ mnew)
{
    int i = blockIdx.x * 256 + threadIdx.x;
    int b = i >> 9;
    float g = gate[b];
    mnew[i] = g * m[i] + (1.f - g) * (mm[i] + tmp[i]);
}

// ---------------- launch ----------------
extern "C" void kernel_launch(void* const* d_in, const int* in_sizes, int n_in,
                              void* d_out, int out_size)
{
    const float* c    = (const float*)d_in[0];
    const float* m    = (const float*)d_in[1];
    const float* k    = (const float*)d_in[2];
    const float* q    = (const float*)d_in[3];
    const float* cw   = (const float*)d_in[4];
    const int*   mask = (const int*)  d_in[5];
    const float* cs   = (const float*)d_in[6];
    const float* ms   = (const float*)d_in[7];
    const float* Wcq  = (const float*)d_in[8];
    const float* bcq  = (const float*)d_in[9];
    const float* Wca  = (const float*)d_in[10];
    const float* bca  = (const float*)d_in[11];
    const float* Wm_r = (const float*)d_in[12];
    const float* bm_r = (const float*)d_in[13];
    const float* Wk   = (const float*)d_in[14];
    const float* bk   = (const float*)d_in[15];
    const float* WI   = (const float*)d_in[16];
    const float* bI   = (const float*)d_in[17];
    const float* Wra  = (const float*)d_in[18];
    const float* bra  = (const float*)d_in[19];
    const float* Wm_w = (const float*)d_in[20];
    const float* bm_w = (const float*)d_in[21];
    const float* Wsa  = (const float*)d_in[22];
    const float* bsa  = (const float*)d_in[23];
    const float* Wm2  = (const float*)d_in[24];
    const float* bm2  = (const float*)d_in[25];
    const float* Wc   = (const float*)d_in[26];
    const float* bc   = (const float*)d_in[27];
    const float* Ws   = (const float*)d_in[28];

    float* out      = (float*)d_out;
    float* out_cnew = out;                       // [B,D]
    float* out_mnew = out + 131072;              // [B,D]
    float* out_cv   = out + 262144;              // [B,L]
    float* out_rv   = out + 270336;              // [B,D,H,W]

    __half *p_kT, *p_I2, *p_J2, *p_Wk2, *p_WI2, *p_Wra2;
    float *p_ra, *p_cq, *p_mI, *p_r, *p_mprev, *p_mm, *p_msa, *p_tmp, *p_gate;
    cudaGetSymbolAddress((void**)&p_kT,   g_kT);
    cudaGetSymbolAddress((void**)&p_I2,   g_I2);
    cudaGetSymbolAddress((void**)&p_J2,   g_J2);
    cudaGetSymbolAddress((void**)&p_Wk2,  g_Wk2);
    cudaGetSymbolAddress((void**)&p_WI2,  g_WI2);
    cudaGetSymbolAddress((void**)&p_Wra2, g_Wra2);
    cudaGetSymbolAddress((void**)&p_ra,   g_ra);
    cudaGetSymbolAddress((void**)&p_cq,   g_cq);
    cudaGetSymbolAddress((void**)&p_mI,   g_mI);
    cudaGetSymbolAddress((void**)&p_r,    g_r);
    cudaGetSymbolAddress((void**)&p_mprev,g_mprev);
    cudaGetSymbolAddress((void**)&p_mm,   g_mm);
    cudaGetSymbolAddress((void**)&p_msa,  g_msa);
    cudaGetSymbolAddress((void**)&p_tmp,  g_tmp);
    cudaGetSymbolAddress((void**)&p_gate, g_gate);

    cudaFuncSetAttribute((const void*)mma_gemm<512,  false, 0>, cudaFuncAttributeMaxDynamicSharedMemorySize, MG_SMEM);
    cudaFuncSetAttribute((const void*)mma_gemm<1024, true,  0>, cudaFuncAttributeMaxDynamicSharedMemorySize, MG_SMEM);
    cudaFuncSetAttribute((const void*)mma_gemm<512,  false, 1>, cudaFuncAttributeMaxDynamicSharedMemorySize, MG_SMEM);
    cudaFuncSetAttribute(softmax_rv_kernel, cudaFuncAttributeMaxDynamicSharedMemorySize, SMRV_SMEM);

    // ---- ordered so my 4th launch = mma_gemm I (ncu -s 5 -c 1 visibility) ----
    // 1. Wk -> fp16
    halve_w_kernel<<<(DIM*DIM + 255)/256, 256>>>(Wk, p_Wk2, DIM*DIM);
    // 2. k -> kT fp16
    transpose_half_k<<<dim3(7, 16, BATCH), dim3(32, 8)>>>(k, p_kT);
    // 3. mI = m @ Wm_r^T + bm_r
    gemm_small<512, false><<<dim3(8, 4), 256>>>(m, nullptr, Wm_r, bm_r, p_mI);
    // 4. I = mI ⊙ (kT @ Wk^T + bk) -> fp16           [HMMA]  << profiled
    mma_gemm<512, false, 0><<<dim3(4, 392), 256, MG_SMEM>>>(
        p_kT, nullptr, p_Wk2, bk, p_mI, p_I2, nullptr);
    // 5. WI -> fp16
    halve_w_kernel<<<(DIM*2*DIM + 255)/256, 256>>>(WI, p_WI2, DIM*2*DIM);
    // 6. cq = [c|q] @ Wcq^T + bcq
    gemm_small<1024, true><<<dim3(8, 4), 256>>>(c, q, Wcq, bcq, p_cq);
    // 7. ControlUnit tail -> cv, c_new
    control_kernel<<<BATCH, 512>>>(p_cq, cw, mask, Wca, bca, out_cv, out_cnew);
    // 8. J = c_new ⊙ ([I|kT] @ WI^T + bI) -> fp16    [HMMA]
    mma_gemm<1024, true, 0><<<dim3(4, 392), 256, MG_SMEM>>>(
        p_I2, p_kT, p_WI2, bI, out_cnew, p_J2, nullptr);
    // 9. Wra -> fp16
    halve_w_kernel<<<(DIM*DIM + 255)/256, 256>>>(Wra, p_Wra2, DIM*DIM);
    // 10. ra = J @ Wra^T + bra -> fp32               [HMMA]
    mma_gemm<512, false, 1><<<dim3(4, 392), 256, MG_SMEM>>>(
        p_J2, nullptr, p_Wra2, bra, nullptr, nullptr, p_ra);
    // 11. rv = softmax_c(ra) -> d_out (transposed), r = sum_p rv*k
    softmax_rv_kernel<<<BATCH, 512, SMRV_SMEM>>>(p_ra, p_kT, out_rv, p_r);
    // 12. m_prev = [r|m] @ Wm_w^T + bm_w
    gemm_small<1024, true><<<dim3(8, 4), 256>>>(p_r, m, Wm_w, bm_w, p_mprev);
    // 13. m_ = m_prev @ Wm2^T + bm2
    gemm_small<512, false><<<dim3(8, 4), 256>>>(p_mprev, nullptr, Wm2, bm2, p_mm);
    // 14. gate, sa softmax, m_sa
    gate_sa_kernel<<<BATCH, 256>>>(out_cnew, Wc, bc, cs, Wsa, bsa, ms, p_gate, p_msa);
    // 15. tmp = m_sa @ Ws^T
    gemm_small<512, false><<<dim3(8, 4), 256>>>(p_msa, nullptr, Ws, nullptr, p_tmp);
    // 16. m_new = gate*m + (1-gate)*(m_ + tmp)
    final_kernel<<<(BATCH * DIM) / 256, 256>>>(m, p_mm, p_tmp, p_gate, out_mnew);
}

// round 10
// speedup vs baseline: 1.9489x; 1.0466x over previous
#include <cuda_runtime.h>
#include <cuda_bf16.h>
#include <cuda_fp16.h>
#include <math.h>
#include <stdint.h>

#define BATCH 256
#define DIM   512
#define LW    32
#define PIX   196
#define TT    8
#define MBIG  (BATCH*PIX)   // 50176

// ---------------- scratch (static __device__ — allocation-guard safe) ----------------
__device__ __half g_kT [MBIG*512];     // plain fp16, stride 512
__device__ __half g_I2 [MBIG*512];
__device__ __half g_J2 [MBIG*512];
__device__ __half g_ra [MBIG*512];     // fp16 now
__device__ __half g_Wk2 [DIM*DIM];
__device__ __half g_WI2 [DIM*2*DIM];
__device__ __half g_Wra2[DIM*DIM];
__device__ float g_cq  [BATCH*DIM];
__device__ float g_mI  [BATCH*DIM];
__device__ float g_r   [BATCH*DIM];
__device__ float g_mprev[BATCH*DIM];
__device__ float g_mm  [BATCH*DIM];
__device__ float g_msa [BATCH*DIM];
__device__ float g_tmp [BATCH*DIM];
__device__ float g_gate[BATCH];

// ================= helpers =================
__device__ __forceinline__ uint32_t smem_u32(const void* p) {
    uint32_t a;
    asm("{ .reg .u64 t; cvta.to.shared.u64 t, %1; cvt.u32.u64 %0, t; }" : "=r"(a) : "l"(p));
    return a;
}
__device__ __forceinline__ void cpasync16(uint32_t dst, const void* src) {
    asm volatile("cp.async.cg.shared.global [%0], [%1], 16;" :: "r"(dst), "l"(src) : "memory");
}
__device__ __forceinline__ void cp_commit() { asm volatile("cp.async.commit_group;" ::: "memory"); }
__device__ __forceinline__ void cp_wait1() { asm volatile("cp.async.wait_group 1;" ::: "memory"); }
__device__ __forceinline__ void cp_wait0() { asm volatile("cp.async.wait_group 0;" ::: "memory"); }

__device__ __forceinline__ void ldm_x4(uint32_t& r0, uint32_t& r1, uint32_t& r2, uint32_t& r3, uint32_t a) {
    asm volatile("ldmatrix.sync.aligned.m8n8.x4.shared.b16 {%0,%1,%2,%3}, [%4];"
                 : "=r"(r0), "=r"(r1), "=r"(r2), "=r"(r3) : "r"(a));
}
__device__ __forceinline__ void mma16816h(float* c, const uint32_t* a, const uint32_t* b) {
    asm volatile("mma.sync.aligned.m16n8k16.row.col.f32.f16.f16.f32 "
                 "{%0,%1,%2,%3}, {%4,%5,%6,%7}, {%8,%9}, {%0,%1,%2,%3};"
                 : "+f"(c[0]), "+f"(c[1]), "+f"(c[2]), "+f"(c[3])
                 : "r"(a[0]), "r"(a[1]), "r"(a[2]), "r"(a[3]), "r"(b[0]), "r"(b[1]));
}

// ================= HMMA pure-fp16 GEMM =================
// 64-K stages: A 128x128B + B 128x128B = 32KB/stage, 3-stage ring (96KB), 2 CTAs/SM.
// EPI 0: v = (acc + bias[n]) * scale[m/PIX, n] -> fp16 into O[row][512]
// EPI 1: v = acc + bias[n] -> fp16 into O[row][512]
#define MG_STAGE 32768
#define MG_SMEM  (3*MG_STAGE)

template<int K, bool CONCAT, int EPI>
__global__ void __launch_bounds__(256, 2) mma_gemm(
    const __half* __restrict__ A0, const __half* __restrict__ A1,
    const __half* __restrict__ W,
    const float* __restrict__ bias, const float* __restrict__ scale,
    __half* __restrict__ O)
{
    constexpr int KIT = K / 64;
    extern __shared__ __align__(128) char dsm[];
    const uint32_t smb = smem_u32(dsm);

    const int tid = threadIdx.x, lane = tid & 31, wid = tid >> 5;
    const int bm = blockIdx.y * 128, bn = blockIdx.x * 128;
    const int wm = (wid >> 2) * 64, wn = (wid & 3) * 32;

    float acc[4][4][4];
    #pragma unroll
    for (int i = 0; i < 4; i++)
        #pragma unroll
        for (int j = 0; j < 4; j++)
            #pragma unroll
            for (int v = 0; v < 4; v++) acc[i][j][v] = 0.f;

    auto load_stage = [&](int it, int stage) {
        uint32_t sb = smb + (uint32_t)stage * MG_STAGE;
        int k0 = it * 64;
        const __half* Asrc = A0;
        int ac = k0;
        if (CONCAT && k0 >= 512) { Asrc = A1; ac = k0 - 512; }
        #pragma unroll
        for (int j = 0; j < 4; j++) {
            int f = tid + j * 256;                 // 0..1023
            int row = f >> 3, cc = f & 7;
            uint32_t d = sb + row * 128 + (uint32_t)((cc ^ (row & 7)) * 16);
            cpasync16(d, Asrc + (size_t)(bm + row) * 512 + ac + cc * 8);          // A
            cpasync16(d + 16384u, W + (size_t)(bn + row) * K + k0 + cc * 8);      // W
        }
    };

    load_stage(0, 0); cp_commit();
    if (KIT > 1) { load_stage(1, 1); cp_commit(); }

    for (int it = 0; it < KIT; ++it) {
        if (it + 1 < KIT) cp_wait1(); else cp_wait0();
        __syncthreads();
        if (it + 2 < KIT) { load_stage(it + 2, (it + 2) % 3); cp_commit(); }

        const uint32_t sb = smb + (uint32_t)(it % 3) * MG_STAGE;
        const uint32_t sA = sb, sB = sb + 16384u;
        #pragma unroll
        for (int kp = 0; kp < 4; kp++) {
            uint32_t bf[2][4];
            #pragma unroll
            for (int pr = 0; pr < 2; pr++) {
                int nrow = wn + pr * 16 + ((lane >> 4) << 3) + (lane & 7);
                int chunk = (kp * 2 + ((lane >> 3) & 1)) ^ (nrow & 7);
                ldm_x4(bf[pr][0], bf[pr][1], bf[pr][2], bf[pr][3], sB + nrow * 128 + chunk * 16);
            }
            #pragma unroll
            for (int mi = 0; mi < 4; mi++) {
                uint32_t ah[4];
                int row = wm + mi * 16 + (lane & 15);
                int chunk = (kp * 2 + (lane >> 4)) ^ (row & 7);
                ldm_x4(ah[0], ah[1], ah[2], ah[3], sA + row * 128 + chunk * 16);
                #pragma unroll
                for (int ni = 0; ni < 4; ni++)
                    mma16816h(acc[mi][ni], ah, &bf[ni >> 1][(ni & 1) * 2]);
            }
        }
    }

    // ---------------- epilogue ----------------
    #pragma unroll
    for (int ni = 0; ni < 4; ni++) {
        const int n0 = bn + wn + ni * 8 + 2 * (lane & 3);
        const float b0 = bias[n0], b1 = bias[n0 + 1];
        #pragma unroll
        for (int mi = 0; mi < 4; mi++) {
            const int r0 = bm + wm + mi * 16 + (lane >> 2);
            const int r1 = r0 + 8;
            float* c = acc[mi][ni];
            if (EPI == 0) {
                const float* s0 = scale + (size_t)(r0 / PIX) * DIM;
                const float* s1 = scale + (size_t)(r1 / PIX) * DIM;
                float v00 = (c[0] + b0) * s0[n0], v01 = (c[1] + b1) * s0[n0 + 1];
                float v10 = (c[2] + b0) * s1[n0], v11 = (c[3] + b1) * s1[n0 + 1];
                *reinterpret_cast<__half2*>(O + (size_t)r0 * 512 + n0) = __floats2half2_rn(v00, v01);
                *reinterpret_cast<__half2*>(O + (size_t)r1 * 512 + n0) = __floats2half2_rn(v10, v11);
            } else {
                *reinterpret_cast<__half2*>(O + (size_t)r0 * 512 + n0) = __floats2half2_rn(c[0] + b0, c[1] + b1);
                *reinterpret_cast<__half2*>(O + (size_t)r1 * 512 + n0) = __floats2half2_rn(c[2] + b0, c[3] + b1);
            }
        }
    }
}

// ================= small fp32 GEMM: register-prefetch, 1 sync/iter =================
template<int K, bool CONCAT>
__global__ void __launch_bounds__(256) gemm_small(
    const float* __restrict__ A0, const float* __restrict__ A1,
    const float* __restrict__ W, const float* __restrict__ bias,
    float* __restrict__ C)
{
    constexpr int BM = 64, BN = 64, BK = 32;
    constexpr int NIT = K / BK;
    constexpr int halfK = K / 2;
    __shared__ __align__(16) float As[2][BK][BM];
    __shared__ __align__(16) float Bs[2][BK][BN];

    const int tid = threadIdx.x;
    const int bm = blockIdx.y * BM, bn = blockIdx.x * BN;
    const int tx = tid & 15, ty = tid >> 4;

    float4 pa[2], pb[2];
    auto gload = [&](int it) {
        int k0 = it * BK;
        #pragma unroll
        for (int j = 0; j < 2; j++) {
            int f = tid + j * 256;
            int r = f >> 3, c4 = (f & 7) * 4;
            int gk = k0 + c4;
            const float* srcA;
            if (CONCAT) {
                srcA = (gk < halfK) ? (A0 + (size_t)(bm + r) * halfK + gk)
                                    : (A1 + (size_t)(bm + r) * halfK + (gk - halfK));
            } else {
                srcA = A0 + (size_t)(bm + r) * K + gk;
            }
            pa[j] = *reinterpret_cast<const float4*>(srcA);
            pb[j] = *reinterpret_cast<const float4*>(W + (size_t)(bn + r) * K + gk);
        }
    };
    auto sstore = [&](int buf) {
        #pragma unroll
        for (int j = 0; j < 2; j++) {
            int f = tid + j * 256;
            int r = f >> 3, c4 = (f & 7) * 4;
            As[buf][c4 + 0][r] = pa[j].x; As[buf][c4 + 1][r] = pa[j].y;
            As[buf][c4 + 2][r] = pa[j].z; As[buf][c4 + 3][r] = pa[j].w;
            Bs[buf][c4 + 0][r] = pb[j].x; Bs[buf][c4 + 1][r] = pb[j].y;
            Bs[buf][c4 + 2][r] = pb[j].z; Bs[buf][c4 + 3][r] = pb[j].w;
        }
    };

    float acc[4][4];
    #pragma unroll
    for (int i = 0; i < 4; i++)
        #pragma unroll
        for (int j = 0; j < 4; j++) acc[i][j] = 0.f;

    gload(0); sstore(0); __syncthreads();
    for (int it = 0; it < NIT; ++it) {
        if (it + 1 < NIT) gload(it + 1);
        const int buf = it & 1;
        #pragma unroll
        for (int kk = 0; kk < BK; kk++) {
            float4 a = *reinterpret_cast<const float4*>(&As[buf][kk][ty * 4]);
            float4 b = *reinterpret_cast<const float4*>(&Bs[buf][kk][tx * 4]);
            acc[0][0] = fmaf(a.x, b.x, acc[0][0]); acc[0][1] = fmaf(a.x, b.y, acc[0][1]);
            acc[0][2] = fmaf(a.x, b.z, acc[0][2]); acc[0][3] = fmaf(a.x, b.w, acc[0][3]);
            acc[1][0] = fmaf(a.y, b.x, acc[1][0]); acc[1][1] = fmaf(a.y, b.y, acc[1][1]);
            acc[1][2] = fmaf(a.y, b.z, acc[1][2]); acc[1][3] = fmaf(a.y, b.w, acc[1][3]);
            acc[2][0] = fmaf(a.z, b.x, acc[2][0]); acc[2][1] = fmaf(a.z, b.y, acc[2][1]);
            acc[2][2] = fmaf(a.z, b.z, acc[2][2]); acc[2][3] = fmaf(a.z, b.w, acc[2][3]);
            acc[3][0] = fmaf(a.w, b.x, acc[3][0]); acc[3][1] = fmaf(a.w, b.y, acc[3][1]);
            acc[3][2] = fmaf(a.w, b.z, acc[3][2]); acc[3][3] = fmaf(a.w, b.w, acc[3][3]);
        }
        // store NEXT tile into the idle buffer concurrently; single barrier
        if (it + 1 < NIT) sstore(buf ^ 1);
        __syncthreads();
    }

    float bb[4];
    #pragma unroll
    for (int j = 0; j < 4; j++) bb[j] = bias ? bias[bn + tx * 4 + j] : 0.f;
    #pragma unroll
    for (int i = 0; i < 4; i++) {
        int gm = bm + ty * 4 + i;
        float4 v = make_float4(acc[i][0] + bb[0], acc[i][1] + bb[1],
                               acc[i][2] + bb[2], acc[i][3] + bb[3]);
        *reinterpret_cast<float4*>(&C[(size_t)gm * DIM + bn + tx * 4]) = v;
    }
}

// ================= conversions =================
// batched fp32 -> fp16 of Wk (256K), WI (512K), Wra (256K): grid covers 1M elems
__global__ void halve_w3_kernel(const float* __restrict__ wk, const float* __restrict__ wi,
                                const float* __restrict__ wra,
                                __half* __restrict__ ok, __half* __restrict__ oi,
                                __half* __restrict__ ora)
{
    int i = blockIdx.x * 256 + threadIdx.x;     // 0 .. 1048575
    if (i < 262144) ok[i] = __float2half_rn(wk[i]);
    else if (i < 786432) { int j = i - 262144; oi[j] = __float2half_rn(wi[j]); }
    else { int j = i - 786432; ora[j] = __float2half_rn(wra[j]); }
}

// k [B,D,P] -> kT [B*P][512] fp16
__global__ void transpose_half_k(const float* __restrict__ k, __half* __restrict__ kT)
{
    __shared__ float tile[32][33];
    int b  = blockIdx.z;
    int p0 = blockIdx.x * 32;
    int c0 = blockIdx.y * 32;
    int tx = threadIdx.x, ty = threadIdx.y;
    #pragma unroll
    for (int j = 0; j < 32; j += 8) {
        int c = c0 + ty + j, p = p0 + tx;
        if (p < PIX) tile[ty + j][tx] = k[((size_t)b * DIM + c) * PIX + p];
    }
    __syncthreads();
    #pragma unroll
    for (int j = 0; j < 32; j += 8) {
        int p = p0 + ty + j, c = c0 + tx;
        if (p < PIX)
            kT[((size_t)b * PIX + p) * 512 + c] = __float2half_rn(tile[tx][ty + j]);
    }
}

// ---------------- reduction helpers ----------------
template<int NW>
__device__ __forceinline__ float blkSum(float v, float* red) {
    #pragma unroll
    for (int o = 16; o > 0; o >>= 1) v += __shfl_xor_sync(0xffffffffu, v, o);
    __syncthreads();
    if ((threadIdx.x & 31) == 0) red[threadIdx.x >> 5] = v;
    __syncthreads();
    float s = 0.f;
    #pragma unroll
    for (int i = 0; i < NW; i++) s += red[i];
    return s;
}

// ---------------- ControlUnit tail: warp-per-l ----------------
__global__ void __launch_bounds__(512) control_kernel(
    const float* __restrict__ cq, const float* __restrict__ cw,
    const int* __restrict__ mask, const float* __restrict__ Wca,
    const float* __restrict__ bca,
    float* __restrict__ cv_out, float* __restrict__ cnew)
{
    int b = blockIdx.x, tid = threadIdx.x;   // 512 threads
    int w = tid >> 5, lane = tid & 31;
    __shared__ float u[DIM];
    __shared__ float s[LW];
    const float* cwb = cw + (size_t)b * LW * DIM;
    u[tid] = cq[(size_t)b * DIM + tid] * Wca[tid];
    __syncthreads();
    #pragma unroll
    for (int li = 0; li < 2; li++) {
        int l = w * 2 + li;
        const float* row = cwb + (size_t)l * DIM;
        float p = 0.f;
        #pragma unroll
        for (int j = 0; j < 16; j++) p = fmaf(u[lane + j * 32], row[lane + j * 32], p);
        #pragma unroll
        for (int o = 16; o > 0; o >>= 1) p += __shfl_xor_sync(0xffffffffu, p, o);
        if (lane == 0) s[l] = (mask[b * LW + l] > 0) ? (p + bca[0]) : -INFINITY;
    }
    __syncthreads();
    if (tid == 0) {
        float mx = -INFINITY;
        for (int l = 0; l < LW; l++) mx = fmaxf(mx, s[l]);
        float sm = 0.f;
        for (int l = 0; l < LW; l++) { float e = __expf(s[l] - mx); s[l] = e; sm += e; }
        float inv = 1.f / sm;
        for (int l = 0; l < LW; l++) { s[l] *= inv; cv_out[b * LW + l] = s[l]; }
    }
    __syncthreads();
    float a = 0.f;
    #pragma unroll
    for (int l = 0; l < LW; l++) a = fmaf(s[l], cwb[(size_t)l * DIM + tid], a);
    cnew[(size_t)b * DIM + tid] = a;
}

// ---------------- softmax over channels: warp-per-pixel (fp16 ra), 28-pixel staging ----------
#define SMRV_TILE_STRIDE 517
#define SMRV_SMEM (28*SMRV_TILE_STRIDE*4)

__global__ void __launch_bounds__(512) softmax_rv_kernel(
    const __half* __restrict__ ra, const __half* __restrict__ kT,
    float* __restrict__ rv_out, float* __restrict__ r_out)
{
    extern __shared__ float tile[];          // [28][517]
    __shared__ float rsum[DIM];
    const int b = blockIdx.x, tid = threadIdx.x;
    const int w = tid >> 5, lane = tid & 31;
    const __half* rab = ra + (size_t)b * PIX * 512;
    const __half* kb = kT + (size_t)b * PIX * 512;
    float* rvb = rv_out + (size_t)b * DIM * PIX;

    if (tid < DIM) rsum[tid] = 0.f;
    float racc[16];
    #pragma unroll
    for (int j = 0; j < 16; j++) racc[j] = 0.f;
    __syncthreads();

    for (int pp = 0; pp < 7; pp++) {
        if (w < 14) {
            #pragma unroll
            for (int half = 0; half < 2; half++) {
                const int i = half * 14 + w;
                const int p = pp * 28 + i;
                float x[16];
                #pragma unroll
                for (int q = 0; q < 4; q++) {
                    const size_t ridx = (size_t)p * 512 + q * 128 + lane * 4;
                    __half2 r0 = *reinterpret_cast<const __half2*>(rab + ridx);
                    __half2 r1 = *reinterpret_cast<const __half2*>(rab + ridx + 2);
                    x[q * 4 + 0] = __half2float(r0.x); x[q * 4 + 1] = __half2float(r0.y);
                    x[q * 4 + 2] = __half2float(r1.x); x[q * 4 + 3] = __half2float(r1.y);
                }
                float mx = x[0];
                #pragma unroll
                for (int j = 1; j < 16; j++) mx = fmaxf(mx, x[j]);
                #pragma unroll
                for (int o = 16; o > 0; o >>= 1) mx = fmaxf(mx, __shfl_xor_sync(0xffffffffu, mx, o));
                float sm = 0.f;
                #pragma unroll
                for (int j = 0; j < 16; j++) { x[j] = __expf(x[j] - mx); sm += x[j]; }
                #pragma unroll
                for (int o = 16; o > 0; o >>= 1) sm += __shfl_xor_sync(0xffffffffu, sm, o);
                const float inv = 1.f / sm;
                #pragma unroll
                for (int q = 0; q < 4; q++) {
                    float rv0 = x[q * 4 + 0] * inv, rv1 = x[q * 4 + 1] * inv;
                    float rv2 = x[q * 4 + 2] * inv, rv3 = x[q * 4 + 3] * inv;
                    float* tr = &tile[i * SMRV_TILE_STRIDE + q * 128 + lane * 4];
                    tr[0] = rv0; tr[1] = rv1; tr[2] = rv2; tr[3] = rv3;
                    const size_t kidx = (size_t)p * 512 + q * 128 + lane * 4;
                    __half2 kh0 = *reinterpret_cast<const __half2*>(kb + kidx);
                    __half2 kh1 = *reinterpret_cast<const __half2*>(kb + kidx + 2);
                    racc[q * 4 + 0] = fmaf(rv0, __half2float(kh0.x), racc[q * 4 + 0]);
                    racc[q * 4 + 1] = fmaf(rv1, __half2float(kh0.y), racc[q * 4 + 1]);
                    racc[q * 4 + 2] = fmaf(rv2, __half2float(kh1.x), racc[q * 4 + 2]);
                    racc[q * 4 + 3] = fmaf(rv3, __half2float(kh1.y), racc[q * 4 + 3]);
                }
            }
        }
        __syncthreads();
        #pragma unroll 1
        for (int cc = 0; cc < 32; cc++) {
            int c = w * 32 + cc;
            if (lane < 28) rvb[(size_t)c * PIX + pp * 28 + lane] = tile[lane * SMRV_TILE_STRIDE + c];
        }
        __syncthreads();
    }

    #pragma unroll
    for (int q = 0; q < 4; q++)
        #pragma unroll
        for (int j = 0; j < 4; j++)
            atomicAdd(&rsum[q * 128 + lane * 4 + j], racc[q * 4 + j]);
    __syncthreads();
    if (tid < DIM) r_out[(size_t)b * DIM + tid] = rsum[tid];
}

// ---------------- gate, sa softmax over T, m_sa ----------------
__global__ void gate_sa_kernel(const float* __restrict__ cnew, const float* __restrict__ Wc,
                               const float* __restrict__ bc,   const float* __restrict__ cs,
                               const float* __restrict__ Wsa,  const float* __restrict__ bsa,
                               const float* __restrict__ ms,
                               float* __restrict__ gate_out, float* __restrict__ msa_out)
{
    int b = blockIdx.x, tid = threadIdx.x;   // 256 threads
    __shared__ float red[8];
    __shared__ float sa[TT];
    __shared__ float gsh;
    float p = 0.f;
    for (int d = tid; d < DIM; d += 256) p += cnew[(size_t)b * DIM + d] * Wc[d];
    float tot = blkSum<8>(p, red);
    if (tid == 0) gsh = 1.f / (1.f + __expf(-(tot + bc[0])));
    __syncthreads();
    float gate = gsh;
    for (int t8 = 0; t8 < TT; t8++) {
        float qv = 0.f;
        const float* csrow = cs + ((size_t)t8 * BATCH + b) * DIM;
        for (int d = tid; d < DIM; d += 256) qv += csrow[d] * Wsa[d];
        float qt = blkSum<8>(qv, red);
        if (tid == 0) sa[t8] = gate * qt + bsa[0];
    }
    __syncthreads();
    if (tid == 0) {
        float mx = -INFINITY;
        for (int i = 0; i < TT; i++) mx = fmaxf(mx, sa[i]);
        float sm = 0.f;
        for (int i = 0; i < TT; i++) { float e = __expf(sa[i] - mx); sa[i] = e; sm += e; }
        float inv = 1.f / sm;
        for (int i = 0; i < TT; i++) sa[i] *= inv;
    }
    __syncthreads();
    for (int d = tid; d < DIM; d += 256) {
        float a = 0.f;
        #pragma unroll
        for (int i = 0; i < TT; i++)
            a = fmaf(sa[i], ms[((size_t)i * BATCH + b) * DIM + d], a);
        msa_out[(size_t)b * DIM + d] = a;
    }
    if (tid == 0) gate_out[b] = gate;
}

// ---------------- final ----------------
__global__ void final_kernel(const float* __restrict__ m, const float* __restrict__ mm,
                             const float* __restrict__ tmp, const float* __restrict__ gate,
                             float* __restrict__ mnew)
{
    int i = blockIdx.x * 256 + threadIdx.x;
    int b = i >> 9;
    float g = gate[b];
    mnew[i] = g * m[i] + (1.f - g) * (mm[i] + tmp[i]);
}

// ---------------- launch ----------------
extern "C" void kernel_launch(void* const* d_in, const int* in_sizes, int n_in,
                              void* d_out, int out_size)
{
    const float* c    = (const float*)d_in[0];
    const float* m    = (const float*)d_in[1];
    const float* k    = (const float*)d_in[2];
    const float* q    = (const float*)d_in[3];
    const float* cw   = (const float*)d_in[4];
    const int*   mask = (const int*)  d_in[5];
    const float* cs   = (const float*)d_in[6];
    const float* ms   = (const float*)d_in[7];
    const float* Wcq  = (const float*)d_in[8];
    const float* bcq  = (const float*)d_in[9];
    const float* Wca  = (const float*)d_in[10];
    const float* bca  = (const float*)d_in[11];
    const float* Wm_r = (const float*)d_in[12];
    const float* bm_r = (const float*)d_in[13];
    const float* Wk   = (const float*)d_in[14];
    const float* bk   = (const float*)d_in[15];
    const float* WI   = (const float*)d_in[16];
    const float* bI   = (const float*)d_in[17];
    const float* Wra  = (const float*)d_in[18];
    const float* bra  = (const float*)d_in[19];
    const float* Wm_w = (const float*)d_in[20];
    const float* bm_w = (const float*)d_in[21];
    const float* Wsa  = (const float*)d_in[22];
    const float* bsa  = (const float*)d_in[23];
    const float* Wm2  = (const float*)d_in[24];
    const float* bm2  = (const float*)d_in[25];
    const float* Wc   = (const float*)d_in[26];
    const float* bc   = (const float*)d_in[27];
    const float* Ws   = (const float*)d_in[28];

    float* out      = (float*)d_out;
    float* out_cnew = out;                       // [B,D]
    float* out_mnew = out + 131072;              // [B,D]
    float* out_cv   = out + 262144;              // [B,L]
    float* out_rv   = out + 270336;              // [B,D,H,W]

    __half *p_kT, *p_I2, *p_J2, *p_ra, *p_Wk2, *p_WI2, *p_Wra2;
    float *p_cq, *p_mI, *p_r, *p_mprev, *p_mm, *p_msa, *p_tmp, *p_gate;
    cudaGetSymbolAddress((void**)&p_kT,   g_kT);
    cudaGetSymbolAddress((void**)&p_I2,   g_I2);
    cudaGetSymbolAddress((void**)&p_J2,   g_J2);
    cudaGetSymbolAddress((void**)&p_ra,   g_ra);
    cudaGetSymbolAddress((void**)&p_Wk2,  g_Wk2);
    cudaGetSymbolAddress((void**)&p_WI2,  g_WI2);
    cudaGetSymbolAddress((void**)&p_Wra2, g_Wra2);
    cudaGetSymbolAddress((void**)&p_cq,   g_cq);
    cudaGetSymbolAddress((void**)&p_mI,   g_mI);
    cudaGetSymbolAddress((void**)&p_r,    g_r);
    cudaGetSymbolAddress((void**)&p_mprev,g_mprev);
    cudaGetSymbolAddress((void**)&p_mm,   g_mm);
    cudaGetSymbolAddress((void**)&p_msa,  g_msa);
    cudaGetSymbolAddress((void**)&p_tmp,  g_tmp);
    cudaGetSymbolAddress((void**)&p_gate, g_gate);

    cudaFuncSetAttribute((const void*)mma_gemm<512,  false, 0>, cudaFuncAttributeMaxDynamicSharedMemorySize, MG_SMEM);
    cudaFuncSetAttribute((const void*)mma_gemm<1024, true,  0>, cudaFuncAttributeMaxDynamicSharedMemorySize, MG_SMEM);
    cudaFuncSetAttribute((const void*)mma_gemm<512,  false, 1>, cudaFuncAttributeMaxDynamicSharedMemorySize, MG_SMEM);
    cudaFuncSetAttribute(softmax_rv_kernel, cudaFuncAttributeMaxDynamicSharedMemorySize, SMRV_SMEM);

    // ---- ordered so my 4th launch = mma_gemm I (ncu -s 5 -c 1 visibility) ----
    // 1. Wk, WI, Wra -> fp16 (single batched launch)
    halve_w3_kernel<<<4096, 256>>>(Wk, WI, Wra, p_Wk2, p_WI2, p_Wra2);
    // 2. k -> kT fp16
    transpose_half_k<<<dim3(7, 16, BATCH), dim3(32, 8)>>>(k, p_kT);
    // 3. mI = m @ Wm_r^T + bm_r
    gemm_small<512, false><<<dim3(8, 4), 256>>>(m, nullptr, Wm_r, bm_r, p_mI);
    // 4. I = mI ⊙ (kT @ Wk^T + bk) -> fp16           [HMMA]  << profiled
    mma_gemm<512, false, 0><<<dim3(4, 392), 256, MG_SMEM>>>(
        p_kT, nullptr, p_Wk2, bk, p_mI, p_I2);
    // 5. cq = [c|q] @ Wcq^T + bcq
    gemm_small<1024, true><<<dim3(8, 4), 256>>>(c, q, Wcq, bcq, p_cq);
    // 6. ControlUnit tail -> cv, c_new
    control_kernel<<<BATCH, 512>>>(p_cq, cw, mask, Wca, bca, out_cv, out_cnew);
    // 7. J = c_new ⊙ ([I|kT] @ WI^T + bI) -> fp16    [HMMA]
    mma_gemm<1024, true, 0><<<dim3(4, 392), 256, MG_SMEM>>>(
        p_I2, p_kT, p_WI2, bI, out_cnew, p_J2);
    // 8. ra = J @ Wra^T + bra -> fp16                [HMMA]
    mma_gemm<512, false, 1><<<dim3(4, 392), 256, MG_SMEM>>>(
        p_J2, nullptr, p_Wra2, bra, nullptr, p_ra);
    // 9. rv = softmax_c(ra) -> d_out (transposed), r = sum_p rv*k
    softmax_rv_kernel<<<BATCH, 512, SMRV_SMEM>>>(p_ra, p_kT, out_rv, p_r);
    // 10. m_prev = [r|m] @ Wm_w^T + bm_w
    gemm_small<1024, true><<<dim3(8, 4), 256>>>(p_r, m, Wm_w, bm_w, p_mprev);
    // 11. m_ = m_prev @ Wm2^T + bm2
    gemm_small<512, false><<<dim3(8, 4), 256>>>(p_mprev, nullptr, Wm2, bm2, p_mm);
    // 12. gate, sa softmax, m_sa
    gate_sa_kernel<<<BATCH, 256>>>(out_cnew, Wc, bc, cs, Wsa, bsa, ms, p_gate, p_msa);
    // 13. tmp = m_sa @ Ws^T
    gemm_small<512, false><<<dim3(8, 4), 256>>>(p_msa, nullptr, Ws, nullptr, p_tmp);
    // 14. m_new = gate*m + (1-gate)*(m_ + tmp)
    final_kernel<<<(BATCH * DIM) / 256, 256>>>(m, p_mm, p_tmp, p_gate, out_mnew);
}

// round 11
// speedup vs baseline: 2.2288x; 1.1436x over previous
#include <cuda_runtime.h>
#include <cuda_bf16.h>
#include <cuda_fp16.h>
#include <math.h>
#include <stdint.h>

#define BATCH 256
#define DIM   512
#define LW    32
#define PIX   196
#define TT    8
#define MBIG  (BATCH*PIX)   // 50176

// ---------------- scratch (static __device__ — allocation-guard safe) ----------------
__device__ __half g_kT [MBIG*512];     // plain fp16, stride 512
__device__ __half g_I2 [MBIG*512];
__device__ __half g_J2 [MBIG*512];
__device__ __half g_ra [MBIG*512];
__device__ __half g_Wk2 [DIM*DIM];
__device__ __half g_WI2 [DIM*2*DIM];
__device__ __half g_Wra2[DIM*DIM];
__device__ float g_cq  [BATCH*DIM];
__device__ float g_mI  [BATCH*DIM];
__device__ float g_r   [BATCH*DIM];
__device__ float g_mprev[BATCH*DIM];
__device__ float g_mm  [BATCH*DIM];
__device__ float g_msa [BATCH*DIM];
__device__ float g_tmp [BATCH*DIM];
__device__ float g_gate[BATCH];

// ---------------- second stream + fork/join events (created at load, pre-capture) ----
static cudaStream_t g_s2 = nullptr;
static cudaEvent_t  g_evFork = nullptr, g_evA = nullptr, g_evB = nullptr, g_evC = nullptr;
static struct StreamInit {
    StreamInit() {
        cudaStreamCreateWithFlags(&g_s2, cudaStreamNonBlocking);
        cudaEventCreateWithFlags(&g_evFork, cudaEventDisableTiming);
        cudaEventCreateWithFlags(&g_evA,    cudaEventDisableTiming);
        cudaEventCreateWithFlags(&g_evB,    cudaEventDisableTiming);
        cudaEventCreateWithFlags(&g_evC,    cudaEventDisableTiming);
    }
} g_streamInit;

// ================= helpers =================
__device__ __forceinline__ uint32_t smem_u32(const void* p) {
    uint32_t a;
    asm("{ .reg .u64 t; cvta.to.shared.u64 t, %1; cvt.u32.u64 %0, t; }" : "=r"(a) : "l"(p));
    return a;
}
__device__ __forceinline__ void cpasync16(uint32_t dst, const void* src) {
    asm volatile("cp.async.cg.shared.global [%0], [%1], 16;" :: "r"(dst), "l"(src) : "memory");
}
__device__ __forceinline__ void cp_commit() { asm volatile("cp.async.commit_group;" ::: "memory"); }
__device__ __forceinline__ void cp_wait1() { asm volatile("cp.async.wait_group 1;" ::: "memory"); }
__device__ __forceinline__ void cp_wait0() { asm volatile("cp.async.wait_group 0;" ::: "memory"); }

__device__ __forceinline__ void ldm_x4(uint32_t& r0, uint32_t& r1, uint32_t& r2, uint32_t& r3, uint32_t a) {
    asm volatile("ldmatrix.sync.aligned.m8n8.x4.shared.b16 {%0,%1,%2,%3}, [%4];"
                 : "=r"(r0), "=r"(r1), "=r"(r2), "=r"(r3) : "r"(a));
}
__device__ __forceinline__ void mma16816h(float* c, const uint32_t* a, const uint32_t* b) {
    asm volatile("mma.sync.aligned.m16n8k16.row.col.f32.f16.f16.f32 "
                 "{%0,%1,%2,%3}, {%4,%5,%6,%7}, {%8,%9}, {%0,%1,%2,%3};"
                 : "+f"(c[0]), "+f"(c[1]), "+f"(c[2]), "+f"(c[3])
                 : "r"(a[0]), "r"(a[1]), "r"(a[2]), "r"(a[3]), "r"(b[0]), "r"(b[1]));
}

// ================= HMMA pure-fp16 GEMM =================
#define MG_STAGE 32768
#define MG_SMEM  (3*MG_STAGE)

template<int K, bool CONCAT, int EPI>
__global__ void __launch_bounds__(256, 2) mma_gemm(
    const __half* __restrict__ A0, const __half* __restrict__ A1,
    const __half* __restrict__ W,
    const float* __restrict__ bias, const float* __restrict__ scale,
    __half* __restrict__ O)
{
    constexpr int KIT = K / 64;
    extern __shared__ __align__(128) char dsm[];
    const uint32_t smb = smem_u32(dsm);

    const int tid = threadIdx.x, lane = tid & 31, wid = tid >> 5;
    const int bm = blockIdx.y * 128, bn = blockIdx.x * 128;
    const int wm = (wid >> 2) * 64, wn = (wid & 3) * 32;

    float acc[4][4][4];
    #pragma unroll
    for (int i = 0; i < 4; i++)
        #pragma unroll
        for (int j = 0; j < 4; j++)
            #pragma unroll
            for (int v = 0; v < 4; v++) acc[i][j][v] = 0.f;

    auto load_stage = [&](int it, int stage) {
        uint32_t sb = smb + (uint32_t)stage * MG_STAGE;
        int k0 = it * 64;
        const __half* Asrc = A0;
        int ac = k0;
        if (CONCAT && k0 >= 512) { Asrc = A1; ac = k0 - 512; }
        #pragma unroll
        for (int j = 0; j < 4; j++) {
            int f = tid + j * 256;
            int row = f >> 3, cc = f & 7;
            uint32_t d = sb + row * 128 + (uint32_t)((cc ^ (row & 7)) * 16);
            cpasync16(d, Asrc + (size_t)(bm + row) * 512 + ac + cc * 8);
            cpasync16(d + 16384u, W + (size_t)(bn + row) * K + k0 + cc * 8);
        }
    };

    load_stage(0, 0); cp_commit();
    if (KIT > 1) { load_stage(1, 1); cp_commit(); }

    for (int it = 0; it < KIT; ++it) {
        if (it + 1 < KIT) cp_wait1(); else cp_wait0();
        __syncthreads();
        if (it + 2 < KIT) { load_stage(it + 2, (it + 2) % 3); cp_commit(); }

        const uint32_t sb = smb + (uint32_t)(it % 3) * MG_STAGE;
        const uint32_t sA = sb, sB = sb + 16384u;
        #pragma unroll
        for (int kp = 0; kp < 4; kp++) {
            uint32_t bf[2][4];
            #pragma unroll
            for (int pr = 0; pr < 2; pr++) {
                int nrow = wn + pr * 16 + ((lane >> 4) << 3) + (lane & 7);
                int chunk = (kp * 2 + ((lane >> 3) & 1)) ^ (nrow & 7);
                ldm_x4(bf[pr][0], bf[pr][1], bf[pr][2], bf[pr][3], sB + nrow * 128 + chunk * 16);
            }
            #pragma unroll
            for (int mi = 0; mi < 4; mi++) {
                uint32_t ah[4];
                int row = wm + mi * 16 + (lane & 15);
                int chunk = (kp * 2 + (lane >> 4)) ^ (row & 7);
                ldm_x4(ah[0], ah[1], ah[2], ah[3], sA + row * 128 + chunk * 16);
                #pragma unroll
                for (int ni = 0; ni < 4; ni++)
                    mma16816h(acc[mi][ni], ah, &bf[ni >> 1][(ni & 1) * 2]);
            }
        }
    }

    #pragma unroll
    for (int ni = 0; ni < 4; ni++) {
        const int n0 = bn + wn + ni * 8 + 2 * (lane & 3);
        const float b0 = bias[n0], b1 = bias[n0 + 1];
        #pragma unroll
        for (int mi = 0; mi < 4; mi++) {
            const int r0 = bm + wm + mi * 16 + (lane >> 2);
            const int r1 = r0 + 8;
            float* c = acc[mi][ni];
            if (EPI == 0) {
                const float* s0 = scale + (size_t)(r0 / PIX) * DIM;
                const float* s1 = scale + (size_t)(r1 / PIX) * DIM;
                float v00 = (c[0] + b0) * s0[n0], v01 = (c[1] + b1) * s0[n0 + 1];
                float v10 = (c[2] + b0) * s1[n0], v11 = (c[3] + b1) * s1[n0 + 1];
                *reinterpret_cast<__half2*>(O + (size_t)r0 * 512 + n0) = __floats2half2_rn(v00, v01);
                *reinterpret_cast<__half2*>(O + (size_t)r1 * 512 + n0) = __floats2half2_rn(v10, v11);
            } else {
                *reinterpret_cast<__half2*>(O + (size_t)r0 * 512 + n0) = __floats2half2_rn(c[0] + b0, c[1] + b1);
                *reinterpret_cast<__half2*>(O + (size_t)r1 * 512 + n0) = __floats2half2_rn(c[2] + b0, c[3] + b1);
            }
        }
    }
}

// ================= small fp32 GEMM: register-prefetch, 1 sync/iter =================
template<int K, bool CONCAT>
__global__ void __launch_bounds__(256) gemm_small(
    const float* __restrict__ A0, const float* __restrict__ A1,
    const float* __restrict__ W, const float* __restrict__ bias,
    float* __restrict__ C)
{
    constexpr int BM = 64, BN = 64, BK = 32;
    constexpr int NIT = K / BK;
    constexpr int halfK = K / 2;
    __shared__ __align__(16) float As[2][BK][BM];
    __shared__ __align__(16) float Bs[2][BK][BN];

    const int tid = threadIdx.x;
    const int bm = blockIdx.y * BM, bn = blockIdx.x * BN;
    const int tx = tid & 15, ty = tid >> 4;

    float4 pa[2], pb[2];
    auto gload = [&](int it) {
        int k0 = it * BK;
        #pragma unroll
        for (int j = 0; j < 2; j++) {
            int f = tid + j * 256;
            int r = f >> 3, c4 = (f & 7) * 4;
            int gk = k0 + c4;
            const float* srcA;
            if (CONCAT) {
                srcA = (gk < halfK) ? (A0 + (size_t)(bm + r) * halfK + gk)
                                    : (A1 + (size_t)(bm + r) * halfK + (gk - halfK));
            } else {
                srcA = A0 + (size_t)(bm + r) * K + gk;
            }
            pa[j] = *reinterpret_cast<const float4*>(srcA);
            pb[j] = *reinterpret_cast<const float4*>(W + (size_t)(bn + r) * K + gk);
        }
    };
    auto sstore = [&](int buf) {
        #pragma unroll
        for (int j = 0; j < 2; j++) {
            int f = tid + j * 256;
            int r = f >> 3, c4 = (f & 7) * 4;
            As[buf][c4 + 0][r] = pa[j].x; As[buf][c4 + 1][r] = pa[j].y;
            As[buf][c4 + 2][r] = pa[j].z; As[buf][c4 + 3][r] = pa[j].w;
            Bs[buf][c4 + 0][r] = pb[j].x; Bs[buf][c4 + 1][r] = pb[j].y;
            Bs[buf][c4 + 2][r] = pb[j].z; Bs[buf][c4 + 3][r] = pb[j].w;
        }
    };

    float acc[4][4];
    #pragma unroll
    for (int i = 0; i < 4; i++)
        #pragma unroll
        for (int j = 0; j < 4; j++) acc[i][j] = 0.f;

    gload(0); sstore(0); __syncthreads();
    for (int it = 0; it < NIT; ++it) {
        if (it + 1 < NIT) gload(it + 1);
        const int buf = it & 1;
        #pragma unroll
        for (int kk = 0; kk < BK; kk++) {
            float4 a = *reinterpret_cast<const float4*>(&As[buf][kk][ty * 4]);
            float4 b = *reinterpret_cast<const float4*>(&Bs[buf][kk][tx * 4]);
            acc[0][0] = fmaf(a.x, b.x, acc[0][0]); acc[0][1] = fmaf(a.x, b.y, acc[0][1]);
            acc[0][2] = fmaf(a.x, b.z, acc[0][2]); acc[0][3] = fmaf(a.x, b.w, acc[0][3]);
            acc[1][0] = fmaf(a.y, b.x, acc[1][0]); acc[1][1] = fmaf(a.y, b.y, acc[1][1]);
            acc[1][2] = fmaf(a.y, b.z, acc[1][2]); acc[1][3] = fmaf(a.y, b.w, acc[1][3]);
            acc[2][0] = fmaf(a.z, b.x, acc[2][0]); acc[2][1] = fmaf(a.z, b.y, acc[2][1]);
            acc[2][2] = fmaf(a.z, b.z, acc[2][2]); acc[2][3] = fmaf(a.z, b.w, acc[2][3]);
            acc[3][0] = fmaf(a.w, b.x, acc[3][0]); acc[3][1] = fmaf(a.w, b.y, acc[3][1]);
            acc[3][2] = fmaf(a.w, b.z, acc[3][2]); acc[3][3] = fmaf(a.w, b.w, acc[3][3]);
        }
        if (it + 1 < NIT) sstore(buf ^ 1);
        __syncthreads();
    }

    float bb[4];
    #pragma unroll
    for (int j = 0; j < 4; j++) bb[j] = bias ? bias[bn + tx * 4 + j] : 0.f;
    #pragma unroll
    for (int i = 0; i < 4; i++) {
        int gm = bm + ty * 4 + i;
        float4 v = make_float4(acc[i][0] + bb[0], acc[i][1] + bb[1],
                               acc[i][2] + bb[2], acc[i][3] + bb[3]);
        *reinterpret_cast<float4*>(&C[(size_t)gm * DIM + bn + tx * 4]) = v;
    }
}

// ================= conversions =================
__global__ void halve_w3_kernel(const float* __restrict__ wk, const float* __restrict__ wi,
                                const float* __restrict__ wra,
                                __half* __restrict__ ok, __half* __restrict__ oi,
                                __half* __restrict__ ora)
{
    int i = blockIdx.x * 256 + threadIdx.x;
    if (i < 262144) ok[i] = __float2half_rn(wk[i]);
    else if (i < 786432) { int j = i - 262144; oi[j] = __float2half_rn(wi[j]); }
    else { int j = i - 786432; ora[j] = __float2half_rn(wra[j]); }
}

__global__ void transpose_half_k(const float* __restrict__ k, __half* __restrict__ kT)
{
    __shared__ float tile[32][33];
    int b  = blockIdx.z;
    int p0 = blockIdx.x * 32;
    int c0 = blockIdx.y * 32;
    int tx = threadIdx.x, ty = threadIdx.y;
    #pragma unroll
    for (int j = 0; j < 32; j += 8) {
        int c = c0 + ty + j, p = p0 + tx;
        if (p < PIX) tile[ty + j][tx] = k[((size_t)b * DIM + c) * PIX + p];
    }
    __syncthreads();
    #pragma unroll
    for (int j = 0; j < 32; j += 8) {
        int p = p0 + ty + j, c = c0 + tx;
        if (p < PIX)
            kT[((size_t)b * PIX + p) * 512 + c] = __float2half_rn(tile[tx][ty + j]);
    }
}

// ---------------- reduction helpers ----------------
template<int NW>
__device__ __forceinline__ float blkSum(float v, float* red) {
    #pragma unroll
    for (int o = 16; o > 0; o >>= 1) v += __shfl_xor_sync(0xffffffffu, v, o);
    __syncthreads();
    if ((threadIdx.x & 31) == 0) red[threadIdx.x >> 5] = v;
    __syncthreads();
    float s = 0.f;
    #pragma unroll
    for (int i = 0; i < NW; i++) s += red[i];
    return s;
}

// ---------------- ControlUnit tail: warp-per-l ----------------
__global__ void __launch_bounds__(512) control_kernel(
    const float* __restrict__ cq, const float* __restrict__ cw,
    const int* __restrict__ mask, const float* __restrict__ Wca,
    const float* __restrict__ bca,
    float* __restrict__ cv_out, float* __restrict__ cnew)
{
    int b = blockIdx.x, tid = threadIdx.x;   // 512 threads
    int w = tid >> 5, lane = tid & 31;
    __shared__ float u[DIM];
    __shared__ float s[LW];
    const float* cwb = cw + (size_t)b * LW * DIM;
    u[tid] = cq[(size_t)b * DIM + tid] * Wca[tid];
    __syncthreads();
    #pragma unroll
    for (int li = 0; li < 2; li++) {
        int l = w * 2 + li;
        const float* row = cwb + (size_t)l * DIM;
        float p = 0.f;
        #pragma unroll
        for (int j = 0; j < 16; j++) p = fmaf(u[lane + j * 32], row[lane + j * 32], p);
        #pragma unroll
        for (int o = 16; o > 0; o >>= 1) p += __shfl_xor_sync(0xffffffffu, p, o);
        if (lane == 0) s[l] = (mask[b * LW + l] > 0) ? (p + bca[0]) : -INFINITY;
    }
    __syncthreads();
    if (tid == 0) {
        float mx = -INFINITY;
        for (int l = 0; l < LW; l++) mx = fmaxf(mx, s[l]);
        float sm = 0.f;
        for (int l = 0; l < LW; l++) { float e = __expf(s[l] - mx); s[l] = e; sm += e; }
        float inv = 1.f / sm;
        for (int l = 0; l < LW; l++) { s[l] *= inv; cv_out[b * LW + l] = s[l]; }
    }
    __syncthreads();
    float a = 0.f;
    #pragma unroll
    for (int l = 0; l < LW; l++) a = fmaf(s[l], cwb[(size_t)l * DIM + tid], a);
    cnew[(size_t)b * DIM + tid] = a;
}

// ---------------- softmax over channels: warp-per-pixel (fp16 ra), 28-pixel staging ----------
#define SMRV_TILE_STRIDE 517
#define SMRV_SMEM (28*SMRV_TILE_STRIDE*4)

__global__ void __launch_bounds__(512) softmax_rv_kernel(
    const __half* __restrict__ ra, const __half* __restrict__ kT,
    float* __restrict__ rv_out, float* __restrict__ r_out)
{
    extern __shared__ float tile[];          // [28][517]
    __shared__ float rsum[DIM];
    const int b = blockIdx.x, tid = threadIdx.x;
    const int w = tid >> 5, lane = tid & 31;
    const __half* rab = ra + (size_t)b * PIX * 512;
    const __half* kb = kT + (size_t)b * PIX * 512;
    float* rvb = rv_out + (size_t)b * DIM * PIX;

    if (tid < DIM) rsum[tid] = 0.f;
    float racc[16];
    #pragma unroll
    for (int j = 0; j < 16; j++) racc[j] = 0.f;
    __syncthreads();

    for (int pp = 0; pp < 7; pp++) {
        if (w < 14) {
            #pragma unroll
            for (int half = 0; half < 2; half++) {
                const int i = half * 14 + w;
                const int p = pp * 28 + i;
                float x[16];
                #pragma unroll
                for (int q = 0; q < 4; q++) {
                    const size_t ridx = (size_t)p * 512 + q * 128 + lane * 4;
                    __half2 r0 = *reinterpret_cast<const __half2*>(rab + ridx);
                    __half2 r1 = *reinterpret_cast<const __half2*>(rab + ridx + 2);
                    x[q * 4 + 0] = __half2float(r0.x); x[q * 4 + 1] = __half2float(r0.y);
                    x[q * 4 + 2] = __half2float(r1.x); x[q * 4 + 3] = __half2float(r1.y);
                }
                float mx = x[0];
                #pragma unroll
                for (int j = 1; j < 16; j++) mx = fmaxf(mx, x[j]);
                #pragma unroll
                for (int o = 16; o > 0; o >>= 1) mx = fmaxf(mx, __shfl_xor_sync(0xffffffffu, mx, o));
                float sm = 0.f;
                #pragma unroll
                for (int j = 0; j < 16; j++) { x[j] = __expf(x[j] - mx); sm += x[j]; }
                #pragma unroll
                for (int o = 16; o > 0; o >>= 1) sm += __shfl_xor_sync(0xffffffffu, sm, o);
                const float inv = 1.f / sm;
                #pragma unroll
                for (int q = 0; q < 4; q++) {
                    float rv0 = x[q * 4 + 0] * inv, rv1 = x[q * 4 + 1] * inv;
                    float rv2 = x[q * 4 + 2] * inv, rv3 = x[q * 4 + 3] * inv;
                    float* tr = &tile[i * SMRV_TILE_STRIDE + q * 128 + lane * 4];
                    tr[0] = rv0; tr[1] = rv1; tr[2] = rv2; tr[3] = rv3;
                    const size_t kidx = (size_t)p * 512 + q * 128 + lane * 4;
                    __half2 kh0 = *reinterpret_cast<const __half2*>(kb + kidx);
                    __half2 kh1 = *reinterpret_cast<const __half2*>(kb + kidx + 2);
                    racc[q * 4 + 0] = fmaf(rv0, __half2float(kh0.x), racc[q * 4 + 0]);
                    racc[q * 4 + 1] = fmaf(rv1, __half2float(kh0.y), racc[q * 4 + 1]);
                    racc[q * 4 + 2] = fmaf(rv2, __half2float(kh1.x), racc[q * 4 + 2]);
                    racc[q * 4 + 3] = fmaf(rv3, __half2float(kh1.y), racc[q * 4 + 3]);
                }
            }
        }
        __syncthreads();
        #pragma unroll 1
        for (int cc = 0; cc < 32; cc++) {
            int c = w * 32 + cc;
            if (lane < 28) rvb[(size_t)c * PIX + pp * 28 + lane] = tile[lane * SMRV_TILE_STRIDE + c];
        }
        __syncthreads();
    }

    #pragma unroll
    for (int q = 0; q < 4; q++)
        #pragma unroll
        for (int j = 0; j < 4; j++)
            atomicAdd(&rsum[q * 128 + lane * 4 + j], racc[q * 4 + j]);
    __syncthreads();
    if (tid < DIM) r_out[(size_t)b * DIM + tid] = rsum[tid];
}

// ---------------- gate, sa softmax over T, m_sa ----------------
__global__ void gate_sa_kernel(const float* __restrict__ cnew, const float* __restrict__ Wc,
                               const float* __restrict__ bc,   const float* __restrict__ cs,
                               const float* __restrict__ Wsa,  const float* __restrict__ bsa,
                               const float* __restrict__ ms,
                               float* __restrict__ gate_out, float* __restrict__ msa_out)
{
    int b = blockIdx.x, tid = threadIdx.x;   // 256 threads
    __shared__ float red[8];
    __shared__ float sa[TT];
    __shared__ float gsh;
    float p = 0.f;
    for (int d = tid; d < DIM; d += 256) p += cnew[(size_t)b * DIM + d] * Wc[d];
    float tot = blkSum<8>(p, red);
    if (tid == 0) gsh = 1.f / (1.f + __expf(-(tot + bc[0])));
    __syncthreads();
    float gate = gsh;
    for (int t8 = 0; t8 < TT; t8++) {
        float qv = 0.f;
        const float* csrow = cs + ((size_t)t8 * BATCH + b) * DIM;
        for (int d = tid; d < DIM; d += 256) qv += csrow[d] * Wsa[d];
        float qt = blkSum<8>(qv, red);
        if (tid == 0) sa[t8] = gate * qt + bsa[0];
    }
    __syncthreads();
    if (tid == 0) {
        float mx = -INFINITY;
        for (int i = 0; i < TT; i++) mx = fmaxf(mx, sa[i]);
        float sm = 0.f;
        for (int i = 0; i < TT; i++) { float e = __expf(sa[i] - mx); sa[i] = e; sm += e; }
        float inv = 1.f / sm;
        for (int i = 0; i < TT; i++) sa[i] *= inv;
    }
    __syncthreads();
    for (int d = tid; d < DIM; d += 256) {
        float a = 0.f;
        #pragma unroll
        for (int i = 0; i < TT; i++)
            a = fmaf(sa[i], ms[((size_t)i * BATCH + b) * DIM + d], a);
        msa_out[(size_t)b * DIM + d] = a;
    }
    if (tid == 0) gate_out[b] = gate;
}

// ---------------- final ----------------
__global__ void final_kernel(const float* __restrict__ m, const float* __restrict__ mm,
                             const float* __restrict__ tmp, const float* __restrict__ gate,
                             float* __restrict__ mnew)
{
    int i = blockIdx.x * 256 + threadIdx.x;
    int b = i >> 9;
    float g = gate[b];
    mnew[i] = g * m[i] + (1.f - g) * (mm[i] + tmp[i]);
}

// ---------------- launch ----------------
extern "C" void kernel_launch(void* const* d_in, const int* in_sizes, int n_in,
                              void* d_out, int out_size)
{
    const float* c    = (const float*)d_in[0];
    const float* m    = (const float*)d_in[1];
    const float* k    = (const float*)d_in[2];
    const float* q    = (const float*)d_in[3];
    const float* cw   = (const float*)d_in[4];
    const int*   mask = (const int*)  d_in[5];
    const float* cs   = (const float*)d_in[6];
    const float* ms   = (const float*)d_in[7];
    const float* Wcq  = (const float*)d_in[8];
    const float* bcq  = (const float*)d_in[9];
    const float* Wca  = (const float*)d_in[10];
    const float* bca  = (const float*)d_in[11];
    const float* Wm_r = (const float*)d_in[12];
    const float* bm_r = (const float*)d_in[13];
    const float* Wk   = (const float*)d_in[14];
    const float* bk   = (const float*)d_in[15];
    const float* WI   = (const float*)d_in[16];
    const float* bI   = (const float*)d_in[17];
    const float* Wra  = (const float*)d_in[18];
    const float* bra  = (const float*)d_in[19];
    const float* Wm_w = (const float*)d_in[20];
    const float* bm_w = (const float*)d_in[21];
    const float* Wsa  = (const float*)d_in[22];
    const float* bsa  = (const float*)d_in[23];
    const float* Wm2  = (const float*)d_in[24];
    const float* bm2  = (const float*)d_in[25];
    const float* Wc   = (const float*)d_in[26];
    const float* bc   = (const float*)d_in[27];
    const float* Ws   = (const float*)d_in[28];

    float* out      = (float*)d_out;
    float* out_cnew = out;                       // [B,D]
    float* out_mnew = out + 131072;              // [B,D]
    float* out_cv   = out + 262144;              // [B,L]
    float* out_rv   = out + 270336;              // [B,D,H,W]

    __half *p_kT, *p_I2, *p_J2, *p_ra, *p_Wk2, *p_WI2, *p_Wra2;
    float *p_cq, *p_mI, *p_r, *p_mprev, *p_mm, *p_msa, *p_tmp, *p_gate;
    cudaGetSymbolAddress((void**)&p_kT,   g_kT);
    cudaGetSymbolAddress((void**)&p_I2,   g_I2);
    cudaGetSymbolAddress((void**)&p_J2,   g_J2);
    cudaGetSymbolAddress((void**)&p_ra,   g_ra);
    cudaGetSymbolAddress((void**)&p_Wk2,  g_Wk2);
    cudaGetSymbolAddress((void**)&p_WI2,  g_WI2);
    cudaGetSymbolAddress((void**)&p_Wra2, g_Wra2);
    cudaGetSymbolAddress((void**)&p_cq,   g_cq);
    cudaGetSymbolAddress((void**)&p_mI,   g_mI);
    cudaGetSymbolAddress((void**)&p_r,    g_r);
    cudaGetSymbolAddress((void**)&p_mprev,g_mprev);
    cudaGetSymbolAddress((void**)&p_mm,   g_mm);
    cudaGetSymbolAddress((void**)&p_msa,  g_msa);
    cudaGetSymbolAddress((void**)&p_tmp,  g_tmp);
    cudaGetSymbolAddress((void**)&p_gate, g_gate);

    cudaFuncSetAttribute((const void*)mma_gemm<512,  false, 0>, cudaFuncAttributeMaxDynamicSharedMemorySize, MG_SMEM);
    cudaFuncSetAttribute((const void*)mma_gemm<1024, true,  0>, cudaFuncAttributeMaxDynamicSharedMemorySize, MG_SMEM);
    cudaFuncSetAttribute((const void*)mma_gemm<512,  false, 1>, cudaFuncAttributeMaxDynamicSharedMemorySize, MG_SMEM);
    cudaFuncSetAttribute(softmax_rv_kernel, cudaFuncAttributeMaxDynamicSharedMemorySize, SMRV_SMEM);

    // ================== two-stream DAG ==================
    // s0 (capture/NULL): transpose -> [evA] gemmI -> [evB] gemmJ -> gemmRA -> softmax
    //                     -> m_prev -> m_ -> [evC] final
    // s2:                 halve_w3 -> mI -> evA -> cq -> control -> evB
    //                     -> gate_sa -> tmp -> evC
    cudaStream_t s2 = g_s2;

    // s0: transpose first (longest pole before gemmI)
    transpose_half_k<<<dim3(7, 16, BATCH), dim3(32, 8)>>>(k, p_kT);

    // fork s2 from capture stream
    cudaEventRecord(g_evFork, 0);
    cudaStreamWaitEvent(s2, g_evFork, 0);

    // s2 chain
    halve_w3_kernel<<<4096, 256, 0, s2>>>(Wk, WI, Wra, p_Wk2, p_WI2, p_Wra2);
    gemm_small<512, false><<<dim3(8, 4), 256, 0, s2>>>(m, nullptr, Wm_r, bm_r, p_mI);
    cudaEventRecord(g_evA, s2);
    gemm_small<1024, true><<<dim3(8, 4), 256, 0, s2>>>(c, q, Wcq, bcq, p_cq);
    control_kernel<<<BATCH, 512, 0, s2>>>(p_cq, cw, mask, Wca, bca, out_cv, out_cnew);
    cudaEventRecord(g_evB, s2);
    gate_sa_kernel<<<BATCH, 256, 0, s2>>>(out_cnew, Wc, bc, cs, Wsa, bsa, ms, p_gate, p_msa);
    gemm_small<512, false><<<dim3(8, 4), 256, 0, s2>>>(p_msa, nullptr, Ws, nullptr, p_tmp);
    cudaEventRecord(g_evC, s2);

    // s0 chain
    cudaStreamWaitEvent(0, g_evA, 0);   // needs Wk2 + mI
    mma_gemm<512, false, 0><<<dim3(4, 392), 256, MG_SMEM>>>(
        p_kT, nullptr, p_Wk2, bk, p_mI, p_I2);
    cudaStreamWaitEvent(0, g_evB, 0);   // needs cnew (+ WI2, already covered)
    mma_gemm<1024, true, 0><<<dim3(4, 392), 256, MG_SMEM>>>(
        p_I2, p_kT, p_WI2, bI, out_cnew, p_J2);
    mma_gemm<512, false, 1><<<dim3(4, 392), 256, MG_SMEM>>>(
        p_J2, nullptr, p_Wra2, bra, nullptr, p_ra);
    softmax_rv_kernel<<<BATCH, 512, SMRV_SMEM>>>(p_ra, p_kT, out_rv, p_r);
    gemm_small<1024, true><<<dim3(8, 4), 256>>>(p_r, m, Wm_w, bm_w, p_mprev);
    gemm_small<512, false><<<dim3(8, 4), 256>>>(p_mprev, nullptr, Wm2, bm2, p_mm);
    cudaStreamWaitEvent(0, g_evC, 0);   // needs gate + tmp
    final_kernel<<<(BATCH * DIM) / 256, 256>>>(m, p_mm, p_tmp, p_gate, out_mnew);
}

// round 12
// speedup vs baseline: 2.3997x; 1.0767x over previous
#include <cuda_runtime.h>
#include <cuda_bf16.h>
#include <cuda_fp16.h>
#include <math.h>
#include <stdint.h>

#define BATCH 256
#define DIM   512
#define LW    32
#define PIX   196
#define TT    8
#define MBIG  (BATCH*PIX)   // 50176

// ---------------- scratch (static __device__ — allocation-guard safe) ----------------
__device__ __half g_kT [MBIG*512];     // plain fp16, stride 512
__device__ __half g_I2 [MBIG*512];
__device__ __half g_J2 [MBIG*512];
__device__ __half g_ra [MBIG*512];
__device__ __half g_Wk2 [DIM*DIM];
__device__ __half g_WI2 [DIM*2*DIM];
__device__ __half g_Wra2[DIM*DIM];
__device__ float g_cq  [BATCH*DIM];
__device__ float g_mI  [BATCH*DIM];
__device__ float g_r   [BATCH*DIM];
__device__ float g_mprev[BATCH*DIM];
__device__ float g_mm  [BATCH*DIM];
__device__ float g_msa [BATCH*DIM];
__device__ float g_tmp [BATCH*DIM];
__device__ float g_gate[BATCH];

// ---------------- second stream + fork/join events (created at load, pre-capture) ----
static cudaStream_t g_s2 = nullptr;
static cudaEvent_t  g_evFork = nullptr, g_evA = nullptr, g_evB = nullptr, g_evC = nullptr;
static struct StreamInit {
    StreamInit() {
        cudaStreamCreateWithFlags(&g_s2, cudaStreamNonBlocking);
        cudaEventCreateWithFlags(&g_evFork, cudaEventDisableTiming);
        cudaEventCreateWithFlags(&g_evA,    cudaEventDisableTiming);
        cudaEventCreateWithFlags(&g_evB,    cudaEventDisableTiming);
        cudaEventCreateWithFlags(&g_evC,    cudaEventDisableTiming);
    }
} g_streamInit;

// ================= helpers =================
__device__ __forceinline__ uint32_t smem_u32(const void* p) {
    uint32_t a;
    asm("{ .reg .u64 t; cvta.to.shared.u64 t, %1; cvt.u32.u64 %0, t; }" : "=r"(a) : "l"(p));
    return a;
}
__device__ __forceinline__ void cpasync16(uint32_t dst, const void* src) {
    asm volatile("cp.async.cg.shared.global [%0], [%1], 16;" :: "r"(dst), "l"(src) : "memory");
}
__device__ __forceinline__ void cp_commit() { asm volatile("cp.async.commit_group;" ::: "memory"); }
__device__ __forceinline__ void cp_wait1() { asm volatile("cp.async.wait_group 1;" ::: "memory"); }
__device__ __forceinline__ void cp_wait0() { asm volatile("cp.async.wait_group 0;" ::: "memory"); }

__device__ __forceinline__ void ldm_x4(uint32_t& r0, uint32_t& r1, uint32_t& r2, uint32_t& r3, uint32_t a) {
    asm volatile("ldmatrix.sync.aligned.m8n8.x4.shared.b16 {%0,%1,%2,%3}, [%4];"
                 : "=r"(r0), "=r"(r1), "=r"(r2), "=r"(r3) : "r"(a));
}
__device__ __forceinline__ void mma16816h(float* c, const uint32_t* a, const uint32_t* b) {
    asm volatile("mma.sync.aligned.m16n8k16.row.col.f32.f16.f16.f32 "
                 "{%0,%1,%2,%3}, {%4,%5,%6,%7}, {%8,%9}, {%0,%1,%2,%3};"
                 : "+f"(c[0]), "+f"(c[1]), "+f"(c[2]), "+f"(c[3])
                 : "r"(a[0]), "r"(a[1]), "r"(a[2]), "r"(a[3]), "r"(b[0]), "r"(b[1]));
}

// ================= HMMA pure-fp16 GEMM =================
#define MG_STAGE 32768
#define MG_SMEM  (3*MG_STAGE)

template<int K, bool CONCAT, int EPI>
__global__ void __launch_bounds__(256, 2) mma_gemm(
    const __half* __restrict__ A0, const __half* __restrict__ A1,
    const __half* __restrict__ W,
    const float* __restrict__ bias, const float* __restrict__ scale,
    __half* __restrict__ O)
{
    constexpr int KIT = K / 64;
    extern __shared__ __align__(128) char dsm[];
    const uint32_t smb = smem_u32(dsm);

    const int tid = threadIdx.x, lane = tid & 31, wid = tid >> 5;
    const int bm = blockIdx.y * 128, bn = blockIdx.x * 128;
    const int wm = (wid >> 2) * 64, wn = (wid & 3) * 32;

    float acc[4][4][4];
    #pragma unroll
    for (int i = 0; i < 4; i++)
        #pragma unroll
        for (int j = 0; j < 4; j++)
            #pragma unroll
            for (int v = 0; v < 4; v++) acc[i][j][v] = 0.f;

    auto load_stage = [&](int it, int stage) {
        uint32_t sb = smb + (uint32_t)stage * MG_STAGE;
        int k0 = it * 64;
        const __half* Asrc = A0;
        int ac = k0;
        if (CONCAT && k0 >= 512) { Asrc = A1; ac = k0 - 512; }
        #pragma unroll
        for (int j = 0; j < 4; j++) {
            int f = tid + j * 256;
            int row = f >> 3, cc = f & 7;
            uint32_t d = sb + row * 128 + (uint32_t)((cc ^ (row & 7)) * 16);
            cpasync16(d, Asrc + (size_t)(bm + row) * 512 + ac + cc * 8);
            cpasync16(d + 16384u, W + (size_t)(bn + row) * K + k0 + cc * 8);
        }
    };

    load_stage(0, 0); cp_commit();
    if (KIT > 1) { load_stage(1, 1); cp_commit(); }

    for (int it = 0; it < KIT; ++it) {
        if (it + 1 < KIT) cp_wait1(); else cp_wait0();
        __syncthreads();
        if (it + 2 < KIT) { load_stage(it + 2, (it + 2) % 3); cp_commit(); }

        const uint32_t sb = smb + (uint32_t)(it % 3) * MG_STAGE;
        const uint32_t sA = sb, sB = sb + 16384u;
        #pragma unroll
        for (int kp = 0; kp < 4; kp++) {
            uint32_t bf[2][4];
            #pragma unroll
            for (int pr = 0; pr < 2; pr++) {
                int nrow = wn + pr * 16 + ((lane >> 4) << 3) + (lane & 7);
                int chunk = (kp * 2 + ((lane >> 3) & 1)) ^ (nrow & 7);
                ldm_x4(bf[pr][0], bf[pr][1], bf[pr][2], bf[pr][3], sB + nrow * 128 + chunk * 16);
            }
            #pragma unroll
            for (int mi = 0; mi < 4; mi++) {
                uint32_t ah[4];
                int row = wm + mi * 16 + (lane & 15);
                int chunk = (kp * 2 + (lane >> 4)) ^ (row & 7);
                ldm_x4(ah[0], ah[1], ah[2], ah[3], sA + row * 128 + chunk * 16);
                #pragma unroll
                for (int ni = 0; ni < 4; ni++)
                    mma16816h(acc[mi][ni], ah, &bf[ni >> 1][(ni & 1) * 2]);
            }
        }
    }

    #pragma unroll
    for (int ni = 0; ni < 4; ni++) {
        const int n0 = bn + wn + ni * 8 + 2 * (lane & 3);
        const float b0 = bias[n0], b1 = bias[n0 + 1];
        #pragma unroll
        for (int mi = 0; mi < 4; mi++) {
            const int r0 = bm + wm + mi * 16 + (lane >> 2);
            const int r1 = r0 + 8;
            float* c = acc[mi][ni];
            if (EPI == 0) {
                const float* s0 = scale + (size_t)(r0 / PIX) * DIM;
                const float* s1 = scale + (size_t)(r1 / PIX) * DIM;
                float v00 = (c[0] + b0) * s0[n0], v01 = (c[1] + b1) * s0[n0 + 1];
                float v10 = (c[2] + b0) * s1[n0], v11 = (c[3] + b1) * s1[n0 + 1];
                *reinterpret_cast<__half2*>(O + (size_t)r0 * 512 + n0) = __floats2half2_rn(v00, v01);
                *reinterpret_cast<__half2*>(O + (size_t)r1 * 512 + n0) = __floats2half2_rn(v10, v11);
            } else {
                *reinterpret_cast<__half2*>(O + (size_t)r0 * 512 + n0) = __floats2half2_rn(c[0] + b0, c[1] + b1);
                *reinterpret_cast<__half2*>(O + (size_t)r1 * 512 + n0) = __floats2half2_rn(c[2] + b0, c[3] + b1);
            }
        }
    }
}

// ================= small fp32 GEMM v2: BM=BN=32, TM=TN=2, 128 CTAs =================
template<int K, bool CONCAT>
__global__ void __launch_bounds__(256) gemm_small(
    const float* __restrict__ A0, const float* __restrict__ A1,
    const float* __restrict__ W, const float* __restrict__ bias,
    float* __restrict__ C)
{
    constexpr int BM = 32, BN = 32, BK = 32;
    constexpr int NIT = K / BK;
    constexpr int halfK = K / 2;
    __shared__ __align__(16) float As[2][BK][BM];
    __shared__ __align__(16) float Bs[2][BK][BN];

    const int tid = threadIdx.x;                 // 256 threads
    const int bm = blockIdx.y * BM, bn = blockIdx.x * BN;
    const int tx = tid & 15, ty = tid >> 4;      // 16 x 16

    float4 pa, pb;
    auto gload = [&](int it) {
        int k0 = it * BK;
        int r = tid >> 3, c4 = (tid & 7) * 4;    // 32 rows x 8 chunks
        int gk = k0 + c4;
        const float* srcA;
        if (CONCAT) {
            srcA = (gk < halfK) ? (A0 + (size_t)(bm + r) * halfK + gk)
                                : (A1 + (size_t)(bm + r) * halfK + (gk - halfK));
        } else {
            srcA = A0 + (size_t)(bm + r) * K + gk;
        }
        pa = *reinterpret_cast<const float4*>(srcA);
        pb = *reinterpret_cast<const float4*>(W + (size_t)(bn + r) * K + gk);
    };
    auto sstore = [&](int buf) {
        int r = tid >> 3, c4 = (tid & 7) * 4;
        As[buf][c4 + 0][r] = pa.x; As[buf][c4 + 1][r] = pa.y;
        As[buf][c4 + 2][r] = pa.z; As[buf][c4 + 3][r] = pa.w;
        Bs[buf][c4 + 0][r] = pb.x; Bs[buf][c4 + 1][r] = pb.y;
        Bs[buf][c4 + 2][r] = pb.z; Bs[buf][c4 + 3][r] = pb.w;
    };

    float acc[2][2] = {{0.f, 0.f}, {0.f, 0.f}};

    gload(0); sstore(0); __syncthreads();
    for (int it = 0; it < NIT; ++it) {
        if (it + 1 < NIT) gload(it + 1);
        const int buf = it & 1;
        #pragma unroll
        for (int kk = 0; kk < BK; kk++) {
            float2 a = *reinterpret_cast<const float2*>(&As[buf][kk][ty * 2]);
            float2 b = *reinterpret_cast<const float2*>(&Bs[buf][kk][tx * 2]);
            acc[0][0] = fmaf(a.x, b.x, acc[0][0]); acc[0][1] = fmaf(a.x, b.y, acc[0][1]);
            acc[1][0] = fmaf(a.y, b.x, acc[1][0]); acc[1][1] = fmaf(a.y, b.y, acc[1][1]);
        }
        if (it + 1 < NIT) sstore(buf ^ 1);
        __syncthreads();
    }

    float b0 = bias ? bias[bn + tx * 2]     : 0.f;
    float b1 = bias ? bias[bn + tx * 2 + 1] : 0.f;
    #pragma unroll
    for (int i = 0; i < 2; i++) {
        int gm = bm + ty * 2 + i;
        float2 v = make_float2(acc[i][0] + b0, acc[i][1] + b1);
        *reinterpret_cast<float2*>(&C[(size_t)gm * DIM + bn + tx * 2]) = v;
    }
}

// ================= conversions =================
__global__ void halve_w3_kernel(const float* __restrict__ wk, const float* __restrict__ wi,
                                const float* __restrict__ wra,
                                __half* __restrict__ ok, __half* __restrict__ oi,
                                __half* __restrict__ ora)
{
    int i = blockIdx.x * 256 + threadIdx.x;
    if (i < 262144) ok[i] = __float2half_rn(wk[i]);
    else if (i < 786432) { int j = i - 262144; oi[j] = __float2half_rn(wi[j]); }
    else { int j = i - 786432; ora[j] = __float2half_rn(wra[j]); }
}

__global__ void transpose_half_k(const float* __restrict__ k, __half* __restrict__ kT)
{
    __shared__ float tile[32][33];
    int b  = blockIdx.z;
    int p0 = blockIdx.x * 32;
    int c0 = blockIdx.y * 32;
    int tx = threadIdx.x, ty = threadIdx.y;
    #pragma unroll
    for (int j = 0; j < 32; j += 8) {
        int c = c0 + ty + j, p = p0 + tx;
        if (p < PIX) tile[ty + j][tx] = k[((size_t)b * DIM + c) * PIX + p];
    }
    __syncthreads();
    #pragma unroll
    for (int j = 0; j < 32; j += 8) {
        int p = p0 + ty + j, c = c0 + tx;
        if (p < PIX)
            kT[((size_t)b * PIX + p) * 512 + c] = __float2half_rn(tile[tx][ty + j]);
    }
}

// ---------------- reduction helpers ----------------
template<int NW>
__device__ __forceinline__ float blkSum(float v, float* red) {
    #pragma unroll
    for (int o = 16; o > 0; o >>= 1) v += __shfl_xor_sync(0xffffffffu, v, o);
    __syncthreads();
    if ((threadIdx.x & 31) == 0) red[threadIdx.x >> 5] = v;
    __syncthreads();
    float s = 0.f;
    #pragma unroll
    for (int i = 0; i < NW; i++) s += red[i];
    return s;
}

// ---------------- ControlUnit tail: warp-per-l ----------------
__global__ void __launch_bounds__(512) control_kernel(
    const float* __restrict__ cq, const float* __restrict__ cw,
    const int* __restrict__ mask, const float* __restrict__ Wca,
    const float* __restrict__ bca,
    float* __restrict__ cv_out, float* __restrict__ cnew)
{
    int b = blockIdx.x, tid = threadIdx.x;   // 512 threads
    int w = tid >> 5, lane = tid & 31;
    __shared__ float u[DIM];
    __shared__ float s[LW];
    const float* cwb = cw + (size_t)b * LW * DIM;
    u[tid] = cq[(size_t)b * DIM + tid] * Wca[tid];
    __syncthreads();
    #pragma unroll
    for (int li = 0; li < 2; li++) {
        int l = w * 2 + li;
        const float* row = cwb + (size_t)l * DIM;
        float p = 0.f;
        #pragma unroll
        for (int j = 0; j < 16; j++) p = fmaf(u[lane + j * 32], row[lane + j * 32], p);
        #pragma unroll
        for (int o = 16; o > 0; o >>= 1) p += __shfl_xor_sync(0xffffffffu, p, o);
        if (lane == 0) s[l] = (mask[b * LW + l] > 0) ? (p + bca[0]) : -INFINITY;
    }
    __syncthreads();
    if (tid == 0) {
        float mx = -INFINITY;
        for (int l = 0; l < LW; l++) mx = fmaxf(mx, s[l]);
        float sm = 0.f;
        for (int l = 0; l < LW; l++) { float e = __expf(s[l] - mx); s[l] = e; sm += e; }
        float inv = 1.f / sm;
        for (int l = 0; l < LW; l++) { s[l] *= inv; cv_out[b * LW + l] = s[l]; }
    }
    __syncthreads();
    float a = 0.f;
    #pragma unroll
    for (int l = 0; l < LW; l++) a = fmaf(s[l], cwb[(size_t)l * DIM + tid], a);
    cnew[(size_t)b * DIM + tid] = a;
}

// ---------------- softmax over channels: warp-per-pixel (fp16 ra), 28-pixel staging ----------
#define SMRV_TILE_STRIDE 517
#define SMRV_SMEM (28*SMRV_TILE_STRIDE*4)

__global__ void __launch_bounds__(512) softmax_rv_kernel(
    const __half* __restrict__ ra, const __half* __restrict__ kT,
    float* __restrict__ rv_out, float* __restrict__ r_out)
{
    extern __shared__ float tile[];          // [28][517]
    __shared__ float rsum[DIM];
    const int b = blockIdx.x, tid = threadIdx.x;
    const int w = tid >> 5, lane = tid & 31;
    const __half* rab = ra + (size_t)b * PIX * 512;
    const __half* kb = kT + (size_t)b * PIX * 512;
    float* rvb = rv_out + (size_t)b * DIM * PIX;

    if (tid < DIM) rsum[tid] = 0.f;
    float racc[16];
    #pragma unroll
    for (int j = 0; j < 16; j++) racc[j] = 0.f;
    __syncthreads();

    for (int pp = 0; pp < 7; pp++) {
        if (w < 14) {
            #pragma unroll
            for (int half = 0; half < 2; half++) {
                const int i = half * 14 + w;
                const int p = pp * 28 + i;
                float x[16];
                #pragma unroll
                for (int q = 0; q < 4; q++) {
                    const size_t ridx = (size_t)p * 512 + q * 128 + lane * 4;
                    __half2 r0 = *reinterpret_cast<const __half2*>(rab + ridx);
                    __half2 r1 = *reinterpret_cast<const __half2*>(rab + ridx + 2);
                    x[q * 4 + 0] = __half2float(r0.x); x[q * 4 + 1] = __half2float(r0.y);
                    x[q * 4 + 2] = __half2float(r1.x); x[q * 4 + 3] = __half2float(r1.y);
                }
                float mx = x[0];
                #pragma unroll
                for (int j = 1; j < 16; j++) mx = fmaxf(mx, x[j]);
                #pragma unroll
                for (int o = 16; o > 0; o >>= 1) mx = fmaxf(mx, __shfl_xor_sync(0xffffffffu, mx, o));
                float sm = 0.f;
                #pragma unroll
                for (int j = 0; j < 16; j++) { x[j] = __expf(x[j] - mx); sm += x[j]; }
                #pragma unroll
                for (int o = 16; o > 0; o >>= 1) sm += __shfl_xor_sync(0xffffffffu, sm, o);
                const float inv = 1.f / sm;
                #pragma unroll
                for (int q = 0; q < 4; q++) {
                    float rv0 = x[q * 4 + 0] * inv, rv1 = x[q * 4 + 1] * inv;
                    float rv2 = x[q * 4 + 2] * inv, rv3 = x[q * 4 + 3] * inv;
                    float* tr = &tile[i * SMRV_TILE_STRIDE + q * 128 + lane * 4];
                    tr[0] = rv0; tr[1] = rv1; tr[2] = rv2; tr[3] = rv3;
                    const size_t kidx = (size_t)p * 512 + q * 128 + lane * 4;
                    __half2 kh0 = *reinterpret_cast<const __half2*>(kb + kidx);
                    __half2 kh1 = *reinterpret_cast<const __half2*>(kb + kidx + 2);
                    racc[q * 4 + 0] = fmaf(rv0, __half2float(kh0.x), racc[q * 4 + 0]);
                    racc[q * 4 + 1] = fmaf(rv1, __half2float(kh0.y), racc[q * 4 + 1]);
                    racc[q * 4 + 2] = fmaf(rv2, __half2float(kh1.x), racc[q * 4 + 2]);
                    racc[q * 4 + 3] = fmaf(rv3, __half2float(kh1.y), racc[q * 4 + 3]);
                }
            }
        }
        __syncthreads();
        #pragma unroll 1
        for (int cc = 0; cc < 32; cc++) {
            int c = w * 32 + cc;
            if (lane < 28) rvb[(size_t)c * PIX + pp * 28 + lane] = tile[lane * SMRV_TILE_STRIDE + c];
        }
        __syncthreads();
    }

    #pragma unroll
    for (int q = 0; q < 4; q++)
        #pragma unroll
        for (int j = 0; j < 4; j++)
            atomicAdd(&rsum[q * 128 + lane * 4 + j], racc[q * 4 + j]);
    __syncthreads();
    if (tid < DIM) r_out[(size_t)b * DIM + tid] = rsum[tid];
}

// ---------------- gate, sa softmax over T, m_sa ----------------
__global__ void gate_sa_kernel(const float* __restrict__ cnew, const float* __restrict__ Wc,
                               const float* __restrict__ bc,   const float* __restrict__ cs,
                               const float* __restrict__ Wsa,  const float* __restrict__ bsa,
                               const float* __restrict__ ms,
                               float* __restrict__ gate_out, float* __restrict__ msa_out)
{
    int b = blockIdx.x, tid = threadIdx.x;   // 256 threads
    __shared__ float red[8];
    __shared__ float sa[TT];
    __shared__ float gsh;
    float p = 0.f;
    for (int d = tid; d < DIM; d += 256) p += cnew[(size_t)b * DIM + d] * Wc[d];
    float tot = blkSum<8>(p, red);
    if (tid == 0) gsh = 1.f / (1.f + __expf(-(tot + bc[0])));
    __syncthreads();
    float gate = gsh;
    for (int t8 = 0; t8 < TT; t8++) {
        float qv = 0.f;
        const float* csrow = cs + ((size_t)t8 * BATCH + b) * DIM;
        for (int d = tid; d < DIM; d += 256) qv += csrow[d] * Wsa[d];
        float qt = blkSum<8>(qv, red);
        if (tid == 0) sa[t8] = gate * qt + bsa[0];
    }
    __syncthreads();
    if (tid == 0) {
        float mx = -INFINITY;
        for (int i = 0; i < TT; i++) mx = fmaxf(mx, sa[i]);
        float sm = 0.f;
        for (int i = 0; i < TT; i++) { float e = __expf(sa[i] - mx); sa[i] = e; sm += e; }
        float inv = 1.f / sm;
        for (int i = 0; i < TT; i++) sa[i] *= inv;
    }
    __syncthreads();
    for (int d = tid; d < DIM; d += 256) {
        float a = 0.f;
        #pragma unroll
        for (int i = 0; i < TT; i++)
            a = fmaf(sa[i], ms[((size_t)i * BATCH + b) * DIM + d], a);
        msa_out[(size_t)b * DIM + d] = a;
    }
    if (tid == 0) gate_out[b] = gate;
}

// ---------------- final ----------------
__global__ void final_kernel(const float* __restrict__ m, const float* __restrict__ mm,
                             const float* __restrict__ tmp, const float* __restrict__ gate,
                             float* __restrict__ mnew)
{
    int i = blockIdx.x * 256 + threadIdx.x;
    int b = i >> 9;
    float g = gate[b];
    mnew[i] = g * m[i] + (1.f - g) * (mm[i] + tmp[i]);
}

// ---------------- launch ----------------
extern "C" void kernel_launch(void* const* d_in, const int* in_sizes, int n_in,
                              void* d_out, int out_size)
{
    const float* c    = (const float*)d_in[0];
    const float* m    = (const float*)d_in[1];
    const float* k    = (const float*)d_in[2];
    const float* q    = (const float*)d_in[3];
    const float* cw   = (const float*)d_in[4];
    const int*   mask = (const int*)  d_in[5];
    const float* cs   = (const float*)d_in[6];
    const float* ms   = (const float*)d_in[7];
    const float* Wcq  = (const float*)d_in[8];
    const float* bcq  = (const float*)d_in[9];
    const float* Wca  = (const float*)d_in[10];
    const float* bca  = (const float*)d_in[11];
    const float* Wm_r = (const float*)d_in[12];
    const float* bm_r = (const float*)d_in[13];
    const float* Wk   = (const float*)d_in[14];
    const float* bk   = (const float*)d_in[15];
    const float* WI   = (const float*)d_in[16];
    const float* bI   = (const float*)d_in[17];
    const float* Wra  = (const float*)d_in[18];
    const float* bra  = (const float*)d_in[19];
    const float* Wm_w = (const float*)d_in[20];
    const float* bm_w = (const float*)d_in[21];
    const float* Wsa  = (const float*)d_in[22];
    const float* bsa  = (const float*)d_in[23];
    const float* Wm2  = (const float*)d_in[24];
    const float* bm2  = (const float*)d_in[25];
    const float* Wc   = (const float*)d_in[26];
    const float* bc   = (const float*)d_in[27];
    const float* Ws   = (const float*)d_in[28];

    float* out      = (float*)d_out;
    float* out_cnew = out;                       // [B,D]
    float* out_mnew = out + 131072;              // [B,D]
    float* out_cv   = out + 262144;              // [B,L]
    float* out_rv   = out + 270336;              // [B,D,H,W]

    __half *p_kT, *p_I2, *p_J2, *p_ra, *p_Wk2, *p_WI2, *p_Wra2;
    float *p_cq, *p_mI, *p_r, *p_mprev, *p_mm, *p_msa, *p_tmp, *p_gate;
    cudaGetSymbolAddress((void**)&p_kT,   g_kT);
    cudaGetSymbolAddress((void**)&p_I2,   g_I2);
    cudaGetSymbolAddress((void**)&p_J2,   g_J2);
    cudaGetSymbolAddress((void**)&p_ra,   g_ra);
    cudaGetSymbolAddress((void**)&p_Wk2,  g_Wk2);
    cudaGetSymbolAddress((void**)&p_WI2,  g_WI2);
    cudaGetSymbolAddress((void**)&p_Wra2, g_Wra2);
    cudaGetSymbolAddress((void**)&p_cq,   g_cq);
    cudaGetSymbolAddress((void**)&p_mI,   g_mI);
    cudaGetSymbolAddress((void**)&p_r,    g_r);
    cudaGetSymbolAddress((void**)&p_mprev,g_mprev);
    cudaGetSymbolAddress((void**)&p_mm,   g_mm);
    cudaGetSymbolAddress((void**)&p_msa,  g_msa);
    cudaGetSymbolAddress((void**)&p_tmp,  g_tmp);
    cudaGetSymbolAddress((void**)&p_gate, g_gate);

    cudaFuncSetAttribute((const void*)mma_gemm<512,  false, 0>, cudaFuncAttributeMaxDynamicSharedMemorySize, MG_SMEM);
    cudaFuncSetAttribute((const void*)mma_gemm<1024, true,  0>, cudaFuncAttributeMaxDynamicSharedMemorySize, MG_SMEM);
    cudaFuncSetAttribute((const void*)mma_gemm<512,  false, 1>, cudaFuncAttributeMaxDynamicSharedMemorySize, MG_SMEM);
    cudaFuncSetAttribute(softmax_rv_kernel, cudaFuncAttributeMaxDynamicSharedMemorySize, SMRV_SMEM);

    // ================== two-stream DAG ==================
    cudaStream_t s2 = g_s2;

    // s0: transpose first (longest pole before gemmI)
    transpose_half_k<<<dim3(7, 16, BATCH), dim3(32, 8)>>>(k, p_kT);

    // fork s2 from capture stream
    cudaEventRecord(g_evFork, 0);
    cudaStreamWaitEvent(s2, g_evFork, 0);

    // s2 chain
    halve_w3_kernel<<<4096, 256, 0, s2>>>(Wk, WI, Wra, p_Wk2, p_WI2, p_Wra2);
    gemm_small<512, false><<<dim3(16, 8), 256, 0, s2>>>(m, nullptr, Wm_r, bm_r, p_mI);
    cudaEventRecord(g_evA, s2);
    gemm_small<1024, true><<<dim3(16, 8), 256, 0, s2>>>(c, q, Wcq, bcq, p_cq);
    control_kernel<<<BATCH, 512, 0, s2>>>(p_cq, cw, mask, Wca, bca, out_cv, out_cnew);
    cudaEventRecord(g_evB, s2);
    gate_sa_kernel<<<BATCH, 256, 0, s2>>>(out_cnew, Wc, bc, cs, Wsa, bsa, ms, p_gate, p_msa);
    gemm_small<512, false><<<dim3(16, 8), 256, 0, s2>>>(p_msa, nullptr, Ws, nullptr, p_tmp);
    cudaEventRecord(g_evC, s2);

    // s0 chain
    cudaStreamWaitEvent(0, g_evA, 0);   // needs Wk2 + mI
    mma_gemm<512, false, 0><<<dim3(4, 392), 256, MG_SMEM>>>(
        p_kT, nullptr, p_Wk2, bk, p_mI, p_I2);
    cudaStreamWaitEvent(0, g_evB, 0);   // needs cnew (+ WI2, already covered)
    mma_gemm<1024, true, 0><<<dim3(4, 392), 256, MG_SMEM>>>(
        p_I2, p_kT, p_WI2, bI, out_cnew, p_J2);
    mma_gemm<512, false, 1><<<dim3(4, 392), 256, MG_SMEM>>>(
        p_J2, nullptr, p_Wra2, bra, nullptr, p_ra);
    softmax_rv_kernel<<<BATCH, 512, SMRV_SMEM>>>(p_ra, p_kT, out_rv, p_r);
    gemm_small<1024, true><<<dim3(16, 8), 256>>>(p_r, m, Wm_w, bm_w, p_mprev);
    gemm_small<512, false><<<dim3(16, 8), 256>>>(p_mprev, nullptr, Wm2, bm2, p_mm);
    cudaStreamWaitEvent(0, g_evC, 0);   // needs gate + tmp
    final_kernel<<<(BATCH * DIM) / 256, 256>>>(m, p_mm, p_tmp, p_gate, out_mnew);
}